// round 1
// baseline (speedup 1.0000x reference)
#include <cuda_runtime.h>
#include <cuda_bf16.h>
#include <math_constants.h>

// Problem constants (fixed shapes from reference)
#define BATCH 4
#define SEQ   2048
#define CDIM  1024
#define HEADS 16
#define HDIM  64
#define TOKENS (BATCH * SEQ)         // 8192
#define QKVDIM (3 * CDIM)            // 3072

// ---------------------------------------------------------------------------
// Scratch (device globals — no allocation allowed)
// ---------------------------------------------------------------------------
__device__ float g_qkv[(size_t)TOKENS * QKVDIM];   // [token][3*C]  (q | k | v)
__device__ float g_attn[(size_t)TOKENS * CDIM];    // attention output [B,N,C]

// ---------------------------------------------------------------------------
// Generic tiled GEMM:  C[M,N] = A[M,K] @ B[K,N] + bias[N]
// 64x64 tile, BK=16, 256 threads, 4x4 micro-tile per thread
// ---------------------------------------------------------------------------
#define GBM 64
#define GBN 64
#define GBK 16

__global__ __launch_bounds__(256) void gemm_bias_kernel(
    const float* __restrict__ A, const float* __restrict__ B,
    const float* __restrict__ bias, float* __restrict__ C,
    int M, int N, int K)
{
    __shared__ float As[GBK][GBM + 1];                 // [k][m], pad -> conflict-free stores
    __shared__ __align__(16) float Bs[GBK][GBN];       // [k][n]

    const int tid = threadIdx.x;
    const int tx = tid & 15;
    const int ty = tid >> 4;
    const int rowBase = blockIdx.y * GBM;
    const int colBase = blockIdx.x * GBN;

    float acc[4][4] = {};

    for (int k0 = 0; k0 < K; k0 += GBK) {
        // A tile 64x16: consecutive tid -> consecutive k (coalesced), store transposed
        #pragma unroll
        for (int i = 0; i < 4; ++i) {
            int linear = tid + i * 256;                // 0..1023
            int m  = linear >> 4;
            int kk = linear & 15;
            As[kk][m] = A[(size_t)(rowBase + m) * K + k0 + kk];
        }
        // B tile 16x64: consecutive tid -> consecutive n (coalesced)
        #pragma unroll
        for (int i = 0; i < 4; ++i) {
            int linear = tid + i * 256;
            int kk = linear >> 6;
            int n  = linear & 63;
            Bs[kk][n] = B[(size_t)(k0 + kk) * N + colBase + n];
        }
        __syncthreads();

        #pragma unroll
        for (int kk = 0; kk < GBK; ++kk) {
            const float4 b4 = *(const float4*)&Bs[kk][tx << 2];
            const float a0 = As[kk][(ty << 2) + 0];
            const float a1 = As[kk][(ty << 2) + 1];
            const float a2 = As[kk][(ty << 2) + 2];
            const float a3 = As[kk][(ty << 2) + 3];
            acc[0][0] += a0 * b4.x; acc[0][1] += a0 * b4.y; acc[0][2] += a0 * b4.z; acc[0][3] += a0 * b4.w;
            acc[1][0] += a1 * b4.x; acc[1][1] += a1 * b4.y; acc[1][2] += a1 * b4.z; acc[1][3] += a1 * b4.w;
            acc[2][0] += a2 * b4.x; acc[2][1] += a2 * b4.y; acc[2][2] += a2 * b4.z; acc[2][3] += a2 * b4.w;
            acc[3][0] += a3 * b4.x; acc[3][1] += a3 * b4.y; acc[3][2] += a3 * b4.z; acc[3][3] += a3 * b4.w;
        }
        __syncthreads();
    }

    #pragma unroll
    for (int i = 0; i < 4; ++i) {
        const int row = rowBase + (ty << 2) + i;
        #pragma unroll
        for (int j = 0; j < 4; ++j) {
            const int col = colBase + (tx << 2) + j;
            C[(size_t)row * N + col] = acc[i][j] + bias[col];
        }
    }
}

// ---------------------------------------------------------------------------
// RMSNorm (in-place on q and k sections of g_qkv).
// One warp per (token, slot): slot 0..15 = q heads (qn_w), 16..31 = k heads (kn_w)
// ---------------------------------------------------------------------------
__global__ __launch_bounds__(256) void rmsnorm_kernel(
    float* __restrict__ qkv,
    const float* __restrict__ qn_w, const float* __restrict__ kn_w)
{
    const int gwarp = (blockIdx.x * blockDim.x + threadIdx.x) >> 5;
    const int lane  = threadIdx.x & 31;
    const int token = gwarp >> 5;             // / 32 slots
    const int slot  = gwarp & 31;
    if (token >= TOKENS) return;

    const bool is_q = (slot < 16);
    const int  h    = slot & 15;
    const float* w  = is_q ? qn_w : kn_w;
    float* row = qkv + (size_t)token * QKVDIM + (is_q ? 0 : CDIM) + h * HDIM;

    float x0 = row[lane];
    float x1 = row[lane + 32];
    float ss = x0 * x0 + x1 * x1;
    #pragma unroll
    for (int off = 16; off; off >>= 1) ss += __shfl_xor_sync(0xffffffffu, ss, off);
    const float inv = rsqrtf(ss * (1.0f / 64.0f) + 1e-6f);
    row[lane]      = x0 * inv * w[lane];
    row[lane + 32] = x1 * inv * w[lane + 32];
}

// ---------------------------------------------------------------------------
// Flash-style attention. One CTA per (b*H + h, q-tile of 64). 256 threads.
// Thread (ty,tx) owns S/P rows r0..r0+3 x cols tx*4..+3, and O rows r0..r0+3 x
// dims tx*4..+3.  KPs holds K transposed [d][c] (xor-swizzled) during S, and
// is reused for P [r][c] (xor-swizzled) during the PV accumulation.
// Shared = 3 * 16KB = 48KB exactly.
// ---------------------------------------------------------------------------
__global__ __launch_bounds__(256) void attn_kernel(
    const float* __restrict__ qkv, float* __restrict__ out)
{
    __shared__ __align__(16) float Qs [64 * 64];
    __shared__ __align__(16) float KPs[64 * 64];
    __shared__ __align__(16) float Vs [64 * 64];

    const int tid = threadIdx.x;
    const int tx  = tid & 15;
    const int ty  = tid >> 4;
    const int r0  = ty << 2;

    const int bh = blockIdx.y;
    const int b  = bh >> 4;
    const int h  = bh & 15;
    const int qBase = blockIdx.x * 64;

    const float* qptr = qkv + (size_t)b * SEQ * QKVDIM + h * HDIM;           // + n*3072 + d
    const float* kptr = qptr + CDIM;
    const float* vptr = qptr + 2 * CDIM;

    // Load Q tile, folding the 1/sqrt(D) scale
    #pragma unroll
    for (int i = 0; i < 16; ++i) {
        int linear = tid + i * 256;
        int r = linear >> 6, d = linear & 63;
        Qs[(r << 6) + d] = qptr[(size_t)(qBase + r) * QKVDIM + d] * 0.125f;
    }

    float m_run[4], l_run[4], o[4][4];
    #pragma unroll
    for (int i = 0; i < 4; ++i) {
        m_run[i] = -CUDART_INF_F;
        l_run[i] = 0.0f;
        #pragma unroll
        for (int j = 0; j < 4; ++j) o[i][j] = 0.0f;
    }

    for (int kt = 0; kt < SEQ / 64; ++kt) {
        const int kBase = kt * 64;
        __syncthreads();   // prior-iter readers of KPs/Vs done; also orders Qs on iter 0

        // Load K (transposed + swizzled) and V (natural)
        #pragma unroll
        for (int i = 0; i < 16; ++i) {
            int linear = tid + i * 256;
            int c = linear >> 6, d = linear & 63;
            const size_t tok = (size_t)(kBase + c) * QKVDIM;
            float kv = kptr[tok + d];
            KPs[(d << 6) + ((((c >> 2) ^ (d & 15))) << 2) + (c & 3)] = kv;
            Vs[(c << 6) + d] = vptr[tok + d];
        }
        __syncthreads();

        // S = (Q*scale) @ K^T
        float s[4][4] = {};
        #pragma unroll
        for (int d0 = 0; d0 < 64; d0 += 4) {
            float qv[4][4];
            #pragma unroll
            for (int i = 0; i < 4; ++i) {
                const float4 t = *(const float4*)&Qs[((r0 + i) << 6) + d0];
                qv[i][0] = t.x; qv[i][1] = t.y; qv[i][2] = t.z; qv[i][3] = t.w;
            }
            #pragma unroll
            for (int dd = 0; dd < 4; ++dd) {
                const int d = d0 + dd;
                const float4 k4 = *(const float4*)&KPs[(d << 6) + ((tx ^ (d & 15)) << 2)];
                #pragma unroll
                for (int i = 0; i < 4; ++i) {
                    s[i][0] += qv[i][dd] * k4.x;
                    s[i][1] += qv[i][dd] * k4.y;
                    s[i][2] += qv[i][dd] * k4.z;
                    s[i][3] += qv[i][dd] * k4.w;
                }
            }
        }

        // Online softmax (row reductions across the 16 tx lanes sharing ty)
        #pragma unroll
        for (int i = 0; i < 4; ++i) {
            float mx = fmaxf(fmaxf(s[i][0], s[i][1]), fmaxf(s[i][2], s[i][3]));
            #pragma unroll
            for (int off = 8; off; off >>= 1)
                mx = fmaxf(mx, __shfl_xor_sync(0xffffffffu, mx, off));
            const float mnew = fmaxf(m_run[i], mx);
            const float corr = __expf(m_run[i] - mnew);
            float rs = 0.0f;
            #pragma unroll
            for (int j = 0; j < 4; ++j) {
                s[i][j] = __expf(s[i][j] - mnew);
                rs += s[i][j];
            }
            #pragma unroll
            for (int off = 8; off; off >>= 1)
                rs += __shfl_xor_sync(0xffffffffu, rs, off);
            l_run[i] = l_run[i] * corr + rs;
            m_run[i] = mnew;
            #pragma unroll
            for (int j = 0; j < 4; ++j) o[i][j] *= corr;
        }

        __syncthreads();   // everyone done reading KPs as K

        // Store P (swizzled) into KPs
        #pragma unroll
        for (int i = 0; i < 4; ++i) {
            const int r = r0 + i;
            *(float4*)&KPs[(r << 6) + ((tx ^ (r & 15)) << 2)] =
                make_float4(s[i][0], s[i][1], s[i][2], s[i][3]);
        }
        __syncthreads();

        // O += P @ V
        #pragma unroll
        for (int k0 = 0; k0 < 64; k0 += 4) {
            float pv[4][4];
            #pragma unroll
            for (int i = 0; i < 4; ++i) {
                const int r = r0 + i;
                const float4 t = *(const float4*)&KPs[(r << 6) + ((((k0 >> 2) ^ (r & 15))) << 2)];
                pv[i][0] = t.x; pv[i][1] = t.y; pv[i][2] = t.z; pv[i][3] = t.w;
            }
            #pragma unroll
            for (int kk = 0; kk < 4; ++kk) {
                const float4 v4 = *(const float4*)&Vs[((k0 + kk) << 6) + (tx << 2)];
                #pragma unroll
                for (int i = 0; i < 4; ++i) {
                    o[i][0] += pv[i][kk] * v4.x;
                    o[i][1] += pv[i][kk] * v4.y;
                    o[i][2] += pv[i][kk] * v4.z;
                    o[i][3] += pv[i][kk] * v4.w;
                }
            }
        }
    }

    // Normalize and write out in [B,N,C] layout
    #pragma unroll
    for (int i = 0; i < 4; ++i) {
        const float inv = 1.0f / l_run[i];
        const size_t row = (size_t)b * SEQ + qBase + r0 + i;
        float* dst = out + row * CDIM + h * HDIM + (tx << 2);
        dst[0] = o[i][0] * inv;
        dst[1] = o[i][1] * inv;
        dst[2] = o[i][2] * inv;
        dst[3] = o[i][3] * inv;
    }
}

// ---------------------------------------------------------------------------
// Launch
// ---------------------------------------------------------------------------
extern "C" void kernel_launch(void* const* d_in, const int* in_sizes, int n_in,
                              void* d_out, int out_size)
{
    (void)in_sizes; (void)n_in; (void)out_size;
    const float* x      = (const float*)d_in[0];
    const float* W_qkv  = (const float*)d_in[1];
    const float* b_qkv  = (const float*)d_in[2];
    const float* W_proj = (const float*)d_in[3];
    const float* b_proj = (const float*)d_in[4];
    const float* qn_w   = (const float*)d_in[5];
    const float* kn_w   = (const float*)d_in[6];
    float* out = (float*)d_out;

    float *qkv = nullptr, *attn = nullptr;
    cudaGetSymbolAddress((void**)&qkv,  g_qkv);
    cudaGetSymbolAddress((void**)&attn, g_attn);

    // 1) QKV projection: [8192,1024] @ [1024,3072] + b
    gemm_bias_kernel<<<dim3(QKVDIM / GBN, TOKENS / GBM), 256>>>(
        x, W_qkv, b_qkv, qkv, TOKENS, QKVDIM, CDIM);

    // 2) RMSNorm on q and k heads (in place). 8192 tokens * 32 rows, 8 warps/block
    rmsnorm_kernel<<<(TOKENS * 32) / 8, 256>>>(qkv, qn_w, kn_w);

    // 3) Attention -> g_attn in [B,N,C]
    attn_kernel<<<dim3(SEQ / 64, BATCH * HEADS), 256>>>(qkv, attn);

    // 4) Output projection: [8192,1024] @ [1024,1024] + b -> d_out
    gemm_bias_kernel<<<dim3(CDIM / GBN, TOKENS / GBM), 256>>>(
        attn, W_proj, b_proj, out, TOKENS, CDIM, CDIM);
}

// round 3
// speedup vs baseline: 1.3684x; 1.3684x over previous
#include <cuda_runtime.h>
#include <cuda_bf16.h>
#include <math_constants.h>
#include <cstdint>

// Problem constants
#define BATCH 4
#define SEQ   2048
#define CDIM  1024
#define HEADS 16
#define HDIM  64
#define TOKENS (BATCH * SEQ)         // 8192
#define QKVDIM (3 * CDIM)            // 3072
#define KEFF   3072                  // 3 * 1024 (bf16 split-K for both GEMMs)

// ---------------------------------------------------------------------------
// Scratch (device globals — no allocation allowed)
// ---------------------------------------------------------------------------
__device__ float g_qkv[(size_t)TOKENS * QKVDIM];                       // QKV output fp32
__device__ __align__(256) __nv_bfloat16 g_A1[(size_t)TOKENS * KEFF];  // x split       [m, hi|lo|hi]
__device__ __align__(256) __nv_bfloat16 g_B1[(size_t)QKVDIM * KEFF];  // W_qkv^T split [n, hi|hi|lo]
__device__ __align__(256) __nv_bfloat16 g_B2[(size_t)CDIM * KEFF];    // W_proj^T split
__device__ __align__(256) __nv_bfloat16 g_A2[(size_t)TOKENS * KEFF];  // attn out split [m, hi|lo|hi]

// ---------------------------------------------------------------------------
// Small PTX helpers (all portable PTX: sm_80+ features only)
// ---------------------------------------------------------------------------
__device__ __forceinline__ uint32_t smem_u32(const void* p) {
    uint32_t a;
    asm("{ .reg .u64 t; cvta.to.shared.u64 t, %1; cvt.u32.u64 %0, t; }" : "=r"(a) : "l"(p));
    return a;
}
__device__ __forceinline__ void cp_async16(uint32_t dst, const void* src) {
    asm volatile("cp.async.cg.shared.global [%0], [%1], 16;" :: "r"(dst), "l"(src));
}
__device__ __forceinline__ void cp_commit() {
    asm volatile("cp.async.commit_group;" ::: "memory");
}
__device__ __forceinline__ void cp_wait0() {
    asm volatile("cp.async.wait_group 0;" ::: "memory");
}
__device__ __forceinline__ void ldsm_x4(uint32_t* r, uint32_t addr) {
    asm volatile("ldmatrix.sync.aligned.m8n8.x4.shared.b16 {%0,%1,%2,%3}, [%4];"
                 : "=r"(r[0]), "=r"(r[1]), "=r"(r[2]), "=r"(r[3]) : "r"(addr));
}
__device__ __forceinline__ void ldsm_x2(uint32_t* r, uint32_t addr) {
    asm volatile("ldmatrix.sync.aligned.m8n8.x2.shared.b16 {%0,%1}, [%2];"
                 : "=r"(r[0]), "=r"(r[1]) : "r"(addr));
}
__device__ __forceinline__ void mma_bf16(float* c, const uint32_t* a, const uint32_t* b) {
    asm volatile(
        "mma.sync.aligned.m16n8k16.row.col.f32.bf16.bf16.f32 "
        "{%0,%1,%2,%3}, {%4,%5,%6,%7}, {%8,%9}, {%0,%1,%2,%3};"
        : "+f"(c[0]), "+f"(c[1]), "+f"(c[2]), "+f"(c[3])
        : "r"(a[0]), "r"(a[1]), "r"(a[2]), "r"(a[3]), "r"(b[0]), "r"(b[1]));
}

// ---------------------------------------------------------------------------
// Conversion kernels (fp32 -> bf16 hi/lo split)
// ---------------------------------------------------------------------------
__global__ __launch_bounds__(256) void convX_kernel(const float* __restrict__ x,
                                                    __nv_bfloat16* __restrict__ A)
{
    const int idx = blockIdx.x * 256 + threadIdx.x;      // over TOKENS*CDIM
    const int m = idx >> 10;
    const int k = idx & 1023;
    const float v = x[idx];
    const __nv_bfloat16 hi = __float2bfloat16(v);
    const __nv_bfloat16 lo = __float2bfloat16(v - __bfloat162float(hi));
    __nv_bfloat16* row = A + (size_t)m * KEFF;
    row[k]        = hi;
    row[1024 + k] = lo;
    row[2048 + k] = hi;
}

// Transpose + split: W [K=1024, N] fp32  ->  B [N, 3K] bf16, layout [hi|hi|lo]
__global__ __launch_bounds__(256) void convW_kernel(const float* __restrict__ W,
                                                    __nv_bfloat16* __restrict__ B, int N)
{
    __shared__ float t[32][33];
    const int n0 = blockIdx.x * 32;
    const int k0 = blockIdx.y * 32;
    const int tx = threadIdx.x & 31;
    const int ty = threadIdx.x >> 5;          // 0..7
    #pragma unroll
    for (int i = 0; i < 4; ++i)
        t[ty + 8 * i][tx] = W[(size_t)(k0 + ty + 8 * i) * N + n0 + tx];
    __syncthreads();
    #pragma unroll
    for (int i = 0; i < 4; ++i) {
        const int n = n0 + ty + 8 * i;
        const int k = k0 + tx;
        const float v = t[tx][ty + 8 * i];
        const __nv_bfloat16 hi = __float2bfloat16(v);
        const __nv_bfloat16 lo = __float2bfloat16(v - __bfloat162float(hi));
        __nv_bfloat16* row = B + (size_t)n * KEFF;
        row[k]        = hi;
        row[1024 + k] = hi;
        row[2048 + k] = lo;
    }
}

// ---------------------------------------------------------------------------
// mma.sync bf16 GEMM:  C[M,N] = A' @ B'^T + bias
// A' [M, KEFF] row-major bf16, B' [N, KEFF] row-major bf16 (i.e. B col-major).
// CTA tile 128x128, 8 warps (2x4), each warp 64x32. BK=32, cp.async double buffer.
// Smem rows padded to 40 bf16 (80B stride) -> conflict-free ldmatrix.
// ---------------------------------------------------------------------------
#define BM 128
#define BN 128
#define BK 32
#define KST 40                     // padded bf16 stride
#define NCHUNK (KEFF / BK)         // 96

__global__ __launch_bounds__(256) void gemm_mma_kernel(
    const __nv_bfloat16* __restrict__ A, const __nv_bfloat16* __restrict__ Bm,
    const float* __restrict__ bias, float* __restrict__ C, int N)
{
    __shared__ __align__(16) __nv_bfloat16 As[2][BM * KST];
    __shared__ __align__(16) __nv_bfloat16 Bs[2][BN * KST];

    const int tid  = threadIdx.x;
    const int wid  = tid >> 5;
    const int lane = tid & 31;
    const int wm   = wid >> 2;           // 0..1  (64-row slab)
    const int wn   = wid & 3;            // 0..3  (32-col slab)
    const int rowBase = blockIdx.y * BM;
    const int colBase = blockIdx.x * BN;

    const uint32_t asAddr[2] = { smem_u32(As[0]), smem_u32(As[1]) };
    const uint32_t bsAddr[2] = { smem_u32(Bs[0]), smem_u32(Bs[1]) };

    float acc[4][4][4] = {};             // [mt][nt][frag]

    // loader: 512 16B-chunks per tile per matrix; 2 per thread each
    const int lr = tid >> 2;             // row 0..63 base (x2 via +64)
    const int lj = tid & 3;              // 16B chunk within row

    auto loadChunk = [&](int c, int buf) {
        const __nv_bfloat16* Ag = A + (size_t)rowBase * KEFF + c * BK;
        const __nv_bfloat16* Bg = Bm + (size_t)colBase * KEFF + c * BK;
        #pragma unroll
        for (int i = 0; i < 2; ++i) {
            const int r = lr + i * 64;
            cp_async16(asAddr[buf] + r * (KST * 2) + lj * 16, Ag + (size_t)r * KEFF + lj * 8);
            cp_async16(bsAddr[buf] + r * (KST * 2) + lj * 16, Bg + (size_t)r * KEFF + lj * 8);
        }
        cp_commit();
    };

    loadChunk(0, 0);

    for (int c = 0; c < NCHUNK; ++c) {
        const int buf = c & 1;
        cp_wait0();
        __syncthreads();
        if (c + 1 < NCHUNK) loadChunk(c + 1, buf ^ 1);

        #pragma unroll
        for (int ks = 0; ks < 2; ++ks) {
            uint32_t afr[4][4];
            #pragma unroll
            for (int mt = 0; mt < 4; ++mt) {
                const int row = wm * 64 + mt * 16 + (lane & 15);
                const int col = ks * 16 + ((lane >> 4) << 3);
                ldsm_x4(afr[mt], asAddr[buf] + (row * KST + col) * 2);
            }
            uint32_t bfr[4][2];
            #pragma unroll
            for (int nt = 0; nt < 4; ++nt) {
                const int nrow = wn * 32 + nt * 8 + (lane & 7);
                const int col  = ks * 16 + ((lane >> 3) & 1) * 8;
                ldsm_x2(bfr[nt], bsAddr[buf] + (nrow * KST + col) * 2);
            }
            #pragma unroll
            for (int mt = 0; mt < 4; ++mt)
                #pragma unroll
                for (int nt = 0; nt < 4; ++nt)
                    mma_bf16(acc[mt][nt], afr[mt], bfr[nt]);
        }
    }

    // Epilogue: c0,c1 -> (row lane/4, col 2*(lane%4)); c2,c3 -> row+8
    const int erow = lane >> 2;
    const int ecol = (lane & 3) * 2;
    #pragma unroll
    for (int mt = 0; mt < 4; ++mt) {
        const int rA = rowBase + wm * 64 + mt * 16 + erow;
        #pragma unroll
        for (int nt = 0; nt < 4; ++nt) {
            const int col = colBase + wn * 32 + nt * 8 + ecol;
            const float b0 = bias[col], b1 = bias[col + 1];
            *(float2*)&C[(size_t)rA * N + col] =
                make_float2(acc[mt][nt][0] + b0, acc[mt][nt][1] + b1);
            *(float2*)&C[(size_t)(rA + 8) * N + col] =
                make_float2(acc[mt][nt][2] + b0, acc[mt][nt][3] + b1);
        }
    }
}

// ---------------------------------------------------------------------------
// RMSNorm (in-place on q and k sections of g_qkv)
// ---------------------------------------------------------------------------
__global__ __launch_bounds__(256) void rmsnorm_kernel(
    float* __restrict__ qkv,
    const float* __restrict__ qn_w, const float* __restrict__ kn_w)
{
    const int gwarp = (blockIdx.x * blockDim.x + threadIdx.x) >> 5;
    const int lane  = threadIdx.x & 31;
    const int token = gwarp >> 5;
    const int slot  = gwarp & 31;
    if (token >= TOKENS) return;

    const bool is_q = (slot < 16);
    const int  h    = slot & 15;
    const float* w  = is_q ? qn_w : kn_w;
    float* row = qkv + (size_t)token * QKVDIM + (is_q ? 0 : CDIM) + h * HDIM;

    float x0 = row[lane];
    float x1 = row[lane + 32];
    float ss = x0 * x0 + x1 * x1;
    #pragma unroll
    for (int off = 16; off; off >>= 1) ss += __shfl_xor_sync(0xffffffffu, ss, off);
    const float inv = rsqrtf(ss * (1.0f / 64.0f) + 1e-6f);
    row[lane]      = x0 * inv * w[lane];
    row[lane + 32] = x1 * inv * w[lane + 32];
}

// ---------------------------------------------------------------------------
// Flash-style attention (FFMA). Writes bf16 split triple directly to g_A2.
// ---------------------------------------------------------------------------
__global__ __launch_bounds__(256) void attn_kernel(
    const float* __restrict__ qkv, __nv_bfloat16* __restrict__ outA)
{
    __shared__ __align__(16) float Qs [64 * 64];
    __shared__ __align__(16) float KPs[64 * 64];
    __shared__ __align__(16) float Vs [64 * 64];

    const int tid = threadIdx.x;
    const int tx  = tid & 15;
    const int ty  = tid >> 4;
    const int r0  = ty << 2;

    const int bh = blockIdx.y;
    const int b  = bh >> 4;
    const int h  = bh & 15;
    const int qBase = blockIdx.x * 64;

    const float* qptr = qkv + (size_t)b * SEQ * QKVDIM + h * HDIM;
    const float* kptr = qptr + CDIM;
    const float* vptr = qptr + 2 * CDIM;

    #pragma unroll
    for (int i = 0; i < 16; ++i) {
        int linear = tid + i * 256;
        int r = linear >> 6, d = linear & 63;
        Qs[(r << 6) + d] = qptr[(size_t)(qBase + r) * QKVDIM + d] * 0.125f;
    }

    float m_run[4], l_run[4], o[4][4];
    #pragma unroll
    for (int i = 0; i < 4; ++i) {
        m_run[i] = -CUDART_INF_F;
        l_run[i] = 0.0f;
        #pragma unroll
        for (int j = 0; j < 4; ++j) o[i][j] = 0.0f;
    }

    for (int kt = 0; kt < SEQ / 64; ++kt) {
        const int kBase = kt * 64;
        __syncthreads();

        #pragma unroll
        for (int i = 0; i < 16; ++i) {
            int linear = tid + i * 256;
            int c = linear >> 6, d = linear & 63;
            const size_t tok = (size_t)(kBase + c) * QKVDIM;
            float kv = kptr[tok + d];
            KPs[(d << 6) + ((((c >> 2) ^ (d & 15))) << 2) + (c & 3)] = kv;
            Vs[(c << 6) + d] = vptr[tok + d];
        }
        __syncthreads();

        float s[4][4] = {};
        #pragma unroll
        for (int d0 = 0; d0 < 64; d0 += 4) {
            float qv[4][4];
            #pragma unroll
            for (int i = 0; i < 4; ++i) {
                const float4 t = *(const float4*)&Qs[((r0 + i) << 6) + d0];
                qv[i][0] = t.x; qv[i][1] = t.y; qv[i][2] = t.z; qv[i][3] = t.w;
            }
            #pragma unroll
            for (int dd = 0; dd < 4; ++dd) {
                const int d = d0 + dd;
                const float4 k4 = *(const float4*)&KPs[(d << 6) + ((tx ^ (d & 15)) << 2)];
                #pragma unroll
                for (int i = 0; i < 4; ++i) {
                    s[i][0] += qv[i][dd] * k4.x;
                    s[i][1] += qv[i][dd] * k4.y;
                    s[i][2] += qv[i][dd] * k4.z;
                    s[i][3] += qv[i][dd] * k4.w;
                }
            }
        }

        #pragma unroll
        for (int i = 0; i < 4; ++i) {
            float mx = fmaxf(fmaxf(s[i][0], s[i][1]), fmaxf(s[i][2], s[i][3]));
            #pragma unroll
            for (int off = 8; off; off >>= 1)
                mx = fmaxf(mx, __shfl_xor_sync(0xffffffffu, mx, off));
            const float mnew = fmaxf(m_run[i], mx);
            const float corr = __expf(m_run[i] - mnew);
            float rs = 0.0f;
            #pragma unroll
            for (int j = 0; j < 4; ++j) {
                s[i][j] = __expf(s[i][j] - mnew);
                rs += s[i][j];
            }
            #pragma unroll
            for (int off = 8; off; off >>= 1)
                rs += __shfl_xor_sync(0xffffffffu, rs, off);
            l_run[i] = l_run[i] * corr + rs;
            m_run[i] = mnew;
            #pragma unroll
            for (int j = 0; j < 4; ++j) o[i][j] *= corr;
        }

        __syncthreads();

        #pragma unroll
        for (int i = 0; i < 4; ++i) {
            const int r = r0 + i;
            *(float4*)&KPs[(r << 6) + ((tx ^ (r & 15)) << 2)] =
                make_float4(s[i][0], s[i][1], s[i][2], s[i][3]);
        }
        __syncthreads();

        #pragma unroll
        for (int k0 = 0; k0 < 64; k0 += 4) {
            float pv[4][4];
            #pragma unroll
            for (int i = 0; i < 4; ++i) {
                const int r = r0 + i;
                const float4 t = *(const float4*)&KPs[(r << 6) + ((((k0 >> 2) ^ (r & 15))) << 2)];
                pv[i][0] = t.x; pv[i][1] = t.y; pv[i][2] = t.z; pv[i][3] = t.w;
            }
            #pragma unroll
            for (int kk = 0; kk < 4; ++kk) {
                const float4 v4 = *(const float4*)&Vs[((k0 + kk) << 6) + (tx << 2)];
                #pragma unroll
                for (int i = 0; i < 4; ++i) {
                    o[i][0] += pv[i][kk] * v4.x;
                    o[i][1] += pv[i][kk] * v4.y;
                    o[i][2] += pv[i][kk] * v4.z;
                    o[i][3] += pv[i][kk] * v4.w;
                }
            }
        }
    }

    // Epilogue: normalize and write bf16 hi/lo/hi split rows for the proj GEMM
    #pragma unroll
    for (int i = 0; i < 4; ++i) {
        const float inv = 1.0f / l_run[i];
        const size_t row = (size_t)b * SEQ + qBase + r0 + i;
        __nv_bfloat16* dst = outA + row * KEFF;
        #pragma unroll
        for (int j = 0; j < 4; ++j) {
            const float v = o[i][j] * inv;
            const int col = h * HDIM + (tx << 2) + j;
            const __nv_bfloat16 hi = __float2bfloat16(v);
            const __nv_bfloat16 lo = __float2bfloat16(v - __bfloat162float(hi));
            dst[col]        = hi;
            dst[1024 + col] = lo;
            dst[2048 + col] = hi;
        }
    }
}

// ---------------------------------------------------------------------------
// Launch
// ---------------------------------------------------------------------------
extern "C" void kernel_launch(void* const* d_in, const int* in_sizes, int n_in,
                              void* d_out, int out_size)
{
    (void)in_sizes; (void)n_in; (void)out_size;
    const float* x      = (const float*)d_in[0];
    const float* W_qkv  = (const float*)d_in[1];
    const float* b_qkv  = (const float*)d_in[2];
    const float* W_proj = (const float*)d_in[3];
    const float* b_proj = (const float*)d_in[4];
    const float* qn_w   = (const float*)d_in[5];
    const float* kn_w   = (const float*)d_in[6];
    float* out = (float*)d_out;

    float *qkv = nullptr;
    __nv_bfloat16 *A1 = nullptr, *B1 = nullptr, *B2 = nullptr, *A2 = nullptr;
    cudaGetSymbolAddress((void**)&qkv, g_qkv);
    cudaGetSymbolAddress((void**)&A1,  g_A1);
    cudaGetSymbolAddress((void**)&B1,  g_B1);
    cudaGetSymbolAddress((void**)&B2,  g_B2);
    cudaGetSymbolAddress((void**)&A2,  g_A2);

    // 0) Conversions to bf16 split formats
    convX_kernel<<<(TOKENS * CDIM) / 256, 256>>>(x, A1);
    convW_kernel<<<dim3(QKVDIM / 32, CDIM / 32), 256>>>(W_qkv, B1, QKVDIM);
    convW_kernel<<<dim3(CDIM / 32, CDIM / 32), 256>>>(W_proj, B2, CDIM);

    // 1) QKV projection (mma.sync): [8192, 3072] = A1 @ B1^T + b_qkv
    gemm_mma_kernel<<<dim3(QKVDIM / BN, TOKENS / BM), 256>>>(A1, B1, b_qkv, qkv, QKVDIM);

    // 2) RMSNorm on q and k heads (in place)
    rmsnorm_kernel<<<(TOKENS * 32) / 8, 256>>>(qkv, qn_w, kn_w);

    // 3) Attention -> g_A2 (bf16 split, proj-ready)
    attn_kernel<<<dim3(SEQ / 64, BATCH * HEADS), 256>>>(qkv, A2);

    // 4) Output projection (mma.sync): [8192, 1024] = A2 @ B2^T + b_proj
    gemm_mma_kernel<<<dim3(CDIM / BN, TOKENS / BM), 256>>>(A2, B2, b_proj, out, CDIM);
}

// round 4
// speedup vs baseline: 2.9988x; 2.1914x over previous
#include <cuda_runtime.h>
#include <cuda_bf16.h>
#include <math_constants.h>
#include <cstdint>

// Problem constants
#define BATCH 4
#define SEQ   2048
#define CDIM  1024
#define HEADS 16
#define HDIM  64
#define TOKENS (BATCH * SEQ)         // 8192
#define QKVDIM (3 * CDIM)            // 3072
#define KEFF   3072                  // 3 * 1024 (bf16 split-K for both GEMMs)

// ---------------------------------------------------------------------------
// Scratch (device globals — no allocation allowed)
// ---------------------------------------------------------------------------
__device__ float g_qkv[(size_t)TOKENS * QKVDIM];                       // QKV output fp32
__device__ __align__(256) __nv_bfloat16 g_A1[(size_t)TOKENS * KEFF];  // x split       [m, hi|lo|hi]
__device__ __align__(256) __nv_bfloat16 g_B1[(size_t)QKVDIM * KEFF];  // W_qkv^T split [n, hi|hi|lo]
__device__ __align__(256) __nv_bfloat16 g_B2[(size_t)CDIM * KEFF];    // W_proj^T split
__device__ __align__(256) __nv_bfloat16 g_A2[(size_t)TOKENS * KEFF];  // attn out split [m, hi|lo|hi]
__device__ __align__(256) __nv_bfloat16 g_ks[(size_t)BATCH * HEADS * SEQ * 128]; // K split [hi64|lo64]
__device__ __align__(256) __nv_bfloat16 g_vs[(size_t)BATCH * HEADS * SEQ * 128]; // V split [hi64|lo64]

// ---------------------------------------------------------------------------
// PTX helpers (portable sm_80+ features only)
// ---------------------------------------------------------------------------
__device__ __forceinline__ uint32_t smem_u32(const void* p) {
    uint32_t a;
    asm("{ .reg .u64 t; cvta.to.shared.u64 t, %1; cvt.u32.u64 %0, t; }" : "=r"(a) : "l"(p));
    return a;
}
__device__ __forceinline__ void cp_async16(uint32_t dst, const void* src) {
    asm volatile("cp.async.cg.shared.global [%0], [%1], 16;" :: "r"(dst), "l"(src));
}
__device__ __forceinline__ void cp_commit() {
    asm volatile("cp.async.commit_group;" ::: "memory");
}
__device__ __forceinline__ void cp_wait0() {
    asm volatile("cp.async.wait_group 0;" ::: "memory");
}
__device__ __forceinline__ void cp_wait1() {
    asm volatile("cp.async.wait_group 1;" ::: "memory");
}
__device__ __forceinline__ void ldsm_x4(uint32_t* r, uint32_t addr) {
    asm volatile("ldmatrix.sync.aligned.m8n8.x4.shared.b16 {%0,%1,%2,%3}, [%4];"
                 : "=r"(r[0]), "=r"(r[1]), "=r"(r[2]), "=r"(r[3]) : "r"(addr));
}
__device__ __forceinline__ void ldsm_x4_t(uint32_t* r, uint32_t addr) {
    asm volatile("ldmatrix.sync.aligned.m8n8.x4.trans.shared.b16 {%0,%1,%2,%3}, [%4];"
                 : "=r"(r[0]), "=r"(r[1]), "=r"(r[2]), "=r"(r[3]) : "r"(addr));
}
__device__ __forceinline__ void ldsm_x2(uint32_t* r, uint32_t addr) {
    asm volatile("ldmatrix.sync.aligned.m8n8.x2.shared.b16 {%0,%1}, [%2];"
                 : "=r"(r[0]), "=r"(r[1]) : "r"(addr));
}
__device__ __forceinline__ void mma_bf16(float* c, const uint32_t* a, const uint32_t* b) {
    asm volatile(
        "mma.sync.aligned.m16n8k16.row.col.f32.bf16.bf16.f32 "
        "{%0,%1,%2,%3}, {%4,%5,%6,%7}, {%8,%9}, {%0,%1,%2,%3};"
        : "+f"(c[0]), "+f"(c[1]), "+f"(c[2]), "+f"(c[3])
        : "r"(a[0]), "r"(a[1]), "r"(a[2]), "r"(a[3]), "r"(b[0]), "r"(b[1]));
}
__device__ __forceinline__ float ex2f(float x) {
    float y; asm("ex2.approx.ftz.f32 %0, %1;" : "=f"(y) : "f"(x)); return y;
}
__device__ __forceinline__ uint32_t bf16pack(float a, float b) {
    __nv_bfloat162 h;
    h.x = __float2bfloat16(a);
    h.y = __float2bfloat16(b);
    return *(uint32_t*)&h;
}
__device__ __forceinline__ uint32_t bf16pack_lo(float a, float b, uint32_t hipack) {
    __nv_bfloat162 h = *(__nv_bfloat162*)&hipack;
    return bf16pack(a - __bfloat162float(h.x), b - __bfloat162float(h.y));
}

// ---------------------------------------------------------------------------
// Conversion kernels (fp32 -> bf16 hi/lo split)
// ---------------------------------------------------------------------------
__global__ __launch_bounds__(256) void convX_kernel(const float* __restrict__ x,
                                                    __nv_bfloat16* __restrict__ A)
{
    const int idx = blockIdx.x * 256 + threadIdx.x;      // over TOKENS*CDIM
    const int m = idx >> 10;
    const int k = idx & 1023;
    const float v = x[idx];
    const __nv_bfloat16 hi = __float2bfloat16(v);
    const __nv_bfloat16 lo = __float2bfloat16(v - __bfloat162float(hi));
    __nv_bfloat16* row = A + (size_t)m * KEFF;
    row[k]        = hi;
    row[1024 + k] = lo;
    row[2048 + k] = hi;
}

// Transpose + split: W [K=1024, N] fp32  ->  B [N, 3K] bf16, layout [hi|hi|lo]
__global__ __launch_bounds__(256) void convW_kernel(const float* __restrict__ W,
                                                    __nv_bfloat16* __restrict__ B, int N)
{
    __shared__ float t[32][33];
    const int n0 = blockIdx.x * 32;
    const int k0 = blockIdx.y * 32;
    const int tx = threadIdx.x & 31;
    const int ty = threadIdx.x >> 5;          // 0..7
    #pragma unroll
    for (int i = 0; i < 4; ++i)
        t[ty + 8 * i][tx] = W[(size_t)(k0 + ty + 8 * i) * N + n0 + tx];
    __syncthreads();
    #pragma unroll
    for (int i = 0; i < 4; ++i) {
        const int n = n0 + ty + 8 * i;
        const int k = k0 + tx;
        const float v = t[tx][ty + 8 * i];
        const __nv_bfloat16 hi = __float2bfloat16(v);
        const __nv_bfloat16 lo = __float2bfloat16(v - __bfloat162float(hi));
        __nv_bfloat16* row = B + (size_t)n * KEFF;
        row[k]        = hi;
        row[1024 + k] = hi;
        row[2048 + k] = lo;
    }
}

// ---------------------------------------------------------------------------
// mma.sync bf16 GEMM (unchanged from R3):  C[M,N] = A' @ B'^T + bias
// ---------------------------------------------------------------------------
#define BM 128
#define BN 128
#define BK 32
#define KST 40
#define NCHUNKG (KEFF / BK)

__global__ __launch_bounds__(256) void gemm_mma_kernel(
    const __nv_bfloat16* __restrict__ A, const __nv_bfloat16* __restrict__ Bm,
    const float* __restrict__ bias, float* __restrict__ C, int N)
{
    __shared__ __align__(16) __nv_bfloat16 As[2][BM * KST];
    __shared__ __align__(16) __nv_bfloat16 Bs[2][BN * KST];

    const int tid  = threadIdx.x;
    const int wid  = tid >> 5;
    const int lane = tid & 31;
    const int wm   = wid >> 2;
    const int wn   = wid & 3;
    const int rowBase = blockIdx.y * BM;
    const int colBase = blockIdx.x * BN;

    const uint32_t asAddr[2] = { smem_u32(As[0]), smem_u32(As[1]) };
    const uint32_t bsAddr[2] = { smem_u32(Bs[0]), smem_u32(Bs[1]) };

    float acc[4][4][4] = {};

    const int lr = tid >> 2;
    const int lj = tid & 3;

    auto loadChunk = [&](int c, int buf) {
        const __nv_bfloat16* Ag = A + (size_t)rowBase * KEFF + c * BK;
        const __nv_bfloat16* Bg = Bm + (size_t)colBase * KEFF + c * BK;
        #pragma unroll
        for (int i = 0; i < 2; ++i) {
            const int r = lr + i * 64;
            cp_async16(asAddr[buf] + r * (KST * 2) + lj * 16, Ag + (size_t)r * KEFF + lj * 8);
            cp_async16(bsAddr[buf] + r * (KST * 2) + lj * 16, Bg + (size_t)r * KEFF + lj * 8);
        }
        cp_commit();
    };

    loadChunk(0, 0);

    for (int c = 0; c < NCHUNKG; ++c) {
        const int buf = c & 1;
        cp_wait0();
        __syncthreads();
        if (c + 1 < NCHUNKG) loadChunk(c + 1, buf ^ 1);

        #pragma unroll
        for (int ks = 0; ks < 2; ++ks) {
            uint32_t afr[4][4];
            #pragma unroll
            for (int mt = 0; mt < 4; ++mt) {
                const int row = wm * 64 + mt * 16 + (lane & 15);
                const int col = ks * 16 + ((lane >> 4) << 3);
                ldsm_x4(afr[mt], asAddr[buf] + (row * KST + col) * 2);
            }
            uint32_t bfr[4][2];
            #pragma unroll
            for (int nt = 0; nt < 4; ++nt) {
                const int nrow = wn * 32 + nt * 8 + (lane & 7);
                const int col  = ks * 16 + ((lane >> 3) & 1) * 8;
                ldsm_x2(bfr[nt], bsAddr[buf] + (nrow * KST + col) * 2);
            }
            #pragma unroll
            for (int mt = 0; mt < 4; ++mt)
                #pragma unroll
                for (int nt = 0; nt < 4; ++nt)
                    mma_bf16(acc[mt][nt], afr[mt], bfr[nt]);
        }
    }

    const int erow = lane >> 2;
    const int ecol = (lane & 3) * 2;
    #pragma unroll
    for (int mt = 0; mt < 4; ++mt) {
        const int rA = rowBase + wm * 64 + mt * 16 + erow;
        #pragma unroll
        for (int nt = 0; nt < 4; ++nt) {
            const int col = colBase + wn * 32 + nt * 8 + ecol;
            const float b0 = bias[col], b1 = bias[col + 1];
            *(float2*)&C[(size_t)rA * N + col] =
                make_float2(acc[mt][nt][0] + b0, acc[mt][nt][1] + b1);
            *(float2*)&C[(size_t)(rA + 8) * N + col] =
                make_float2(acc[mt][nt][2] + b0, acc[mt][nt][3] + b1);
        }
    }
}

// ---------------------------------------------------------------------------
// RMSNorm (in-place on q and k sections of g_qkv)
// ---------------------------------------------------------------------------
__global__ __launch_bounds__(256) void rmsnorm_kernel(
    float* __restrict__ qkv,
    const float* __restrict__ qn_w, const float* __restrict__ kn_w)
{
    const int gwarp = (blockIdx.x * blockDim.x + threadIdx.x) >> 5;
    const int lane  = threadIdx.x & 31;
    const int token = gwarp >> 5;
    const int slot  = gwarp & 31;
    if (token >= TOKENS) return;

    const bool is_q = (slot < 16);
    const int  h    = slot & 15;
    const float* w  = is_q ? qn_w : kn_w;
    float* row = qkv + (size_t)token * QKVDIM + (is_q ? 0 : CDIM) + h * HDIM;

    float x0 = row[lane];
    float x1 = row[lane + 32];
    float ss = x0 * x0 + x1 * x1;
    #pragma unroll
    for (int off = 16; off; off >>= 1) ss += __shfl_xor_sync(0xffffffffu, ss, off);
    const float inv = rsqrtf(ss * (1.0f / 64.0f) + 1e-6f);
    row[lane]      = x0 * inv * w[lane];
    row[lane + 32] = x1 * inv * w[lane + 32];
}

// ---------------------------------------------------------------------------
// K/V bf16 split precompute: g_qkv -> g_ks / g_vs rows of [hi(64)|lo(64)]
// One thread per (bh, c, pair-of-d). Run AFTER rmsnorm.
// ---------------------------------------------------------------------------
__global__ __launch_bounds__(256) void kvsplit_kernel(const float* __restrict__ qkv,
                                                      __nv_bfloat16* __restrict__ ks,
                                                      __nv_bfloat16* __restrict__ vs)
{
    const int idx = blockIdx.x * 256 + threadIdx.x;   // over 64 * 2048 * 32
    const int d2 = idx & 31;
    const int c  = (idx >> 5) & 2047;
    const int bh = idx >> 16;
    const int b  = bh >> 4;
    const int h  = bh & 15;
    const int d  = d2 * 2;

    const size_t srcRow = ((size_t)(b * SEQ + c)) * QKVDIM + h * HDIM + d;
    const size_t dstRow = ((size_t)bh * SEQ + c) * 128;

    {   // K
        const float2 v = *(const float2*)&qkv[srcRow + CDIM];
        const uint32_t hp = bf16pack(v.x, v.y);
        *(uint32_t*)&ks[dstRow + d]      = hp;
        *(uint32_t*)&ks[dstRow + 64 + d] = bf16pack_lo(v.x, v.y, hp);
    }
    {   // V
        const float2 v = *(const float2*)&qkv[srcRow + 2 * CDIM];
        const uint32_t hp = bf16pack(v.x, v.y);
        *(uint32_t*)&vs[dstRow + d]      = hp;
        *(uint32_t*)&vs[dstRow + 64 + d] = bf16pack_lo(v.x, v.y, hp);
    }
}

// ---------------------------------------------------------------------------
// FlashAttention-2 style mma.sync attention.
// CTA = 128 q-rows x one (b,h); 8 warps x 16 rows. Bc = 64 keys per tile.
// Smem: double-buffered K,V tiles, 256B rows [hi64|lo64], XOR-swizzled 16B chunks.
// 3-term bf16 split for S and PV. Base-2 online softmax. Out -> g_A2 split triple.
// ---------------------------------------------------------------------------
#define ATT_NT (SEQ / 64)             // 32 key tiles
#define ATT_TILE_B 16384              // one matrix tile: 64 rows * 256B
#define ATT_BUF_B  32768              // K + V
#define ATT_SMEM   65536

__global__ __launch_bounds__(256, 1) void attn_mma_kernel(
    const float* __restrict__ qkv,
    const __nv_bfloat16* __restrict__ ks, const __nv_bfloat16* __restrict__ vs,
    __nv_bfloat16* __restrict__ outA)
{
    extern __shared__ __align__(256) char sm[];
    const uint32_t smBase = smem_u32(sm);

    const int tid  = threadIdx.x;
    const int wq   = tid >> 5;            // warp 0..7 -> q-row block
    const int lane = tid & 31;

    const int bh = blockIdx.y;
    const int b  = bh >> 4;
    const int h  = bh & 15;
    const int qBase = blockIdx.x * 128;

    // ---- Load Q fragments (hi/lo), scale folded: 0.125 * log2(e) ----
    const float SC = 0.125f * 1.44269504088896340736f;
    uint32_t qh[4][4], ql[4][4];
    {
        const float* qg = qkv + ((size_t)(b * SEQ + qBase + wq * 16)) * QKVDIM + h * HDIM;
        const int rr = lane >> 2;
        const int cb = (lane & 3) * 2;
        #pragma unroll
        for (int kd = 0; kd < 4; ++kd) {
            const int d0 = kd * 16;
            float2 v0 = *(const float2*)&qg[(size_t)rr * QKVDIM + d0 + cb];
            float2 v1 = *(const float2*)&qg[(size_t)(rr + 8) * QKVDIM + d0 + cb];
            float2 v2 = *(const float2*)&qg[(size_t)rr * QKVDIM + d0 + cb + 8];
            float2 v3 = *(const float2*)&qg[(size_t)(rr + 8) * QKVDIM + d0 + cb + 8];
            v0.x *= SC; v0.y *= SC; v1.x *= SC; v1.y *= SC;
            v2.x *= SC; v2.y *= SC; v3.x *= SC; v3.y *= SC;
            qh[kd][0] = bf16pack(v0.x, v0.y); ql[kd][0] = bf16pack_lo(v0.x, v0.y, qh[kd][0]);
            qh[kd][1] = bf16pack(v1.x, v1.y); ql[kd][1] = bf16pack_lo(v1.x, v1.y, qh[kd][1]);
            qh[kd][2] = bf16pack(v2.x, v2.y); ql[kd][2] = bf16pack_lo(v2.x, v2.y, qh[kd][2]);
            qh[kd][3] = bf16pack(v3.x, v3.y); ql[kd][3] = bf16pack_lo(v3.x, v3.y, qh[kd][3]);
        }
    }

    // ---- cp.async tile loader ----
    auto loadTile = [&](int kt, int buf) {
        const __nv_bfloat16* gk = ks + ((size_t)bh * SEQ + kt * 64) * 128;
        const __nv_bfloat16* gv = vs + ((size_t)bh * SEQ + kt * 64) * 128;
        const uint32_t kb = smBase + buf * ATT_BUF_B;
        const uint32_t vb = kb + ATT_TILE_B;
        #pragma unroll
        for (int m = 0; m < 4; ++m) {
            const int id = tid + m * 256;           // 0..1023
            const int c = id >> 4, j = id & 15;
            const uint32_t soff = c * 256 + ((j ^ (c & 7)) << 4);
            cp_async16(kb + soff, gk + (size_t)c * 128 + j * 8);
            cp_async16(vb + soff, gv + (size_t)c * 128 + j * 8);
        }
        cp_commit();
    };

    float m0 = -CUDART_INF_F, m1 = -CUDART_INF_F, l0 = 0.0f, l1 = 0.0f;
    float O[8][4] = {};

    loadTile(0, 0);

    for (int kt = 0; kt < ATT_NT; ++kt) {
        const int buf = kt & 1;
        __syncthreads();                              // prior compute on buf^1 done
        if (kt + 1 < ATT_NT) { loadTile(kt + 1, buf ^ 1); cp_wait1(); }
        else                 { cp_wait0(); }
        __syncthreads();                              // tile kt visible

        const uint32_t Kb = smBase + buf * ATT_BUF_B;
        const uint32_t Vb = Kb + ATT_TILE_B;

        // ---- S = Q' K'^T (3-term split) ----
        float S[8][4] = {};
        #pragma unroll
        for (int kd = 0; kd < 4; ++kd) {
            uint32_t kh[8][2];
            #pragma unroll
            for (int t = 0; t < 4; ++t) {
                const int row = 16 * t + (lane & 7) + 8 * ((lane >> 4) & 1);
                const int j = kd * 2 + ((lane >> 3) & 1);            // hi region
                uint32_t r[4];
                ldsm_x4(r, Kb + row * 256 + ((j ^ (row & 7)) << 4));
                kh[2 * t][0] = r[0]; kh[2 * t][1] = r[1];
                kh[2 * t + 1][0] = r[2]; kh[2 * t + 1][1] = r[3];
            }
            #pragma unroll
            for (int nc = 0; nc < 8; ++nc) {
                mma_bf16(S[nc], qh[kd], kh[nc]);
                mma_bf16(S[nc], ql[kd], kh[nc]);
            }
            uint32_t kl[8][2];
            #pragma unroll
            for (int t = 0; t < 4; ++t) {
                const int row = 16 * t + (lane & 7) + 8 * ((lane >> 4) & 1);
                const int j = kd * 2 + ((lane >> 3) & 1) + 8;        // lo region
                uint32_t r[4];
                ldsm_x4(r, Kb + row * 256 + ((j ^ (row & 7)) << 4));
                kl[2 * t][0] = r[0]; kl[2 * t][1] = r[1];
                kl[2 * t + 1][0] = r[2]; kl[2 * t + 1][1] = r[3];
            }
            #pragma unroll
            for (int nc = 0; nc < 8; ++nc)
                mma_bf16(S[nc], qh[kd], kl[nc]);
        }

        // ---- Online softmax (base 2) ----
        float mt0 = -CUDART_INF_F, mt1 = -CUDART_INF_F;
        #pragma unroll
        for (int nc = 0; nc < 8; ++nc) {
            mt0 = fmaxf(mt0, fmaxf(S[nc][0], S[nc][1]));
            mt1 = fmaxf(mt1, fmaxf(S[nc][2], S[nc][3]));
        }
        mt0 = fmaxf(mt0, __shfl_xor_sync(0xffffffffu, mt0, 1));
        mt0 = fmaxf(mt0, __shfl_xor_sync(0xffffffffu, mt0, 2));
        mt1 = fmaxf(mt1, __shfl_xor_sync(0xffffffffu, mt1, 1));
        mt1 = fmaxf(mt1, __shfl_xor_sync(0xffffffffu, mt1, 2));
        const float mn0 = fmaxf(m0, mt0);
        const float mn1 = fmaxf(m1, mt1);
        const float c0 = ex2f(m0 - mn0);
        const float c1 = ex2f(m1 - mn1);
        m0 = mn0; m1 = mn1;
        float rs0 = 0.0f, rs1 = 0.0f;
        #pragma unroll
        for (int nc = 0; nc < 8; ++nc) {
            S[nc][0] = ex2f(S[nc][0] - mn0); rs0 += S[nc][0];
            S[nc][1] = ex2f(S[nc][1] - mn0); rs0 += S[nc][1];
            S[nc][2] = ex2f(S[nc][2] - mn1); rs1 += S[nc][2];
            S[nc][3] = ex2f(S[nc][3] - mn1); rs1 += S[nc][3];
        }
        rs0 += __shfl_xor_sync(0xffffffffu, rs0, 1);
        rs0 += __shfl_xor_sync(0xffffffffu, rs0, 2);
        rs1 += __shfl_xor_sync(0xffffffffu, rs1, 1);
        rs1 += __shfl_xor_sync(0xffffffffu, rs1, 2);
        l0 = l0 * c0 + rs0;
        l1 = l1 * c1 + rs1;
        #pragma unroll
        for (int nd = 0; nd < 8; ++nd) {
            O[nd][0] *= c0; O[nd][1] *= c0; O[nd][2] *= c1; O[nd][3] *= c1;
        }

        // ---- O += P V (3-term split; P frags built from S accumulators) ----
        #pragma unroll
        for (int kc = 0; kc < 4; ++kc) {
            uint32_t ph[4], pl[4];
            {
                const float* s0 = S[2 * kc];
                const float* s1 = S[2 * kc + 1];
                ph[0] = bf16pack(s0[0], s0[1]); pl[0] = bf16pack_lo(s0[0], s0[1], ph[0]);
                ph[1] = bf16pack(s0[2], s0[3]); pl[1] = bf16pack_lo(s0[2], s0[3], ph[1]);
                ph[2] = bf16pack(s1[0], s1[1]); pl[2] = bf16pack_lo(s1[0], s1[1], ph[2]);
                ph[3] = bf16pack(s1[2], s1[3]); pl[3] = bf16pack_lo(s1[2], s1[3], ph[3]);
            }
            uint32_t vh[8][2];
            #pragma unroll
            for (int t = 0; t < 4; ++t) {
                const int row = kc * 16 + (lane & 7) + 8 * ((lane >> 3) & 1);
                const int j = 2 * t + ((lane >> 4) & 1);             // hi region
                uint32_t r[4];
                ldsm_x4_t(r, Vb + row * 256 + ((j ^ (row & 7)) << 4));
                vh[2 * t][0] = r[0]; vh[2 * t][1] = r[1];
                vh[2 * t + 1][0] = r[2]; vh[2 * t + 1][1] = r[3];
            }
            #pragma unroll
            for (int nd = 0; nd < 8; ++nd) {
                mma_bf16(O[nd], ph, vh[nd]);
                mma_bf16(O[nd], pl, vh[nd]);
            }
            uint32_t vl[8][2];
            #pragma unroll
            for (int t = 0; t < 4; ++t) {
                const int row = kc * 16 + (lane & 7) + 8 * ((lane >> 3) & 1);
                const int j = 2 * t + ((lane >> 4) & 1) + 8;         // lo region
                uint32_t r[4];
                ldsm_x4_t(r, Vb + row * 256 + ((j ^ (row & 7)) << 4));
                vl[2 * t][0] = r[0]; vl[2 * t][1] = r[1];
                vl[2 * t + 1][0] = r[2]; vl[2 * t + 1][1] = r[3];
            }
            #pragma unroll
            for (int nd = 0; nd < 8; ++nd)
                mma_bf16(O[nd], ph, vl[nd]);
        }
    }

    // ---- Epilogue: normalize, write hi/lo/hi split rows to outA ----
    const float inv0 = 1.0f / l0;
    const float inv1 = 1.0f / l1;
    const size_t row1 = (size_t)b * SEQ + qBase + wq * 16 + (lane >> 2);
    const int colBase = h * HDIM + (lane & 3) * 2;
    #pragma unroll
    for (int nd = 0; nd < 8; ++nd) {
        const int col = colBase + nd * 8;
        {
            const float x = O[nd][0] * inv0, y = O[nd][1] * inv0;
            __nv_bfloat16* p = outA + row1 * KEFF + col;
            const uint32_t hp = bf16pack(x, y);
            *(uint32_t*)p = hp;
            *(uint32_t*)(p + 1024) = bf16pack_lo(x, y, hp);
            *(uint32_t*)(p + 2048) = hp;
        }
        {
            const float x = O[nd][2] * inv1, y = O[nd][3] * inv1;
            __nv_bfloat16* p = outA + (row1 + 8) * KEFF + col;
            const uint32_t hp = bf16pack(x, y);
            *(uint32_t*)p = hp;
            *(uint32_t*)(p + 1024) = bf16pack_lo(x, y, hp);
            *(uint32_t*)(p + 2048) = hp;
        }
    }
}

// ---------------------------------------------------------------------------
// Launch
// ---------------------------------------------------------------------------
extern "C" void kernel_launch(void* const* d_in, const int* in_sizes, int n_in,
                              void* d_out, int out_size)
{
    (void)in_sizes; (void)n_in; (void)out_size;
    const float* x      = (const float*)d_in[0];
    const float* W_qkv  = (const float*)d_in[1];
    const float* b_qkv  = (const float*)d_in[2];
    const float* W_proj = (const float*)d_in[3];
    const float* b_proj = (const float*)d_in[4];
    const float* qn_w   = (const float*)d_in[5];
    const float* kn_w   = (const float*)d_in[6];
    float* out = (float*)d_out;

    float *qkv = nullptr;
    __nv_bfloat16 *A1 = nullptr, *B1 = nullptr, *B2 = nullptr, *A2 = nullptr;
    __nv_bfloat16 *ksp = nullptr, *vsp = nullptr;
    cudaGetSymbolAddress((void**)&qkv, g_qkv);
    cudaGetSymbolAddress((void**)&A1,  g_A1);
    cudaGetSymbolAddress((void**)&B1,  g_B1);
    cudaGetSymbolAddress((void**)&B2,  g_B2);
    cudaGetSymbolAddress((void**)&A2,  g_A2);
    cudaGetSymbolAddress((void**)&ksp, g_ks);
    cudaGetSymbolAddress((void**)&vsp, g_vs);

    cudaFuncSetAttribute(attn_mma_kernel, cudaFuncAttributeMaxDynamicSharedMemorySize, ATT_SMEM);

    // 0) Conversions to bf16 split formats
    convX_kernel<<<(TOKENS * CDIM) / 256, 256>>>(x, A1);
    convW_kernel<<<dim3(QKVDIM / 32, CDIM / 32), 256>>>(W_qkv, B1, QKVDIM);
    convW_kernel<<<dim3(CDIM / 32, CDIM / 32), 256>>>(W_proj, B2, CDIM);

    // 1) QKV projection: [8192, 3072] = A1 @ B1^T + b_qkv
    gemm_mma_kernel<<<dim3(QKVDIM / BN, TOKENS / BM), 256>>>(A1, B1, b_qkv, qkv, QKVDIM);

    // 2) RMSNorm on q and k heads (in place)
    rmsnorm_kernel<<<(TOKENS * 32) / 8, 256>>>(qkv, qn_w, kn_w);

    // 3) K/V bf16 hi/lo split precompute
    kvsplit_kernel<<<(BATCH * HEADS * SEQ * 32) / 256, 256>>>(qkv, ksp, vsp);

    // 4) Attention (tensor cores) -> g_A2 (bf16 split, proj-ready)
    attn_mma_kernel<<<dim3(SEQ / 128, BATCH * HEADS), 256, ATT_SMEM>>>(qkv, ksp, vsp, A2);

    // 5) Output projection: [8192, 1024] = A2 @ B2^T + b_proj
    gemm_mma_kernel<<<dim3(CDIM / BN, TOKENS / BM), 256>>>(A2, B2, b_proj, out, CDIM);
}

// round 5
// speedup vs baseline: 3.5658x; 1.1891x over previous
#include <cuda_runtime.h>
#include <cuda_bf16.h>
#include <math_constants.h>
#include <cstdint>

// Problem constants
#define BATCH 4
#define SEQ   2048
#define CDIM  1024
#define HEADS 16
#define HDIM  64
#define TOKENS (BATCH * SEQ)         // 8192
#define QKVDIM (3 * CDIM)            // 3072
#define KEFF   3072                  // 3 * 1024 (bf16 split-K for both GEMMs)

// ---------------------------------------------------------------------------
// Scratch (device globals — no allocation allowed)
// ---------------------------------------------------------------------------
__device__ float g_qkv[(size_t)TOKENS * QKVDIM];                       // QKV output fp32
__device__ __align__(256) __nv_bfloat16 g_A1[(size_t)TOKENS * KEFF];  // x split       [m, hi|lo|hi]
__device__ __align__(256) __nv_bfloat16 g_B1[(size_t)QKVDIM * KEFF];  // W_qkv^T split [n, hi|hi|lo]
__device__ __align__(256) __nv_bfloat16 g_B2[(size_t)CDIM * KEFF];    // W_proj^T split
__device__ __align__(256) __nv_bfloat16 g_A2[(size_t)TOKENS * KEFF];  // attn out split [m, hi|lo|hi]
__device__ __align__(256) __nv_bfloat16 g_ks[(size_t)BATCH * HEADS * SEQ * 128]; // K split [hi64|lo64]
__device__ __align__(256) __nv_bfloat16 g_vs[(size_t)BATCH * HEADS * SEQ * 128]; // V split [hi64|lo64]

// ---------------------------------------------------------------------------
// PTX helpers (portable sm_80+ features only)
// ---------------------------------------------------------------------------
__device__ __forceinline__ uint32_t smem_u32(const void* p) {
    uint32_t a;
    asm("{ .reg .u64 t; cvta.to.shared.u64 t, %1; cvt.u32.u64 %0, t; }" : "=r"(a) : "l"(p));
    return a;
}
__device__ __forceinline__ void cp_async16(uint32_t dst, const void* src) {
    asm volatile("cp.async.cg.shared.global [%0], [%1], 16;" :: "r"(dst), "l"(src));
}
__device__ __forceinline__ void cp_commit() {
    asm volatile("cp.async.commit_group;" ::: "memory");
}
__device__ __forceinline__ void cp_wait0() {
    asm volatile("cp.async.wait_group 0;" ::: "memory");
}
__device__ __forceinline__ void cp_wait1() {
    asm volatile("cp.async.wait_group 1;" ::: "memory");
}
__device__ __forceinline__ void ldsm_x4(uint32_t* r, uint32_t addr) {
    asm volatile("ldmatrix.sync.aligned.m8n8.x4.shared.b16 {%0,%1,%2,%3}, [%4];"
                 : "=r"(r[0]), "=r"(r[1]), "=r"(r[2]), "=r"(r[3]) : "r"(addr));
}
__device__ __forceinline__ void ldsm_x4_t(uint32_t* r, uint32_t addr) {
    asm volatile("ldmatrix.sync.aligned.m8n8.x4.trans.shared.b16 {%0,%1,%2,%3}, [%4];"
                 : "=r"(r[0]), "=r"(r[1]), "=r"(r[2]), "=r"(r[3]) : "r"(addr));
}
__device__ __forceinline__ void mma_bf16(float* c, const uint32_t* a, const uint32_t* b) {
    asm volatile(
        "mma.sync.aligned.m16n8k16.row.col.f32.bf16.bf16.f32 "
        "{%0,%1,%2,%3}, {%4,%5,%6,%7}, {%8,%9}, {%0,%1,%2,%3};"
        : "+f"(c[0]), "+f"(c[1]), "+f"(c[2]), "+f"(c[3])
        : "r"(a[0]), "r"(a[1]), "r"(a[2]), "r"(a[3]), "r"(b[0]), "r"(b[1]));
}
__device__ __forceinline__ float ex2f(float x) {
    float y; asm("ex2.approx.ftz.f32 %0, %1;" : "=f"(y) : "f"(x)); return y;
}
__device__ __forceinline__ uint32_t bf16pack(float a, float b) {
    __nv_bfloat162 h;
    h.x = __float2bfloat16(a);
    h.y = __float2bfloat16(b);
    return *(uint32_t*)&h;
}
__device__ __forceinline__ uint32_t bf16pack_lo(float a, float b, uint32_t hipack) {
    __nv_bfloat162 h = *(__nv_bfloat162*)&hipack;
    return bf16pack(a - __bfloat162float(h.x), b - __bfloat162float(h.y));
}

// ---------------------------------------------------------------------------
// Conversion kernels (fp32 -> bf16 hi/lo split)
// ---------------------------------------------------------------------------
__global__ __launch_bounds__(256) void convX_kernel(const float* __restrict__ x,
                                                    __nv_bfloat16* __restrict__ A)
{
    const int idx = blockIdx.x * 256 + threadIdx.x;      // over TOKENS*CDIM
    const int m = idx >> 10;
    const int k = idx & 1023;
    const float v = x[idx];
    const __nv_bfloat16 hi = __float2bfloat16(v);
    const __nv_bfloat16 lo = __float2bfloat16(v - __bfloat162float(hi));
    __nv_bfloat16* row = A + (size_t)m * KEFF;
    row[k]        = hi;
    row[1024 + k] = lo;
    row[2048 + k] = hi;
}

// Transpose + split: W [K=1024, N] fp32  ->  B [N, 3K] bf16, layout [hi|hi|lo]
__global__ __launch_bounds__(256) void convW_kernel(const float* __restrict__ W,
                                                    __nv_bfloat16* __restrict__ B, int N)
{
    __shared__ float t[32][33];
    const int n0 = blockIdx.x * 32;
    const int k0 = blockIdx.y * 32;
    const int tx = threadIdx.x & 31;
    const int ty = threadIdx.x >> 5;          // 0..7
    #pragma unroll
    for (int i = 0; i < 4; ++i)
        t[ty + 8 * i][tx] = W[(size_t)(k0 + ty + 8 * i) * N + n0 + tx];
    __syncthreads();
    #pragma unroll
    for (int i = 0; i < 4; ++i) {
        const int n = n0 + ty + 8 * i;
        const int k = k0 + tx;
        const float v = t[tx][ty + 8 * i];
        const __nv_bfloat16 hi = __float2bfloat16(v);
        const __nv_bfloat16 lo = __float2bfloat16(v - __bfloat162float(hi));
        __nv_bfloat16* row = B + (size_t)n * KEFF;
        row[k]        = hi;
        row[1024 + k] = hi;
        row[2048 + k] = lo;
    }
}

// ---------------------------------------------------------------------------
// mma.sync bf16 GEMM v2:  C[M,N] = A' @ B'^T + bias
// CTA 128x128, 8 warps (2x4), warp tile 64x32. BK=64 (128B rows, XOR swizzle),
// 3-stage cp.async pipeline, A and B fragments via ldmatrix.x4.
// ---------------------------------------------------------------------------
#define BM 128
#define BN 128
#define BK 64
#define G_STAGES 3
#define G_STAGE_A (BM * BK * 2)          // 16384
#define G_STAGE_BYTES (2 * G_STAGE_A)    // 32768 (A + B)
#define G_SMEM (G_STAGES * G_STAGE_BYTES)// 98304
#define NCHUNKG (KEFF / BK)              // 48

__global__ __launch_bounds__(256) void gemm_mma_kernel(
    const __nv_bfloat16* __restrict__ A, const __nv_bfloat16* __restrict__ Bm,
    const float* __restrict__ bias, float* __restrict__ C, int N)
{
    extern __shared__ __align__(256) char gsm[];
    const uint32_t base = smem_u32(gsm);

    const int tid  = threadIdx.x;
    const int wid  = tid >> 5;
    const int lane = tid & 31;
    const int wm   = wid >> 2;           // 0..1
    const int wn   = wid & 3;            // 0..3
    const int rowBase = blockIdx.y * BM;
    const int colBase = blockIdx.x * BN;

    float acc[4][4][4] = {};

    // loader: per stage each matrix = 128 rows x 8 chunks(16B); 4 chunks/thread each
    const int lrow = tid >> 3;           // 0..31 (x4 via +32)
    const int lch  = tid & 7;

    auto loadStage = [&](int c, int s) {
        const __nv_bfloat16* Ag = A + (size_t)rowBase * KEFF + c * BK;
        const __nv_bfloat16* Bg = Bm + (size_t)colBase * KEFF + c * BK;
        const uint32_t as = base + s * G_STAGE_BYTES;
        const uint32_t bs = as + G_STAGE_A;
        #pragma unroll
        for (int m = 0; m < 4; ++m) {
            const int row = lrow + m * 32;
            const uint32_t soff = row * 128 + ((lch ^ (row & 7)) << 4);
            cp_async16(as + soff, Ag + (size_t)row * KEFF + lch * 8);
            cp_async16(bs + soff, Bg + (size_t)row * KEFF + lch * 8);
        }
        cp_commit();
    };

    loadStage(0, 0);
    loadStage(1, 1);

    int s = 0;
    for (int c = 0; c < NCHUNKG; ++c) {
        if (c + 2 < NCHUNKG) cp_wait1(); else cp_wait0();
        __syncthreads();
        if (c + 2 < NCHUNKG) loadStage(c + 2, (s + 2) % G_STAGES);

        const uint32_t as = base + s * G_STAGE_BYTES;
        const uint32_t bs = as + G_STAGE_A;

        #pragma unroll
        for (int ks = 0; ks < 4; ++ks) {
            uint32_t afr[4][4];
            #pragma unroll
            for (int mt = 0; mt < 4; ++mt) {
                const int row = wm * 64 + mt * 16 + (lane & 15);
                const int ch  = ks * 2 + (lane >> 4);
                ldsm_x4(afr[mt], as + row * 128 + ((ch ^ (row & 7)) << 4));
            }
            uint32_t bfr[4][2];
            #pragma unroll
            for (int ntp = 0; ntp < 2; ++ntp) {
                const int row = wn * 32 + ntp * 16 + (lane & 7) + ((lane >> 4) << 3);
                const int ch  = ks * 2 + ((lane >> 3) & 1);
                uint32_t r[4];
                ldsm_x4(r, bs + row * 128 + ((ch ^ (row & 7)) << 4));
                bfr[2 * ntp][0]     = r[0]; bfr[2 * ntp][1]     = r[1];
                bfr[2 * ntp + 1][0] = r[2]; bfr[2 * ntp + 1][1] = r[3];
            }
            #pragma unroll
            for (int mt = 0; mt < 4; ++mt)
                #pragma unroll
                for (int nt = 0; nt < 4; ++nt)
                    mma_bf16(acc[mt][nt], afr[mt], bfr[nt]);
        }
        s = (s + 1) % G_STAGES;
        __syncthreads();
    }

    // Epilogue
    const int erow = lane >> 2;
    const int ecol = (lane & 3) * 2;
    #pragma unroll
    for (int mt = 0; mt < 4; ++mt) {
        const int rA = rowBase + wm * 64 + mt * 16 + erow;
        #pragma unroll
        for (int nt = 0; nt < 4; ++nt) {
            const int col = colBase + wn * 32 + nt * 8 + ecol;
            const float b0 = bias[col], b1 = bias[col + 1];
            *(float2*)&C[(size_t)rA * N + col] =
                make_float2(acc[mt][nt][0] + b0, acc[mt][nt][1] + b1);
            *(float2*)&C[(size_t)(rA + 8) * N + col] =
                make_float2(acc[mt][nt][2] + b0, acc[mt][nt][3] + b1);
        }
    }
}

// ---------------------------------------------------------------------------
// RMSNorm (in-place on q and k sections of g_qkv)
// ---------------------------------------------------------------------------
__global__ __launch_bounds__(256) void rmsnorm_kernel(
    float* __restrict__ qkv,
    const float* __restrict__ qn_w, const float* __restrict__ kn_w)
{
    const int gwarp = (blockIdx.x * blockDim.x + threadIdx.x) >> 5;
    const int lane  = threadIdx.x & 31;
    const int token = gwarp >> 5;
    const int slot  = gwarp & 31;
    if (token >= TOKENS) return;

    const bool is_q = (slot < 16);
    const int  h    = slot & 15;
    const float* w  = is_q ? qn_w : kn_w;
    float* row = qkv + (size_t)token * QKVDIM + (is_q ? 0 : CDIM) + h * HDIM;

    float x0 = row[lane];
    float x1 = row[lane + 32];
    float ss = x0 * x0 + x1 * x1;
    #pragma unroll
    for (int off = 16; off; off >>= 1) ss += __shfl_xor_sync(0xffffffffu, ss, off);
    const float inv = rsqrtf(ss * (1.0f / 64.0f) + 1e-6f);
    row[lane]      = x0 * inv * w[lane];
    row[lane + 32] = x1 * inv * w[lane + 32];
}

// ---------------------------------------------------------------------------
// K/V bf16 split precompute: g_qkv -> g_ks / g_vs rows of [hi(64)|lo(64)]
// ---------------------------------------------------------------------------
__global__ __launch_bounds__(256) void kvsplit_kernel(const float* __restrict__ qkv,
                                                      __nv_bfloat16* __restrict__ ks,
                                                      __nv_bfloat16* __restrict__ vs)
{
    const int idx = blockIdx.x * 256 + threadIdx.x;   // over 64 * 2048 * 32
    const int d2 = idx & 31;
    const int c  = (idx >> 5) & 2047;
    const int bh = idx >> 16;
    const int b  = bh >> 4;
    const int h  = bh & 15;
    const int d  = d2 * 2;

    const size_t srcRow = ((size_t)(b * SEQ + c)) * QKVDIM + h * HDIM + d;
    const size_t dstRow = ((size_t)bh * SEQ + c) * 128;

    {   // K
        const float2 v = *(const float2*)&qkv[srcRow + CDIM];
        const uint32_t hp = bf16pack(v.x, v.y);
        *(uint32_t*)&ks[dstRow + d]      = hp;
        *(uint32_t*)&ks[dstRow + 64 + d] = bf16pack_lo(v.x, v.y, hp);
    }
    {   // V
        const float2 v = *(const float2*)&qkv[srcRow + 2 * CDIM];
        const uint32_t hp = bf16pack(v.x, v.y);
        *(uint32_t*)&vs[dstRow + d]      = hp;
        *(uint32_t*)&vs[dstRow + 64 + d] = bf16pack_lo(v.x, v.y, hp);
    }
}

// ---------------------------------------------------------------------------
// FlashAttention-2 style mma.sync attention (unchanged from R4).
// ---------------------------------------------------------------------------
#define ATT_NT (SEQ / 64)             // 32 key tiles
#define ATT_TILE_B 16384              // one matrix tile: 64 rows * 256B
#define ATT_BUF_B  32768              // K + V
#define ATT_SMEM   65536

__global__ __launch_bounds__(256, 1) void attn_mma_kernel(
    const float* __restrict__ qkv,
    const __nv_bfloat16* __restrict__ ks, const __nv_bfloat16* __restrict__ vs,
    __nv_bfloat16* __restrict__ outA)
{
    extern __shared__ __align__(256) char sm[];
    const uint32_t smBase = smem_u32(sm);

    const int tid  = threadIdx.x;
    const int wq   = tid >> 5;
    const int lane = tid & 31;

    const int bh = blockIdx.y;
    const int b  = bh >> 4;
    const int h  = bh & 15;
    const int qBase = blockIdx.x * 128;

    const float SC = 0.125f * 1.44269504088896340736f;
    uint32_t qh[4][4], ql[4][4];
    {
        const float* qg = qkv + ((size_t)(b * SEQ + qBase + wq * 16)) * QKVDIM + h * HDIM;
        const int rr = lane >> 2;
        const int cb = (lane & 3) * 2;
        #pragma unroll
        for (int kd = 0; kd < 4; ++kd) {
            const int d0 = kd * 16;
            float2 v0 = *(const float2*)&qg[(size_t)rr * QKVDIM + d0 + cb];
            float2 v1 = *(const float2*)&qg[(size_t)(rr + 8) * QKVDIM + d0 + cb];
            float2 v2 = *(const float2*)&qg[(size_t)rr * QKVDIM + d0 + cb + 8];
            float2 v3 = *(const float2*)&qg[(size_t)(rr + 8) * QKVDIM + d0 + cb + 8];
            v0.x *= SC; v0.y *= SC; v1.x *= SC; v1.y *= SC;
            v2.x *= SC; v2.y *= SC; v3.x *= SC; v3.y *= SC;
            qh[kd][0] = bf16pack(v0.x, v0.y); ql[kd][0] = bf16pack_lo(v0.x, v0.y, qh[kd][0]);
            qh[kd][1] = bf16pack(v1.x, v1.y); ql[kd][1] = bf16pack_lo(v1.x, v1.y, qh[kd][1]);
            qh[kd][2] = bf16pack(v2.x, v2.y); ql[kd][2] = bf16pack_lo(v2.x, v2.y, qh[kd][2]);
            qh[kd][3] = bf16pack(v3.x, v3.y); ql[kd][3] = bf16pack_lo(v3.x, v3.y, qh[kd][3]);
        }
    }

    auto loadTile = [&](int kt, int buf) {
        const __nv_bfloat16* gk = ks + ((size_t)bh * SEQ + kt * 64) * 128;
        const __nv_bfloat16* gv = vs + ((size_t)bh * SEQ + kt * 64) * 128;
        const uint32_t kb = smBase + buf * ATT_BUF_B;
        const uint32_t vb = kb + ATT_TILE_B;
        #pragma unroll
        for (int m = 0; m < 4; ++m) {
            const int id = tid + m * 256;
            const int c = id >> 4, j = id & 15;
            const uint32_t soff = c * 256 + ((j ^ (c & 7)) << 4);
            cp_async16(kb + soff, gk + (size_t)c * 128 + j * 8);
            cp_async16(vb + soff, gv + (size_t)c * 128 + j * 8);
        }
        cp_commit();
    };

    float m0 = -CUDART_INF_F, m1 = -CUDART_INF_F, l0 = 0.0f, l1 = 0.0f;
    float O[8][4] = {};

    loadTile(0, 0);

    for (int kt = 0; kt < ATT_NT; ++kt) {
        const int buf = kt & 1;
        __syncthreads();
        if (kt + 1 < ATT_NT) { loadTile(kt + 1, buf ^ 1); cp_wait1(); }
        else                 { cp_wait0(); }
        __syncthreads();

        const uint32_t Kb = smBase + buf * ATT_BUF_B;
        const uint32_t Vb = Kb + ATT_TILE_B;

        float S[8][4] = {};
        #pragma unroll
        for (int kd = 0; kd < 4; ++kd) {
            uint32_t kh[8][2];
            #pragma unroll
            for (int t = 0; t < 4; ++t) {
                const int row = 16 * t + (lane & 7) + 8 * ((lane >> 4) & 1);
                const int j = kd * 2 + ((lane >> 3) & 1);
                uint32_t r[4];
                ldsm_x4(r, Kb + row * 256 + ((j ^ (row & 7)) << 4));
                kh[2 * t][0] = r[0]; kh[2 * t][1] = r[1];
                kh[2 * t + 1][0] = r[2]; kh[2 * t + 1][1] = r[3];
            }
            #pragma unroll
            for (int nc = 0; nc < 8; ++nc) {
                mma_bf16(S[nc], qh[kd], kh[nc]);
                mma_bf16(S[nc], ql[kd], kh[nc]);
            }
            uint32_t kl[8][2];
            #pragma unroll
            for (int t = 0; t < 4; ++t) {
                const int row = 16 * t + (lane & 7) + 8 * ((lane >> 4) & 1);
                const int j = kd * 2 + ((lane >> 3) & 1) + 8;
                uint32_t r[4];
                ldsm_x4(r, Kb + row * 256 + ((j ^ (row & 7)) << 4));
                kl[2 * t][0] = r[0]; kl[2 * t][1] = r[1];
                kl[2 * t + 1][0] = r[2]; kl[2 * t + 1][1] = r[3];
            }
            #pragma unroll
            for (int nc = 0; nc < 8; ++nc)
                mma_bf16(S[nc], qh[kd], kl[nc]);
        }

        float mt0 = -CUDART_INF_F, mt1 = -CUDART_INF_F;
        #pragma unroll
        for (int nc = 0; nc < 8; ++nc) {
            mt0 = fmaxf(mt0, fmaxf(S[nc][0], S[nc][1]));
            mt1 = fmaxf(mt1, fmaxf(S[nc][2], S[nc][3]));
        }
        mt0 = fmaxf(mt0, __shfl_xor_sync(0xffffffffu, mt0, 1));
        mt0 = fmaxf(mt0, __shfl_xor_sync(0xffffffffu, mt0, 2));
        mt1 = fmaxf(mt1, __shfl_xor_sync(0xffffffffu, mt1, 1));
        mt1 = fmaxf(mt1, __shfl_xor_sync(0xffffffffu, mt1, 2));
        const float mn0 = fmaxf(m0, mt0);
        const float mn1 = fmaxf(m1, mt1);
        const float c0 = ex2f(m0 - mn0);
        const float c1 = ex2f(m1 - mn1);
        m0 = mn0; m1 = mn1;
        float rs0 = 0.0f, rs1 = 0.0f;
        #pragma unroll
        for (int nc = 0; nc < 8; ++nc) {
            S[nc][0] = ex2f(S[nc][0] - mn0); rs0 += S[nc][0];
            S[nc][1] = ex2f(S[nc][1] - mn0); rs0 += S[nc][1];
            S[nc][2] = ex2f(S[nc][2] - mn1); rs1 += S[nc][2];
            S[nc][3] = ex2f(S[nc][3] - mn1); rs1 += S[nc][3];
        }
        rs0 += __shfl_xor_sync(0xffffffffu, rs0, 1);
        rs0 += __shfl_xor_sync(0xffffffffu, rs0, 2);
        rs1 += __shfl_xor_sync(0xffffffffu, rs1, 1);
        rs1 += __shfl_xor_sync(0xffffffffu, rs1, 2);
        l0 = l0 * c0 + rs0;
        l1 = l1 * c1 + rs1;
        #pragma unroll
        for (int nd = 0; nd < 8; ++nd) {
            O[nd][0] *= c0; O[nd][1] *= c0; O[nd][2] *= c1; O[nd][3] *= c1;
        }

        #pragma unroll
        for (int kc = 0; kc < 4; ++kc) {
            uint32_t ph[4], pl[4];
            {
                const float* s0 = S[2 * kc];
                const float* s1 = S[2 * kc + 1];
                ph[0] = bf16pack(s0[0], s0[1]); pl[0] = bf16pack_lo(s0[0], s0[1], ph[0]);
                ph[1] = bf16pack(s0[2], s0[3]); pl[1] = bf16pack_lo(s0[2], s0[3], ph[1]);
                ph[2] = bf16pack(s1[0], s1[1]); pl[2] = bf16pack_lo(s1[0], s1[1], ph[2]);
                ph[3] = bf16pack(s1[2], s1[3]); pl[3] = bf16pack_lo(s1[2], s1[3], ph[3]);
            }
            uint32_t vh[8][2];
            #pragma unroll
            for (int t = 0; t < 4; ++t) {
                const int row = kc * 16 + (lane & 7) + 8 * ((lane >> 3) & 1);
                const int j = 2 * t + ((lane >> 4) & 1);
                uint32_t r[4];
                ldsm_x4_t(r, Vb + row * 256 + ((j ^ (row & 7)) << 4));
                vh[2 * t][0] = r[0]; vh[2 * t][1] = r[1];
                vh[2 * t + 1][0] = r[2]; vh[2 * t + 1][1] = r[3];
            }
            #pragma unroll
            for (int nd = 0; nd < 8; ++nd) {
                mma_bf16(O[nd], ph, vh[nd]);
                mma_bf16(O[nd], pl, vh[nd]);
            }
            uint32_t vl[8][2];
            #pragma unroll
            for (int t = 0; t < 4; ++t) {
                const int row = kc * 16 + (lane & 7) + 8 * ((lane >> 3) & 1);
                const int j = 2 * t + ((lane >> 4) & 1) + 8;
                uint32_t r[4];
                ldsm_x4_t(r, Vb + row * 256 + ((j ^ (row & 7)) << 4));
                vl[2 * t][0] = r[0]; vl[2 * t][1] = r[1];
                vl[2 * t + 1][0] = r[2]; vl[2 * t + 1][1] = r[3];
            }
            #pragma unroll
            for (int nd = 0; nd < 8; ++nd)
                mma_bf16(O[nd], ph, vl[nd]);
        }
    }

    const float inv0 = 1.0f / l0;
    const float inv1 = 1.0f / l1;
    const size_t row1 = (size_t)b * SEQ + qBase + wq * 16 + (lane >> 2);
    const int colBase = h * HDIM + (lane & 3) * 2;
    #pragma unroll
    for (int nd = 0; nd < 8; ++nd) {
        const int col = colBase + nd * 8;
        {
            const float x = O[nd][0] * inv0, y = O[nd][1] * inv0;
            __nv_bfloat16* p = outA + row1 * KEFF + col;
            const uint32_t hp = bf16pack(x, y);
            *(uint32_t*)p = hp;
            *(uint32_t*)(p + 1024) = bf16pack_lo(x, y, hp);
            *(uint32_t*)(p + 2048) = hp;
        }
        {
            const float x = O[nd][2] * inv1, y = O[nd][3] * inv1;
            __nv_bfloat16* p = outA + (row1 + 8) * KEFF + col;
            const uint32_t hp = bf16pack(x, y);
            *(uint32_t*)p = hp;
            *(uint32_t*)(p + 1024) = bf16pack_lo(x, y, hp);
            *(uint32_t*)(p + 2048) = hp;
        }
    }
}

// ---------------------------------------------------------------------------
// Launch
// ---------------------------------------------------------------------------
extern "C" void kernel_launch(void* const* d_in, const int* in_sizes, int n_in,
                              void* d_out, int out_size)
{
    (void)in_sizes; (void)n_in; (void)out_size;
    const float* x      = (const float*)d_in[0];
    const float* W_qkv  = (const float*)d_in[1];
    const float* b_qkv  = (const float*)d_in[2];
    const float* W_proj = (const float*)d_in[3];
    const float* b_proj = (const float*)d_in[4];
    const float* qn_w   = (const float*)d_in[5];
    const float* kn_w   = (const float*)d_in[6];
    float* out = (float*)d_out;

    float *qkv = nullptr;
    __nv_bfloat16 *A1 = nullptr, *B1 = nullptr, *B2 = nullptr, *A2 = nullptr;
    __nv_bfloat16 *ksp = nullptr, *vsp = nullptr;
    cudaGetSymbolAddress((void**)&qkv, g_qkv);
    cudaGetSymbolAddress((void**)&A1,  g_A1);
    cudaGetSymbolAddress((void**)&B1,  g_B1);
    cudaGetSymbolAddress((void**)&B2,  g_B2);
    cudaGetSymbolAddress((void**)&A2,  g_A2);
    cudaGetSymbolAddress((void**)&ksp, g_ks);
    cudaGetSymbolAddress((void**)&vsp, g_vs);

    cudaFuncSetAttribute(gemm_mma_kernel, cudaFuncAttributeMaxDynamicSharedMemorySize, G_SMEM);
    cudaFuncSetAttribute(attn_mma_kernel, cudaFuncAttributeMaxDynamicSharedMemorySize, ATT_SMEM);

    // 0) Conversions to bf16 split formats
    convX_kernel<<<(TOKENS * CDIM) / 256, 256>>>(x, A1);
    convW_kernel<<<dim3(QKVDIM / 32, CDIM / 32), 256>>>(W_qkv, B1, QKVDIM);
    convW_kernel<<<dim3(CDIM / 32, CDIM / 32), 256>>>(W_proj, B2, CDIM);

    // 1) QKV projection: [8192, 3072] = A1 @ B1^T + b_qkv
    gemm_mma_kernel<<<dim3(QKVDIM / BN, TOKENS / BM), 256, G_SMEM>>>(A1, B1, b_qkv, qkv, QKVDIM);

    // 2) RMSNorm on q and k heads (in place)
    rmsnorm_kernel<<<(TOKENS * 32) / 8, 256>>>(qkv, qn_w, kn_w);

    // 3) K/V bf16 hi/lo split precompute
    kvsplit_kernel<<<(BATCH * HEADS * SEQ * 32) / 256, 256>>>(qkv, ksp, vsp);

    // 4) Attention (tensor cores) -> g_A2 (bf16 split, proj-ready)
    attn_mma_kernel<<<dim3(SEQ / 128, BATCH * HEADS), 256, ATT_SMEM>>>(qkv, ksp, vsp, A2);

    // 5) Output projection: [8192, 1024] = A2 @ B2^T + b_proj
    gemm_mma_kernel<<<dim3(CDIM / BN, TOKENS / BM), 256, G_SMEM>>>(A2, B2, b_proj, out, CDIM);
}

// round 6
// speedup vs baseline: 3.5876x; 1.0061x over previous
#include <cuda_runtime.h>
#include <cuda_bf16.h>
#include <math_constants.h>
#include <cstdint>

// Problem constants
#define BATCH 4
#define SEQ   2048
#define CDIM  1024
#define HEADS 16
#define HDIM  64
#define TOKENS (BATCH * SEQ)         // 8192
#define QKVDIM (3 * CDIM)            // 3072
#define KEFF   3072                  // 3 * 1024 (bf16 split-K for both GEMMs)

// ---------------------------------------------------------------------------
// Scratch (device globals — no allocation allowed)
// ---------------------------------------------------------------------------
__device__ float g_qkv[(size_t)TOKENS * QKVDIM];                       // QKV output fp32
__device__ __align__(256) __nv_bfloat16 g_A1[(size_t)TOKENS * KEFF];  // x split       [m, hi|lo|hi]
__device__ __align__(256) __nv_bfloat16 g_B1[(size_t)QKVDIM * KEFF];  // W_qkv^T split [n, hi|hi|lo]
__device__ __align__(256) __nv_bfloat16 g_B2[(size_t)CDIM * KEFF];    // W_proj^T split
__device__ __align__(256) __nv_bfloat16 g_A2[(size_t)TOKENS * KEFF];  // attn out split [m, hi|lo|hi]
__device__ __align__(256) __nv_bfloat16 g_ks[(size_t)BATCH * HEADS * SEQ * 128]; // K split [hi64|lo64]
__device__ __align__(256) __nv_bfloat16 g_vs[(size_t)BATCH * HEADS * SEQ * 128]; // V split [hi64|lo64]

// ---------------------------------------------------------------------------
// PTX helpers (portable sm_80+ features only)
// ---------------------------------------------------------------------------
__device__ __forceinline__ uint32_t smem_u32(const void* p) {
    uint32_t a;
    asm("{ .reg .u64 t; cvta.to.shared.u64 t, %1; cvt.u32.u64 %0, t; }" : "=r"(a) : "l"(p));
    return a;
}
__device__ __forceinline__ void cp_async16(uint32_t dst, const void* src) {
    asm volatile("cp.async.cg.shared.global [%0], [%1], 16;" :: "r"(dst), "l"(src));
}
__device__ __forceinline__ void cp_commit() {
    asm volatile("cp.async.commit_group;" ::: "memory");
}
__device__ __forceinline__ void cp_wait0() {
    asm volatile("cp.async.wait_group 0;" ::: "memory");
}
__device__ __forceinline__ void cp_wait1() {
    asm volatile("cp.async.wait_group 1;" ::: "memory");
}
__device__ __forceinline__ void ldsm_x4(uint32_t* r, uint32_t addr) {
    asm volatile("ldmatrix.sync.aligned.m8n8.x4.shared.b16 {%0,%1,%2,%3}, [%4];"
                 : "=r"(r[0]), "=r"(r[1]), "=r"(r[2]), "=r"(r[3]) : "r"(addr));
}
__device__ __forceinline__ void ldsm_x4_t(uint32_t* r, uint32_t addr) {
    asm volatile("ldmatrix.sync.aligned.m8n8.x4.trans.shared.b16 {%0,%1,%2,%3}, [%4];"
                 : "=r"(r[0]), "=r"(r[1]), "=r"(r[2]), "=r"(r[3]) : "r"(addr));
}
__device__ __forceinline__ void mma_bf16(float* c, const uint32_t* a, const uint32_t* b) {
    asm volatile(
        "mma.sync.aligned.m16n8k16.row.col.f32.bf16.bf16.f32 "
        "{%0,%1,%2,%3}, {%4,%5,%6,%7}, {%8,%9}, {%0,%1,%2,%3};"
        : "+f"(c[0]), "+f"(c[1]), "+f"(c[2]), "+f"(c[3])
        : "r"(a[0]), "r"(a[1]), "r"(a[2]), "r"(a[3]), "r"(b[0]), "r"(b[1]));
}
__device__ __forceinline__ float ex2f(float x) {
    float y; asm("ex2.approx.ftz.f32 %0, %1;" : "=f"(y) : "f"(x)); return y;
}
__device__ __forceinline__ uint32_t bf16pack(float a, float b) {
    __nv_bfloat162 h;
    h.x = __float2bfloat16(a);
    h.y = __float2bfloat16(b);
    return *(uint32_t*)&h;
}
__device__ __forceinline__ uint32_t bf16pack_lo(float a, float b, uint32_t hipack) {
    __nv_bfloat162 h = *(__nv_bfloat162*)&hipack;
    return bf16pack(a - __bfloat162float(h.x), b - __bfloat162float(h.y));
}

// ---------------------------------------------------------------------------
// Conversion kernels (fp32 -> bf16 hi/lo split)
// ---------------------------------------------------------------------------
__global__ __launch_bounds__(256) void convX_kernel(const float* __restrict__ x,
                                                    __nv_bfloat16* __restrict__ A)
{
    const int idx = blockIdx.x * 256 + threadIdx.x;      // over TOKENS*CDIM
    const int m = idx >> 10;
    const int k = idx & 1023;
    const float v = x[idx];
    const __nv_bfloat16 hi = __float2bfloat16(v);
    const __nv_bfloat16 lo = __float2bfloat16(v - __bfloat162float(hi));
    __nv_bfloat16* row = A + (size_t)m * KEFF;
    row[k]        = hi;
    row[1024 + k] = lo;
    row[2048 + k] = hi;
}

// Transpose + split: W [K=1024, N] fp32  ->  B [N, 3K] bf16, layout [hi|hi|lo]
__global__ __launch_bounds__(256) void convW_kernel(const float* __restrict__ W,
                                                    __nv_bfloat16* __restrict__ B, int N)
{
    __shared__ float t[32][33];
    const int n0 = blockIdx.x * 32;
    const int k0 = blockIdx.y * 32;
    const int tx = threadIdx.x & 31;
    const int ty = threadIdx.x >> 5;          // 0..7
    #pragma unroll
    for (int i = 0; i < 4; ++i)
        t[ty + 8 * i][tx] = W[(size_t)(k0 + ty + 8 * i) * N + n0 + tx];
    __syncthreads();
    #pragma unroll
    for (int i = 0; i < 4; ++i) {
        const int n = n0 + ty + 8 * i;
        const int k = k0 + tx;
        const float v = t[tx][ty + 8 * i];
        const __nv_bfloat16 hi = __float2bfloat16(v);
        const __nv_bfloat16 lo = __float2bfloat16(v - __bfloat162float(hi));
        __nv_bfloat16* row = B + (size_t)n * KEFF;
        row[k]        = hi;
        row[1024 + k] = hi;
        row[2048 + k] = lo;
    }
}

// ---------------------------------------------------------------------------
// mma.sync bf16 GEMM:  C[M,N] = A' @ B'^T + bias
// CTA 128x128, 8 warps (2x4), warp tile 64x32. BK=64 (128B rows, XOR swizzle),
// 3-stage cp.async pipeline, ONE barrier per chunk.
// ---------------------------------------------------------------------------
#define BM 128
#define BN 128
#define BK 64
#define G_STAGES 3
#define G_STAGE_A (BM * BK * 2)          // 16384
#define G_STAGE_BYTES (2 * G_STAGE_A)    // 32768 (A + B)
#define G_SMEM (G_STAGES * G_STAGE_BYTES)// 98304
#define NCHUNKG (KEFF / BK)              // 48

__global__ __launch_bounds__(256) void gemm_mma_kernel(
    const __nv_bfloat16* __restrict__ A, const __nv_bfloat16* __restrict__ Bm,
    const float* __restrict__ bias, float* __restrict__ C, int N)
{
    extern __shared__ __align__(256) char gsm[];
    const uint32_t base = smem_u32(gsm);

    const int tid  = threadIdx.x;
    const int wid  = tid >> 5;
    const int lane = tid & 31;
    const int wm   = wid >> 2;           // 0..1
    const int wn   = wid & 3;            // 0..3
    const int rowBase = blockIdx.y * BM;
    const int colBase = blockIdx.x * BN;

    float acc[4][4][4] = {};

    const int lrow = tid >> 3;           // 0..31 (x4 via +32)
    const int lch  = tid & 7;

    auto loadStage = [&](int c, int s) {
        const __nv_bfloat16* Ag = A + (size_t)rowBase * KEFF + c * BK;
        const __nv_bfloat16* Bg = Bm + (size_t)colBase * KEFF + c * BK;
        const uint32_t as = base + s * G_STAGE_BYTES;
        const uint32_t bs = as + G_STAGE_A;
        #pragma unroll
        for (int m = 0; m < 4; ++m) {
            const int row = lrow + m * 32;
            const uint32_t soff = row * 128 + ((lch ^ (row & 7)) << 4);
            cp_async16(as + soff, Ag + (size_t)row * KEFF + lch * 8);
            cp_async16(bs + soff, Bg + (size_t)row * KEFF + lch * 8);
        }
        cp_commit();
    };

    loadStage(0, 0);
    loadStage(1, 1);

    int s = 0;
    for (int c = 0; c < NCHUNKG; ++c) {
        if (c + 2 < NCHUNKG) cp_wait1(); else cp_wait0();
        __syncthreads();                     // single barrier per chunk
        if (c + 2 < NCHUNKG) loadStage(c + 2, (s + 2) % G_STAGES);

        const uint32_t as = base + s * G_STAGE_BYTES;
        const uint32_t bs = as + G_STAGE_A;

        #pragma unroll
        for (int ks = 0; ks < 4; ++ks) {
            uint32_t afr[4][4];
            #pragma unroll
            for (int mt = 0; mt < 4; ++mt) {
                const int row = wm * 64 + mt * 16 + (lane & 15);
                const int ch  = ks * 2 + (lane >> 4);
                ldsm_x4(afr[mt], as + row * 128 + ((ch ^ (row & 7)) << 4));
            }
            uint32_t bfr[4][2];
            #pragma unroll
            for (int ntp = 0; ntp < 2; ++ntp) {
                const int row = wn * 32 + ntp * 16 + (lane & 7) + ((lane >> 4) << 3);
                const int ch  = ks * 2 + ((lane >> 3) & 1);
                uint32_t r[4];
                ldsm_x4(r, bs + row * 128 + ((ch ^ (row & 7)) << 4));
                bfr[2 * ntp][0]     = r[0]; bfr[2 * ntp][1]     = r[1];
                bfr[2 * ntp + 1][0] = r[2]; bfr[2 * ntp + 1][1] = r[3];
            }
            #pragma unroll
            for (int mt = 0; mt < 4; ++mt)
                #pragma unroll
                for (int nt = 0; nt < 4; ++nt)
                    mma_bf16(acc[mt][nt], afr[mt], bfr[nt]);
        }
        s = (s + 1) % G_STAGES;
    }

    // Epilogue
    const int erow = lane >> 2;
    const int ecol = (lane & 3) * 2;
    #pragma unroll
    for (int mt = 0; mt < 4; ++mt) {
        const int rA = rowBase + wm * 64 + mt * 16 + erow;
        #pragma unroll
        for (int nt = 0; nt < 4; ++nt) {
            const int col = colBase + wn * 32 + nt * 8 + ecol;
            const float b0 = bias[col], b1 = bias[col + 1];
            *(float2*)&C[(size_t)rA * N + col] =
                make_float2(acc[mt][nt][0] + b0, acc[mt][nt][1] + b1);
            *(float2*)&C[(size_t)(rA + 8) * N + col] =
                make_float2(acc[mt][nt][2] + b0, acc[mt][nt][3] + b1);
        }
    }
}

// ---------------------------------------------------------------------------
// Fused RMSNorm + K/V split. One warp per (token, slot).
// slot 0..15 : q head h -> rmsnorm in place (fp32, for attention Q load)
// slot 16..31: k head h -> rmsnorm + bf16 hi/lo split to g_ks,
//              plus v head h -> bf16 hi/lo split to g_vs
// ---------------------------------------------------------------------------
__global__ __launch_bounds__(256) void rmskv_kernel(
    float* __restrict__ qkv,
    const float* __restrict__ qn_w, const float* __restrict__ kn_w,
    __nv_bfloat16* __restrict__ ks, __nv_bfloat16* __restrict__ vs)
{
    const int gwarp = (blockIdx.x * blockDim.x + threadIdx.x) >> 5;
    const int lane  = threadIdx.x & 31;
    const int token = gwarp >> 5;
    const int slot  = gwarp & 31;
    if (token >= TOKENS) return;

    const int h = slot & 15;

    if (slot < 16) {
        float* row = qkv + (size_t)token * QKVDIM + h * HDIM;
        float x0 = row[lane];
        float x1 = row[lane + 32];
        float ss = x0 * x0 + x1 * x1;
        #pragma unroll
        for (int off = 16; off; off >>= 1) ss += __shfl_xor_sync(0xffffffffu, ss, off);
        const float inv = rsqrtf(ss * (1.0f / 64.0f) + 1e-6f);
        row[lane]      = x0 * inv * qn_w[lane];
        row[lane + 32] = x1 * inv * qn_w[lane + 32];
    } else {
        const int b = token >> 11;
        const int n = token & 2047;
        const size_t dstRow = ((size_t)(b * HEADS + h) * SEQ + n) * 128;

        {   // K: rmsnorm + split
            const float* row = qkv + (size_t)token * QKVDIM + CDIM + h * HDIM;
            float x0 = row[lane];
            float x1 = row[lane + 32];
            float ss = x0 * x0 + x1 * x1;
            #pragma unroll
            for (int off = 16; off; off >>= 1) ss += __shfl_xor_sync(0xffffffffu, ss, off);
            const float inv = rsqrtf(ss * (1.0f / 64.0f) + 1e-6f);
            const float k0 = x0 * inv * kn_w[lane];
            const float k1 = x1 * inv * kn_w[lane + 32];
            const __nv_bfloat16 h0 = __float2bfloat16(k0);
            const __nv_bfloat16 h1 = __float2bfloat16(k1);
            ks[dstRow + lane]           = h0;
            ks[dstRow + lane + 32]      = h1;
            ks[dstRow + 64 + lane]      = __float2bfloat16(k0 - __bfloat162float(h0));
            ks[dstRow + 64 + lane + 32] = __float2bfloat16(k1 - __bfloat162float(h1));
        }
        {   // V: split only
            const float* row = qkv + (size_t)token * QKVDIM + 2 * CDIM + h * HDIM;
            const float v0 = row[lane];
            const float v1 = row[lane + 32];
            const __nv_bfloat16 h0 = __float2bfloat16(v0);
            const __nv_bfloat16 h1 = __float2bfloat16(v1);
            vs[dstRow + lane]           = h0;
            vs[dstRow + lane + 32]      = h1;
            vs[dstRow + 64 + lane]      = __float2bfloat16(v0 - __bfloat162float(h0));
            vs[dstRow + 64 + lane + 32] = __float2bfloat16(v1 - __bfloat162float(h1));
        }
    }
}

// ---------------------------------------------------------------------------
// FlashAttention-2 style mma.sync attention. Bc=128, 3-stage pipeline,
// ONE barrier per key tile. CTA = 128 q-rows x (b,h); 8 warps x 16 rows.
// ---------------------------------------------------------------------------
#define ATT_NT (SEQ / 128)            // 16 key tiles
#define ATT_TILE_B 32768              // one matrix tile: 128 rows * 256B
#define ATT_BUF_B  65536              // K + V per stage
#define ATT_STAGES 3
#define ATT_SMEM   (ATT_STAGES * ATT_BUF_B)   // 196608

__global__ __launch_bounds__(256) void attn_mma_kernel(
    const float* __restrict__ qkv,
    const __nv_bfloat16* __restrict__ ks, const __nv_bfloat16* __restrict__ vs,
    __nv_bfloat16* __restrict__ outA)
{
    extern __shared__ __align__(256) char sm[];
    const uint32_t smBase = smem_u32(sm);

    const int tid  = threadIdx.x;
    const int wq   = tid >> 5;
    const int lane = tid & 31;

    const int bh = blockIdx.y;
    const int b  = bh >> 4;
    const int h  = bh & 15;
    const int qBase = blockIdx.x * 128;

    // ---- Q fragments (hi/lo), scale folded: 0.125 * log2(e) ----
    const float SC = 0.125f * 1.44269504088896340736f;
    uint32_t qh[4][4], ql[4][4];
    {
        const float* qg = qkv + ((size_t)(b * SEQ + qBase + wq * 16)) * QKVDIM + h * HDIM;
        const int rr = lane >> 2;
        const int cb = (lane & 3) * 2;
        #pragma unroll
        for (int kd = 0; kd < 4; ++kd) {
            const int d0 = kd * 16;
            float2 v0 = *(const float2*)&qg[(size_t)rr * QKVDIM + d0 + cb];
            float2 v1 = *(const float2*)&qg[(size_t)(rr + 8) * QKVDIM + d0 + cb];
            float2 v2 = *(const float2*)&qg[(size_t)rr * QKVDIM + d0 + cb + 8];
            float2 v3 = *(const float2*)&qg[(size_t)(rr + 8) * QKVDIM + d0 + cb + 8];
            v0.x *= SC; v0.y *= SC; v1.x *= SC; v1.y *= SC;
            v2.x *= SC; v2.y *= SC; v3.x *= SC; v3.y *= SC;
            qh[kd][0] = bf16pack(v0.x, v0.y); ql[kd][0] = bf16pack_lo(v0.x, v0.y, qh[kd][0]);
            qh[kd][1] = bf16pack(v1.x, v1.y); ql[kd][1] = bf16pack_lo(v1.x, v1.y, qh[kd][1]);
            qh[kd][2] = bf16pack(v2.x, v2.y); ql[kd][2] = bf16pack_lo(v2.x, v2.y, qh[kd][2]);
            qh[kd][3] = bf16pack(v3.x, v3.y); ql[kd][3] = bf16pack_lo(v3.x, v3.y, qh[kd][3]);
        }
    }

    // ---- cp.async tile loader: 128 keys, K + V (256B rows, XOR swizzle) ----
    auto loadTile = [&](int kt, int st) {
        const __nv_bfloat16* gk = ks + ((size_t)bh * SEQ + kt * 128) * 128;
        const __nv_bfloat16* gv = vs + ((size_t)bh * SEQ + kt * 128) * 128;
        const uint32_t kb = smBase + st * ATT_BUF_B;
        const uint32_t vb = kb + ATT_TILE_B;
        #pragma unroll
        for (int m = 0; m < 8; ++m) {
            const int id = tid + m * 256;           // 0..2047
            const int c = id >> 4, j = id & 15;
            const uint32_t soff = c * 256 + ((j ^ (c & 7)) << 4);
            cp_async16(kb + soff, gk + (size_t)c * 128 + j * 8);
            cp_async16(vb + soff, gv + (size_t)c * 128 + j * 8);
        }
        cp_commit();
    };

    float m0 = -CUDART_INF_F, m1 = -CUDART_INF_F, l0 = 0.0f, l1 = 0.0f;
    float O[8][4] = {};

    loadTile(0, 0);
    loadTile(1, 1);

    for (int kt = 0; kt < ATT_NT; ++kt) {
        const int st = kt % ATT_STAGES;
        if (kt + 2 < ATT_NT) cp_wait1(); else cp_wait0();
        __syncthreads();                            // single barrier per tile
        if (kt + 2 < ATT_NT) loadTile(kt + 2, (kt + 2) % ATT_STAGES);

        const uint32_t Kb = smBase + st * ATT_BUF_B;
        const uint32_t Vb = Kb + ATT_TILE_B;

        // ---- S = Q' K'^T (3-term split), 128 keys ----
        float S[16][4] = {};
        #pragma unroll
        for (int kd = 0; kd < 4; ++kd) {
            #pragma unroll
            for (int t = 0; t < 8; ++t) {           // hi region
                const int row = 16 * t + (lane & 7) + 8 * ((lane >> 4) & 1);
                const int j = kd * 2 + ((lane >> 3) & 1);
                uint32_t r[4];
                ldsm_x4(r, Kb + row * 256 + ((j ^ (row & 7)) << 4));
                mma_bf16(S[2 * t],     qh[kd], r);
                mma_bf16(S[2 * t],     ql[kd], r);
                mma_bf16(S[2 * t + 1], qh[kd], r + 2);
                mma_bf16(S[2 * t + 1], ql[kd], r + 2);
            }
            #pragma unroll
            for (int t = 0; t < 8; ++t) {           // lo region
                const int row = 16 * t + (lane & 7) + 8 * ((lane >> 4) & 1);
                const int j = kd * 2 + ((lane >> 3) & 1) + 8;
                uint32_t r[4];
                ldsm_x4(r, Kb + row * 256 + ((j ^ (row & 7)) << 4));
                mma_bf16(S[2 * t],     qh[kd], r);
                mma_bf16(S[2 * t + 1], qh[kd], r + 2);
            }
        }

        // ---- Online softmax (base 2) ----
        float mt0 = -CUDART_INF_F, mt1 = -CUDART_INF_F;
        #pragma unroll
        for (int nc = 0; nc < 16; ++nc) {
            mt0 = fmaxf(mt0, fmaxf(S[nc][0], S[nc][1]));
            mt1 = fmaxf(mt1, fmaxf(S[nc][2], S[nc][3]));
        }
        mt0 = fmaxf(mt0, __shfl_xor_sync(0xffffffffu, mt0, 1));
        mt0 = fmaxf(mt0, __shfl_xor_sync(0xffffffffu, mt0, 2));
        mt1 = fmaxf(mt1, __shfl_xor_sync(0xffffffffu, mt1, 1));
        mt1 = fmaxf(mt1, __shfl_xor_sync(0xffffffffu, mt1, 2));
        const float mn0 = fmaxf(m0, mt0);
        const float mn1 = fmaxf(m1, mt1);
        const float c0 = ex2f(m0 - mn0);
        const float c1 = ex2f(m1 - mn1);
        m0 = mn0; m1 = mn1;
        float rs0 = 0.0f, rs1 = 0.0f;
        #pragma unroll
        for (int nc = 0; nc < 16; ++nc) {
            S[nc][0] = ex2f(S[nc][0] - mn0); rs0 += S[nc][0];
            S[nc][1] = ex2f(S[nc][1] - mn0); rs0 += S[nc][1];
            S[nc][2] = ex2f(S[nc][2] - mn1); rs1 += S[nc][2];
            S[nc][3] = ex2f(S[nc][3] - mn1); rs1 += S[nc][3];
        }
        rs0 += __shfl_xor_sync(0xffffffffu, rs0, 1);
        rs0 += __shfl_xor_sync(0xffffffffu, rs0, 2);
        rs1 += __shfl_xor_sync(0xffffffffu, rs1, 1);
        rs1 += __shfl_xor_sync(0xffffffffu, rs1, 2);
        l0 = l0 * c0 + rs0;
        l1 = l1 * c1 + rs1;
        #pragma unroll
        for (int nd = 0; nd < 8; ++nd) {
            O[nd][0] *= c0; O[nd][1] *= c0; O[nd][2] *= c1; O[nd][3] *= c1;
        }

        // ---- O += P V (3-term split), 8 k16 chunks ----
        #pragma unroll
        for (int kc = 0; kc < 8; ++kc) {
            uint32_t ph[4], pl[4];
            {
                const float* s0 = S[2 * kc];
                const float* s1 = S[2 * kc + 1];
                ph[0] = bf16pack(s0[0], s0[1]); pl[0] = bf16pack_lo(s0[0], s0[1], ph[0]);
                ph[1] = bf16pack(s0[2], s0[3]); pl[1] = bf16pack_lo(s0[2], s0[3], ph[1]);
                ph[2] = bf16pack(s1[0], s1[1]); pl[2] = bf16pack_lo(s1[0], s1[1], ph[2]);
                ph[3] = bf16pack(s1[2], s1[3]); pl[3] = bf16pack_lo(s1[2], s1[3], ph[3]);
            }
            #pragma unroll
            for (int t = 0; t < 4; ++t) {           // hi region
                const int row = kc * 16 + (lane & 7) + 8 * ((lane >> 3) & 1);
                const int j = 2 * t + ((lane >> 4) & 1);
                uint32_t r[4];
                ldsm_x4_t(r, Vb + row * 256 + ((j ^ (row & 7)) << 4));
                mma_bf16(O[2 * t],     ph, r);
                mma_bf16(O[2 * t],     pl, r);
                mma_bf16(O[2 * t + 1], ph, r + 2);
                mma_bf16(O[2 * t + 1], pl, r + 2);
            }
            #pragma unroll
            for (int t = 0; t < 4; ++t) {           // lo region
                const int row = kc * 16 + (lane & 7) + 8 * ((lane >> 3) & 1);
                const int j = 2 * t + ((lane >> 4) & 1) + 8;
                uint32_t r[4];
                ldsm_x4_t(r, Vb + row * 256 + ((j ^ (row & 7)) << 4));
                mma_bf16(O[2 * t],     ph, r);
                mma_bf16(O[2 * t + 1], ph, r + 2);
            }
        }
    }

    // ---- Epilogue: normalize, write hi/lo/hi split rows to outA ----
    const float inv0 = 1.0f / l0;
    const float inv1 = 1.0f / l1;
    const size_t row1 = (size_t)b * SEQ + qBase + wq * 16 + (lane >> 2);
    const int colBase = h * HDIM + (lane & 3) * 2;
    #pragma unroll
    for (int nd = 0; nd < 8; ++nd) {
        const int col = colBase + nd * 8;
        {
            const float x = O[nd][0] * inv0, y = O[nd][1] * inv0;
            __nv_bfloat16* p = outA + row1 * KEFF + col;
            const uint32_t hp = bf16pack(x, y);
            *(uint32_t*)p = hp;
            *(uint32_t*)(p + 1024) = bf16pack_lo(x, y, hp);
            *(uint32_t*)(p + 2048) = hp;
        }
        {
            const float x = O[nd][2] * inv1, y = O[nd][3] * inv1;
            __nv_bfloat16* p = outA + (row1 + 8) * KEFF + col;
            const uint32_t hp = bf16pack(x, y);
            *(uint32_t*)p = hp;
            *(uint32_t*)(p + 1024) = bf16pack_lo(x, y, hp);
            *(uint32_t*)(p + 2048) = hp;
        }
    }
}

// ---------------------------------------------------------------------------
// Launch
// ---------------------------------------------------------------------------
extern "C" void kernel_launch(void* const* d_in, const int* in_sizes, int n_in,
                              void* d_out, int out_size)
{
    (void)in_sizes; (void)n_in; (void)out_size;
    const float* x      = (const float*)d_in[0];
    const float* W_qkv  = (const float*)d_in[1];
    const float* b_qkv  = (const float*)d_in[2];
    const float* W_proj = (const float*)d_in[3];
    const float* b_proj = (const float*)d_in[4];
    const float* qn_w   = (const float*)d_in[5];
    const float* kn_w   = (const float*)d_in[6];
    float* out = (float*)d_out;

    float *qkv = nullptr;
    __nv_bfloat16 *A1 = nullptr, *B1 = nullptr, *B2 = nullptr, *A2 = nullptr;
    __nv_bfloat16 *ksp = nullptr, *vsp = nullptr;
    cudaGetSymbolAddress((void**)&qkv, g_qkv);
    cudaGetSymbolAddress((void**)&A1,  g_A1);
    cudaGetSymbolAddress((void**)&B1,  g_B1);
    cudaGetSymbolAddress((void**)&B2,  g_B2);
    cudaGetSymbolAddress((void**)&A2,  g_A2);
    cudaGetSymbolAddress((void**)&ksp, g_ks);
    cudaGetSymbolAddress((void**)&vsp, g_vs);

    cudaFuncSetAttribute(gemm_mma_kernel, cudaFuncAttributeMaxDynamicSharedMemorySize, G_SMEM);
    cudaFuncSetAttribute(attn_mma_kernel, cudaFuncAttributeMaxDynamicSharedMemorySize, ATT_SMEM);

    // 0) Conversions to bf16 split formats
    convX_kernel<<<(TOKENS * CDIM) / 256, 256>>>(x, A1);
    convW_kernel<<<dim3(QKVDIM / 32, CDIM / 32), 256>>>(W_qkv, B1, QKVDIM);
    convW_kernel<<<dim3(CDIM / 32, CDIM / 32), 256>>>(W_proj, B2, CDIM);

    // 1) QKV projection: [8192, 3072] = A1 @ B1^T + b_qkv
    gemm_mma_kernel<<<dim3(QKVDIM / BN, TOKENS / BM), 256, G_SMEM>>>(A1, B1, b_qkv, qkv, QKVDIM);

    // 2) Fused RMSNorm (q in place, k) + K/V bf16 split
    rmskv_kernel<<<(TOKENS * 32) / 8, 256>>>(qkv, qn_w, kn_w, ksp, vsp);

    // 3) Attention (tensor cores) -> g_A2 (bf16 split, proj-ready)
    attn_mma_kernel<<<dim3(SEQ / 128, BATCH * HEADS), 256, ATT_SMEM>>>(qkv, ksp, vsp, A2);

    // 4) Output projection: [8192, 1024] = A2 @ B2^T + b_proj
    gemm_mma_kernel<<<dim3(CDIM / BN, TOKENS / BM), 256, G_SMEM>>>(A2, B2, b_proj, out, CDIM);
}

// round 7
// speedup vs baseline: 5.0855x; 1.4175x over previous
#include <cuda_runtime.h>
#include <cuda_fp16.h>
#include <math_constants.h>
#include <cstdint>

// Problem constants
#define BATCH 4
#define SEQ   2048
#define CDIM  1024
#define HEADS 16
#define HDIM  64
#define TOKENS (BATCH * SEQ)         // 8192
#define QKVDIM (3 * CDIM)            // 3072
#define KA    2048                   // A-side split K (hi|lo)
#define KB    1024                   // B-side K (hi only)

// ---------------------------------------------------------------------------
// Scratch (device globals — no allocation allowed)
// ---------------------------------------------------------------------------
__device__ float g_qkv[(size_t)TOKENS * QKVDIM];                    // QKV output fp32
__device__ __align__(256) __half g_A1[(size_t)TOKENS * KA];        // x split      [m, hi|lo]
__device__ __align__(256) __half g_B1[(size_t)QKVDIM * KB];        // W_qkv^T hi   [n, k]
__device__ __align__(256) __half g_B2[(size_t)CDIM * KB];          // W_proj^T hi
__device__ __align__(256) __half g_A2[(size_t)TOKENS * KA];        // attn out split [m, hi|lo]
__device__ __align__(256) __half g_ks[(size_t)BATCH * HEADS * SEQ * 64]; // K hi [bh, n, d]
__device__ __align__(256) __half g_vs[(size_t)BATCH * HEADS * SEQ * 64]; // V hi

// ---------------------------------------------------------------------------
// PTX helpers (portable sm_80+ features only)
// ---------------------------------------------------------------------------
__device__ __forceinline__ uint32_t smem_u32(const void* p) {
    uint32_t a;
    asm("{ .reg .u64 t; cvta.to.shared.u64 t, %1; cvt.u32.u64 %0, t; }" : "=r"(a) : "l"(p));
    return a;
}
__device__ __forceinline__ void cp_async16(uint32_t dst, const void* src) {
    asm volatile("cp.async.cg.shared.global [%0], [%1], 16;" :: "r"(dst), "l"(src));
}
__device__ __forceinline__ void cp_commit() {
    asm volatile("cp.async.commit_group;" ::: "memory");
}
__device__ __forceinline__ void cp_wait0() {
    asm volatile("cp.async.wait_group 0;" ::: "memory");
}
__device__ __forceinline__ void cp_wait1() {
    asm volatile("cp.async.wait_group 1;" ::: "memory");
}
__device__ __forceinline__ void ldsm_x4(uint32_t* r, uint32_t addr) {
    asm volatile("ldmatrix.sync.aligned.m8n8.x4.shared.b16 {%0,%1,%2,%3}, [%4];"
                 : "=r"(r[0]), "=r"(r[1]), "=r"(r[2]), "=r"(r[3]) : "r"(addr));
}
__device__ __forceinline__ void ldsm_x4_t(uint32_t* r, uint32_t addr) {
    asm volatile("ldmatrix.sync.aligned.m8n8.x4.trans.shared.b16 {%0,%1,%2,%3}, [%4];"
                 : "=r"(r[0]), "=r"(r[1]), "=r"(r[2]), "=r"(r[3]) : "r"(addr));
}
__device__ __forceinline__ void mma_fp16(float* c, const uint32_t* a, const uint32_t* b) {
    asm volatile(
        "mma.sync.aligned.m16n8k16.row.col.f32.f16.f16.f32 "
        "{%0,%1,%2,%3}, {%4,%5,%6,%7}, {%8,%9}, {%0,%1,%2,%3};"
        : "+f"(c[0]), "+f"(c[1]), "+f"(c[2]), "+f"(c[3])
        : "r"(a[0]), "r"(a[1]), "r"(a[2]), "r"(a[3]), "r"(b[0]), "r"(b[1]));
}
__device__ __forceinline__ float ex2f(float x) {
    float y; asm("ex2.approx.ftz.f32 %0, %1;" : "=f"(y) : "f"(x)); return y;
}
__device__ __forceinline__ uint32_t h2pack(float a, float b) {
    __half2 h;
    h.x = __float2half_rn(a);
    h.y = __float2half_rn(b);
    return *(uint32_t*)&h;
}
__device__ __forceinline__ uint32_t h2pack_lo(float a, float b, uint32_t hipack) {
    __half2 h = *(__half2*)&hipack;
    return h2pack(a - __half2float(h.x), b - __half2float(h.y));
}

// ---------------------------------------------------------------------------
// Conversion kernels (fp32 -> fp16 hi/lo split)
// ---------------------------------------------------------------------------
__global__ __launch_bounds__(256) void convX_kernel(const float* __restrict__ x,
                                                    __half* __restrict__ A)
{
    const int idx = blockIdx.x * 256 + threadIdx.x;      // over TOKENS*CDIM
    const int m = idx >> 10;
    const int k = idx & 1023;
    const float v = x[idx];
    const __half hi = __float2half_rn(v);
    __half* row = A + (size_t)m * KA;
    row[k]        = hi;
    row[1024 + k] = __float2half_rn(v - __half2float(hi));
}

// Transpose: W [K=1024, N] fp32 -> B [N, 1024] fp16 (hi only)
__global__ __launch_bounds__(256) void convW_kernel(const float* __restrict__ W,
                                                    __half* __restrict__ B, int N)
{
    __shared__ float t[32][33];
    const int n0 = blockIdx.x * 32;
    const int k0 = blockIdx.y * 32;
    const int tx = threadIdx.x & 31;
    const int ty = threadIdx.x >> 5;          // 0..7
    #pragma unroll
    for (int i = 0; i < 4; ++i)
        t[ty + 8 * i][tx] = W[(size_t)(k0 + ty + 8 * i) * N + n0 + tx];
    __syncthreads();
    #pragma unroll
    for (int i = 0; i < 4; ++i) {
        const int n = n0 + ty + 8 * i;
        const int k = k0 + tx;
        B[(size_t)n * KB + k] = __float2half_rn(t[tx][ty + 8 * i]);
    }
}

// ---------------------------------------------------------------------------
// mma.sync fp16 GEMM:  C[M,N] = (A_hi + A_lo) @ B_hi^T + bias
// A [M, 2048] ([hi|lo]), B [N, 1024] (hi). Chunk c covers A cols c*64;
// matching B chunk is (c & 15). CTA 128x128, 8 warps, BK=64, 3-stage pipeline.
// ---------------------------------------------------------------------------
#define BM 128
#define BN 128
#define BK 64
#define G_STAGES 3
#define G_STAGE_A (BM * BK * 2)          // 16384
#define G_STAGE_BYTES (2 * G_STAGE_A)    // 32768 (A + B)
#define G_SMEM (G_STAGES * G_STAGE_BYTES)// 98304
#define NCHUNKG (KA / BK)                // 32

__global__ __launch_bounds__(256) void gemm_mma_kernel(
    const __half* __restrict__ A, const __half* __restrict__ Bm,
    const float* __restrict__ bias, float* __restrict__ C, int N)
{
    extern __shared__ __align__(256) char gsm[];
    const uint32_t base = smem_u32(gsm);

    const int tid  = threadIdx.x;
    const int wid  = tid >> 5;
    const int lane = tid & 31;
    const int wm   = wid >> 2;           // 0..1
    const int wn   = wid & 3;            // 0..3
    const int rowBase = blockIdx.y * BM;
    const int colBase = blockIdx.x * BN;

    float acc[4][4][4] = {};

    const int lrow = tid >> 3;           // 0..31 (x4 via +32)
    const int lch  = tid & 7;

    auto loadStage = [&](int c, int s) {
        const int bc = c & 15;
        const __half* Ag = A + (size_t)rowBase * KA + c * BK;
        const __half* Bg = Bm + (size_t)colBase * KB + bc * BK;
        const uint32_t as = base + s * G_STAGE_BYTES;
        const uint32_t bs = as + G_STAGE_A;
        #pragma unroll
        for (int m = 0; m < 4; ++m) {
            const int row = lrow + m * 32;
            const uint32_t soff = row * 128 + ((lch ^ (row & 7)) << 4);
            cp_async16(as + soff, Ag + (size_t)row * KA + lch * 8);
            cp_async16(bs + soff, Bg + (size_t)row * KB + lch * 8);
        }
        cp_commit();
    };

    loadStage(0, 0);
    loadStage(1, 1);

    int s = 0;
    for (int c = 0; c < NCHUNKG; ++c) {
        if (c + 2 < NCHUNKG) cp_wait1(); else cp_wait0();
        __syncthreads();
        if (c + 2 < NCHUNKG) loadStage(c + 2, (s + 2) % G_STAGES);

        const uint32_t as = base + s * G_STAGE_BYTES;
        const uint32_t bs = as + G_STAGE_A;

        #pragma unroll
        for (int ks = 0; ks < 4; ++ks) {
            uint32_t afr[4][4];
            #pragma unroll
            for (int mt = 0; mt < 4; ++mt) {
                const int row = wm * 64 + mt * 16 + (lane & 15);
                const int ch  = ks * 2 + (lane >> 4);
                ldsm_x4(afr[mt], as + row * 128 + ((ch ^ (row & 7)) << 4));
            }
            uint32_t bfr[4][2];
            #pragma unroll
            for (int ntp = 0; ntp < 2; ++ntp) {
                const int row = wn * 32 + ntp * 16 + (lane & 7) + ((lane >> 4) << 3);
                const int ch  = ks * 2 + ((lane >> 3) & 1);
                uint32_t r[4];
                ldsm_x4(r, bs + row * 128 + ((ch ^ (row & 7)) << 4));
                bfr[2 * ntp][0]     = r[0]; bfr[2 * ntp][1]     = r[1];
                bfr[2 * ntp + 1][0] = r[2]; bfr[2 * ntp + 1][1] = r[3];
            }
            #pragma unroll
            for (int mt = 0; mt < 4; ++mt)
                #pragma unroll
                for (int nt = 0; nt < 4; ++nt)
                    mma_fp16(acc[mt][nt], afr[mt], bfr[nt]);
        }
        s = (s + 1) % G_STAGES;
    }

    // Epilogue
    const int erow = lane >> 2;
    const int ecol = (lane & 3) * 2;
    #pragma unroll
    for (int mt = 0; mt < 4; ++mt) {
        const int rA = rowBase + wm * 64 + mt * 16 + erow;
        #pragma unroll
        for (int nt = 0; nt < 4; ++nt) {
            const int col = colBase + wn * 32 + nt * 8 + ecol;
            const float b0 = bias[col], b1 = bias[col + 1];
            *(float2*)&C[(size_t)rA * N + col] =
                make_float2(acc[mt][nt][0] + b0, acc[mt][nt][1] + b1);
            *(float2*)&C[(size_t)(rA + 8) * N + col] =
                make_float2(acc[mt][nt][2] + b0, acc[mt][nt][3] + b1);
        }
    }
}

// ---------------------------------------------------------------------------
// Fused RMSNorm + K/V fp16 store. One warp per (token, slot).
// slot 0..15 : q head h -> rmsnorm in place (fp32, for attention Q load)
// slot 16..31: k head h -> rmsnorm + fp16 hi to g_ks; v head h -> fp16 hi to g_vs
// ---------------------------------------------------------------------------
__global__ __launch_bounds__(256) void rmskv_kernel(
    float* __restrict__ qkv,
    const float* __restrict__ qn_w, const float* __restrict__ kn_w,
    __half* __restrict__ ks, __half* __restrict__ vs)
{
    const int gwarp = (blockIdx.x * blockDim.x + threadIdx.x) >> 5;
    const int lane  = threadIdx.x & 31;
    const int token = gwarp >> 5;
    const int slot  = gwarp & 31;
    if (token >= TOKENS) return;

    const int h = slot & 15;

    if (slot < 16) {
        float* row = qkv + (size_t)token * QKVDIM + h * HDIM;
        float x0 = row[lane];
        float x1 = row[lane + 32];
        float ss = x0 * x0 + x1 * x1;
        #pragma unroll
        for (int off = 16; off; off >>= 1) ss += __shfl_xor_sync(0xffffffffu, ss, off);
        const float inv = rsqrtf(ss * (1.0f / 64.0f) + 1e-6f);
        row[lane]      = x0 * inv * qn_w[lane];
        row[lane + 32] = x1 * inv * qn_w[lane + 32];
    } else {
        const int b = token >> 11;
        const int n = token & 2047;
        const size_t dstRow = ((size_t)(b * HEADS + h) * SEQ + n) * 64;

        {   // K: rmsnorm + fp16
            const float* row = qkv + (size_t)token * QKVDIM + CDIM + h * HDIM;
            float x0 = row[lane];
            float x1 = row[lane + 32];
            float ss = x0 * x0 + x1 * x1;
            #pragma unroll
            for (int off = 16; off; off >>= 1) ss += __shfl_xor_sync(0xffffffffu, ss, off);
            const float inv = rsqrtf(ss * (1.0f / 64.0f) + 1e-6f);
            ks[dstRow + lane]      = __float2half_rn(x0 * inv * kn_w[lane]);
            ks[dstRow + lane + 32] = __float2half_rn(x1 * inv * kn_w[lane + 32]);
        }
        {   // V: fp16
            const float* row = qkv + (size_t)token * QKVDIM + 2 * CDIM + h * HDIM;
            vs[dstRow + lane]      = __float2half_rn(row[lane]);
            vs[dstRow + lane + 32] = __float2half_rn(row[lane + 32]);
        }
    }
}

// ---------------------------------------------------------------------------
// FlashAttention-2 style mma.sync fp16 attention. Bc=128, 3-stage pipeline.
// Q and P carried as 2-term fp16 (hi+lo); K and V as fp16 hi only.
// CTA = 128 q-rows x (b,h); 8 warps x 16 rows. K/V tiles: 128 rows x 128B.
// ---------------------------------------------------------------------------
#define ATT_NT (SEQ / 128)            // 16 key tiles
#define ATT_TILE_B 16384              // one matrix tile: 128 rows * 128B
#define ATT_BUF_B  32768              // K + V per stage
#define ATT_STAGES 3
#define ATT_SMEM   (ATT_STAGES * ATT_BUF_B)   // 98304

__global__ __launch_bounds__(256) void attn_mma_kernel(
    const float* __restrict__ qkv,
    const __half* __restrict__ ks, const __half* __restrict__ vs,
    __half* __restrict__ outA)
{
    extern __shared__ __align__(256) char sm[];
    const uint32_t smBase = smem_u32(sm);

    const int tid  = threadIdx.x;
    const int wq   = tid >> 5;
    const int lane = tid & 31;

    const int bh = blockIdx.y;
    const int b  = bh >> 4;
    const int h  = bh & 15;
    const int qBase = blockIdx.x * 128;

    // ---- Q fragments (hi/lo fp16), scale folded: 0.125 * log2(e) ----
    const float SC = 0.125f * 1.44269504088896340736f;
    uint32_t qh[4][4], ql[4][4];
    {
        const float* qg = qkv + ((size_t)(b * SEQ + qBase + wq * 16)) * QKVDIM + h * HDIM;
        const int rr = lane >> 2;
        const int cb = (lane & 3) * 2;
        #pragma unroll
        for (int kd = 0; kd < 4; ++kd) {
            const int d0 = kd * 16;
            float2 v0 = *(const float2*)&qg[(size_t)rr * QKVDIM + d0 + cb];
            float2 v1 = *(const float2*)&qg[(size_t)(rr + 8) * QKVDIM + d0 + cb];
            float2 v2 = *(const float2*)&qg[(size_t)rr * QKVDIM + d0 + cb + 8];
            float2 v3 = *(const float2*)&qg[(size_t)(rr + 8) * QKVDIM + d0 + cb + 8];
            v0.x *= SC; v0.y *= SC; v1.x *= SC; v1.y *= SC;
            v2.x *= SC; v2.y *= SC; v3.x *= SC; v3.y *= SC;
            qh[kd][0] = h2pack(v0.x, v0.y); ql[kd][0] = h2pack_lo(v0.x, v0.y, qh[kd][0]);
            qh[kd][1] = h2pack(v1.x, v1.y); ql[kd][1] = h2pack_lo(v1.x, v1.y, qh[kd][1]);
            qh[kd][2] = h2pack(v2.x, v2.y); ql[kd][2] = h2pack_lo(v2.x, v2.y, qh[kd][2]);
            qh[kd][3] = h2pack(v3.x, v3.y); ql[kd][3] = h2pack_lo(v3.x, v3.y, qh[kd][3]);
        }
    }

    // ---- cp.async tile loader: 128 keys, K + V hi (128B rows, XOR swizzle) ----
    auto loadTile = [&](int kt, int st) {
        const __half* gk = ks + ((size_t)bh * SEQ + kt * 128) * 64;
        const __half* gv = vs + ((size_t)bh * SEQ + kt * 128) * 64;
        const uint32_t kb = smBase + st * ATT_BUF_B;
        const uint32_t vb = kb + ATT_TILE_B;
        #pragma unroll
        for (int m = 0; m < 4; ++m) {
            const int id = tid + m * 256;           // 0..1023
            const int c = id >> 3, j = id & 7;
            const uint32_t soff = c * 128 + ((j ^ (c & 7)) << 4);
            cp_async16(kb + soff, gk + (size_t)c * 64 + j * 8);
            cp_async16(vb + soff, gv + (size_t)c * 64 + j * 8);
        }
        cp_commit();
    };

    float m0 = -CUDART_INF_F, m1 = -CUDART_INF_F, l0 = 0.0f, l1 = 0.0f;
    float O[8][4] = {};

    loadTile(0, 0);
    loadTile(1, 1);

    for (int kt = 0; kt < ATT_NT; ++kt) {
        const int st = kt % ATT_STAGES;
        if (kt + 2 < ATT_NT) cp_wait1(); else cp_wait0();
        __syncthreads();
        if (kt + 2 < ATT_NT) loadTile(kt + 2, (kt + 2) % ATT_STAGES);

        const uint32_t Kb = smBase + st * ATT_BUF_B;
        const uint32_t Vb = Kb + ATT_TILE_B;

        // ---- S = (Qh+Ql) K^T, 128 keys ----
        float S[16][4] = {};
        #pragma unroll
        for (int kd = 0; kd < 4; ++kd) {
            #pragma unroll
            for (int t = 0; t < 8; ++t) {
                const int row = 16 * t + (lane & 7) + 8 * ((lane >> 4) & 1);
                const int j = kd * 2 + ((lane >> 3) & 1);
                uint32_t r[4];
                ldsm_x4(r, Kb + row * 128 + ((j ^ (row & 7)) << 4));
                mma_fp16(S[2 * t],     qh[kd], r);
                mma_fp16(S[2 * t],     ql[kd], r);
                mma_fp16(S[2 * t + 1], qh[kd], r + 2);
                mma_fp16(S[2 * t + 1], ql[kd], r + 2);
            }
        }

        // ---- Online softmax (base 2) ----
        float mt0 = -CUDART_INF_F, mt1 = -CUDART_INF_F;
        #pragma unroll
        for (int nc = 0; nc < 16; ++nc) {
            mt0 = fmaxf(mt0, fmaxf(S[nc][0], S[nc][1]));
            mt1 = fmaxf(mt1, fmaxf(S[nc][2], S[nc][3]));
        }
        mt0 = fmaxf(mt0, __shfl_xor_sync(0xffffffffu, mt0, 1));
        mt0 = fmaxf(mt0, __shfl_xor_sync(0xffffffffu, mt0, 2));
        mt1 = fmaxf(mt1, __shfl_xor_sync(0xffffffffu, mt1, 1));
        mt1 = fmaxf(mt1, __shfl_xor_sync(0xffffffffu, mt1, 2));
        const float mn0 = fmaxf(m0, mt0);
        const float mn1 = fmaxf(m1, mt1);
        const float c0 = ex2f(m0 - mn0);
        const float c1 = ex2f(m1 - mn1);
        m0 = mn0; m1 = mn1;
        float rs0 = 0.0f, rs1 = 0.0f;
        #pragma unroll
        for (int nc = 0; nc < 16; ++nc) {
            S[nc][0] = ex2f(S[nc][0] - mn0); rs0 += S[nc][0];
            S[nc][1] = ex2f(S[nc][1] - mn0); rs0 += S[nc][1];
            S[nc][2] = ex2f(S[nc][2] - mn1); rs1 += S[nc][2];
            S[nc][3] = ex2f(S[nc][3] - mn1); rs1 += S[nc][3];
        }
        rs0 += __shfl_xor_sync(0xffffffffu, rs0, 1);
        rs0 += __shfl_xor_sync(0xffffffffu, rs0, 2);
        rs1 += __shfl_xor_sync(0xffffffffu, rs1, 1);
        rs1 += __shfl_xor_sync(0xffffffffu, rs1, 2);
        l0 = l0 * c0 + rs0;
        l1 = l1 * c1 + rs1;
        #pragma unroll
        for (int nd = 0; nd < 8; ++nd) {
            O[nd][0] *= c0; O[nd][1] *= c0; O[nd][2] *= c1; O[nd][3] *= c1;
        }

        // ---- O += (Ph+Pl) V, 8 k16 chunks ----
        #pragma unroll
        for (int kc = 0; kc < 8; ++kc) {
            uint32_t ph[4], pl[4];
            {
                const float* s0 = S[2 * kc];
                const float* s1 = S[2 * kc + 1];
                ph[0] = h2pack(s0[0], s0[1]); pl[0] = h2pack_lo(s0[0], s0[1], ph[0]);
                ph[1] = h2pack(s0[2], s0[3]); pl[1] = h2pack_lo(s0[2], s0[3], ph[1]);
                ph[2] = h2pack(s1[0], s1[1]); pl[2] = h2pack_lo(s1[0], s1[1], ph[2]);
                ph[3] = h2pack(s1[2], s1[3]); pl[3] = h2pack_lo(s1[2], s1[3], ph[3]);
            }
            #pragma unroll
            for (int t = 0; t < 4; ++t) {
                const int row = kc * 16 + (lane & 7) + 8 * ((lane >> 3) & 1);
                const int j = 2 * t + ((lane >> 4) & 1);
                uint32_t r[4];
                ldsm_x4_t(r, Vb + row * 128 + ((j ^ (row & 7)) << 4));
                mma_fp16(O[2 * t],     ph, r);
                mma_fp16(O[2 * t],     pl, r);
                mma_fp16(O[2 * t + 1], ph, r + 2);
                mma_fp16(O[2 * t + 1], pl, r + 2);
            }
        }
    }

    // ---- Epilogue: normalize, write fp16 hi/lo split rows to outA ----
    const float inv0 = 1.0f / l0;
    const float inv1 = 1.0f / l1;
    const size_t row1 = (size_t)b * SEQ + qBase + wq * 16 + (lane >> 2);
    const int colBase = h * HDIM + (lane & 3) * 2;
    #pragma unroll
    for (int nd = 0; nd < 8; ++nd) {
        const int col = colBase + nd * 8;
        {
            const float x = O[nd][0] * inv0, y = O[nd][1] * inv0;
            __half* p = outA + row1 * KA + col;
            const uint32_t hp = h2pack(x, y);
            *(uint32_t*)p = hp;
            *(uint32_t*)(p + 1024) = h2pack_lo(x, y, hp);
        }
        {
            const float x = O[nd][2] * inv1, y = O[nd][3] * inv1;
            __half* p = outA + (row1 + 8) * KA + col;
            const uint32_t hp = h2pack(x, y);
            *(uint32_t*)p = hp;
            *(uint32_t*)(p + 1024) = h2pack_lo(x, y, hp);
        }
    }
}

// ---------------------------------------------------------------------------
// Launch
// ---------------------------------------------------------------------------
extern "C" void kernel_launch(void* const* d_in, const int* in_sizes, int n_in,
                              void* d_out, int out_size)
{
    (void)in_sizes; (void)n_in; (void)out_size;
    const float* x      = (const float*)d_in[0];
    const float* W_qkv  = (const float*)d_in[1];
    const float* b_qkv  = (const float*)d_in[2];
    const float* W_proj = (const float*)d_in[3];
    const float* b_proj = (const float*)d_in[4];
    const float* qn_w   = (const float*)d_in[5];
    const float* kn_w   = (const float*)d_in[6];
    float* out = (float*)d_out;

    float *qkv = nullptr;
    __half *A1 = nullptr, *B1 = nullptr, *B2 = nullptr, *A2 = nullptr;
    __half *ksp = nullptr, *vsp = nullptr;
    cudaGetSymbolAddress((void**)&qkv, g_qkv);
    cudaGetSymbolAddress((void**)&A1,  g_A1);
    cudaGetSymbolAddress((void**)&B1,  g_B1);
    cudaGetSymbolAddress((void**)&B2,  g_B2);
    cudaGetSymbolAddress((void**)&A2,  g_A2);
    cudaGetSymbolAddress((void**)&ksp, g_ks);
    cudaGetSymbolAddress((void**)&vsp, g_vs);

    cudaFuncSetAttribute(gemm_mma_kernel, cudaFuncAttributeMaxDynamicSharedMemorySize, G_SMEM);
    cudaFuncSetAttribute(attn_mma_kernel, cudaFuncAttributeMaxDynamicSharedMemorySize, ATT_SMEM);

    // 0) Conversions to fp16 formats
    convX_kernel<<<(TOKENS * CDIM) / 256, 256>>>(x, A1);
    convW_kernel<<<dim3(QKVDIM / 32, CDIM / 32), 256>>>(W_qkv, B1, QKVDIM);
    convW_kernel<<<dim3(CDIM / 32, CDIM / 32), 256>>>(W_proj, B2, CDIM);

    // 1) QKV projection: [8192, 3072] = (A1hi+A1lo) @ B1^T + b_qkv
    gemm_mma_kernel<<<dim3(QKVDIM / BN, TOKENS / BM), 256, G_SMEM>>>(A1, B1, b_qkv, qkv, QKVDIM);

    // 2) Fused RMSNorm (q in place, k) + K/V fp16 store
    rmskv_kernel<<<(TOKENS * 32) / 8, 256>>>(qkv, qn_w, kn_w, ksp, vsp);

    // 3) Attention (tensor cores) -> g_A2 (fp16 hi/lo, proj-ready)
    attn_mma_kernel<<<dim3(SEQ / 128, BATCH * HEADS), 256, ATT_SMEM>>>(qkv, ksp, vsp, A2);

    // 4) Output projection: [8192, 1024] = (A2hi+A2lo) @ B2^T + b_proj
    gemm_mma_kernel<<<dim3(CDIM / BN, TOKENS / BM), 256, G_SMEM>>>(A2, B2, b_proj, out, CDIM);
}

// round 8
// speedup vs baseline: 5.3519x; 1.0524x over previous
#include <cuda_runtime.h>
#include <cuda_fp16.h>
#include <math_constants.h>
#include <cstdint>

// Problem constants
#define BATCH 4
#define SEQ   2048
#define CDIM  1024
#define HEADS 16
#define HDIM  64
#define TOKENS (BATCH * SEQ)         // 8192
#define QKVDIM (3 * CDIM)            // 3072
#define KA    2048                   // A-side split K (hi|lo)
#define KB    1024                   // B-side K (hi only)

// ---------------------------------------------------------------------------
// Scratch (device globals — no allocation allowed)
// ---------------------------------------------------------------------------
__device__ float g_qkv[(size_t)TOKENS * QKVDIM];                    // QKV output fp32
__device__ __align__(256) __half g_A1[(size_t)TOKENS * KA];        // x split      [m, hi|lo]
__device__ __align__(256) __half g_B1[(size_t)QKVDIM * KB];        // W_qkv^T hi   [n, k]
__device__ __align__(256) __half g_B2[(size_t)CDIM * KB];          // W_proj^T hi
__device__ __align__(256) __half g_A2[(size_t)TOKENS * KA];        // attn out split [m, hi|lo]
__device__ __align__(256) __half g_ks[(size_t)BATCH * HEADS * SEQ * 64]; // K hi [bh, n, d]
__device__ __align__(256) __half g_vs[(size_t)BATCH * HEADS * SEQ * 64]; // V hi

// ---------------------------------------------------------------------------
// PTX helpers (portable sm_80+ features only)
// ---------------------------------------------------------------------------
__device__ __forceinline__ uint32_t smem_u32(const void* p) {
    uint32_t a;
    asm("{ .reg .u64 t; cvta.to.shared.u64 t, %1; cvt.u32.u64 %0, t; }" : "=r"(a) : "l"(p));
    return a;
}
__device__ __forceinline__ void cp_async16(uint32_t dst, const void* src) {
    asm volatile("cp.async.cg.shared.global [%0], [%1], 16;" :: "r"(dst), "l"(src));
}
__device__ __forceinline__ void cp_commit() {
    asm volatile("cp.async.commit_group;" ::: "memory");
}
__device__ __forceinline__ void cp_wait0() {
    asm volatile("cp.async.wait_group 0;" ::: "memory");
}
__device__ __forceinline__ void cp_wait1() {
    asm volatile("cp.async.wait_group 1;" ::: "memory");
}
__device__ __forceinline__ void ldsm_x4(uint32_t* r, uint32_t addr) {
    asm volatile("ldmatrix.sync.aligned.m8n8.x4.shared.b16 {%0,%1,%2,%3}, [%4];"
                 : "=r"(r[0]), "=r"(r[1]), "=r"(r[2]), "=r"(r[3]) : "r"(addr));
}
__device__ __forceinline__ void ldsm_x4_t(uint32_t* r, uint32_t addr) {
    asm volatile("ldmatrix.sync.aligned.m8n8.x4.trans.shared.b16 {%0,%1,%2,%3}, [%4];"
                 : "=r"(r[0]), "=r"(r[1]), "=r"(r[2]), "=r"(r[3]) : "r"(addr));
}
__device__ __forceinline__ void mma_fp16(float* c, const uint32_t* a, const uint32_t* b) {
    asm volatile(
        "mma.sync.aligned.m16n8k16.row.col.f32.f16.f16.f32 "
        "{%0,%1,%2,%3}, {%4,%5,%6,%7}, {%8,%9}, {%0,%1,%2,%3};"
        : "+f"(c[0]), "+f"(c[1]), "+f"(c[2]), "+f"(c[3])
        : "r"(a[0]), "r"(a[1]), "r"(a[2]), "r"(a[3]), "r"(b[0]), "r"(b[1]));
}
__device__ __forceinline__ float ex2f(float x) {
    float y; asm("ex2.approx.ftz.f32 %0, %1;" : "=f"(y) : "f"(x)); return y;
}
__device__ __forceinline__ uint32_t h2pack(float a, float b) {
    __half2 h;
    h.x = __float2half_rn(a);
    h.y = __float2half_rn(b);
    return *(uint32_t*)&h;
}
__device__ __forceinline__ uint32_t h2pack_lo(float a, float b, uint32_t hipack) {
    __half2 h = *(__half2*)&hipack;
    return h2pack(a - __half2float(h.x), b - __half2float(h.y));
}

// ---------------------------------------------------------------------------
// Conversion kernels (fp32 -> fp16 hi/lo split)
// ---------------------------------------------------------------------------
__global__ __launch_bounds__(256) void convX_kernel(const float* __restrict__ x,
                                                    __half* __restrict__ A)
{
    const int idx = blockIdx.x * 256 + threadIdx.x;      // over TOKENS*CDIM
    const int m = idx >> 10;
    const int k = idx & 1023;
    const float v = x[idx];
    const __half hi = __float2half_rn(v);
    __half* row = A + (size_t)m * KA;
    row[k]        = hi;
    row[1024 + k] = __float2half_rn(v - __half2float(hi));
}

// Transpose: W [K=1024, N] fp32 -> B [N, 1024] fp16 (hi only)
__global__ __launch_bounds__(256) void convW_kernel(const float* __restrict__ W,
                                                    __half* __restrict__ B, int N)
{
    __shared__ float t[32][33];
    const int n0 = blockIdx.x * 32;
    const int k0 = blockIdx.y * 32;
    const int tx = threadIdx.x & 31;
    const int ty = threadIdx.x >> 5;          // 0..7
    #pragma unroll
    for (int i = 0; i < 4; ++i)
        t[ty + 8 * i][tx] = W[(size_t)(k0 + ty + 8 * i) * N + n0 + tx];
    __syncthreads();
    #pragma unroll
    for (int i = 0; i < 4; ++i) {
        const int n = n0 + ty + 8 * i;
        const int k = k0 + tx;
        B[(size_t)n * KB + k] = __float2half_rn(t[tx][ty + 8 * i]);
    }
}

// ---------------------------------------------------------------------------
// mma.sync fp16 GEMM v3:  C[M,N] = (A_hi + A_lo) @ B_hi^T + bias
// Stage holds {A_hi, A_lo, B} for ONE k64 range -> B fragments shared by the
// hi and lo MMAs in registers. 16 chunks, 2-stage double buffer, one barrier
// per chunk. CTA 128x128, 8 warps (2x4), warp tile 64x32.
// ---------------------------------------------------------------------------
#define BM 128
#define BN 128
#define BK 64
#define G_REGION (BM * BK * 2)           // 16384 bytes per matrix region
#define G_STAGE_BYTES (3 * G_REGION)     // 49152 (Ahi + Alo + B)
#define G_SMEM (2 * G_STAGE_BYTES)       // 98304
#define NCHUNKG (KB / BK)                // 16

__global__ __launch_bounds__(256, 2) void gemm_mma_kernel(
    const __half* __restrict__ A, const __half* __restrict__ Bm,
    const float* __restrict__ bias, float* __restrict__ C, int N)
{
    extern __shared__ __align__(256) char gsm[];
    const uint32_t base = smem_u32(gsm);

    const int tid  = threadIdx.x;
    const int wid  = tid >> 5;
    const int lane = tid & 31;
    const int wm   = wid >> 2;           // 0..1
    const int wn   = wid & 3;            // 0..3
    const int rowBase = blockIdx.y * BM;
    const int colBase = blockIdx.x * BN;

    float acc[4][4][4] = {};

    const int lrow = tid >> 3;           // 0..31 (x4 via +32)
    const int lch  = tid & 7;

    auto loadStage = [&](int c, int s) {
        const __half* Ah = A + (size_t)rowBase * KA + c * BK;          // hi cols
        const __half* Al = Ah + 1024;                                   // lo cols
        const __half* Bg = Bm + (size_t)colBase * KB + c * BK;
        const uint32_t st = base + s * G_STAGE_BYTES;
        #pragma unroll
        for (int m = 0; m < 4; ++m) {
            const int row = lrow + m * 32;
            const uint32_t soff = row * 128 + ((lch ^ (row & 7)) << 4);
            cp_async16(st + soff,                Ah + (size_t)row * KA + lch * 8);
            cp_async16(st + G_REGION + soff,     Al + (size_t)row * KA + lch * 8);
            cp_async16(st + 2 * G_REGION + soff, Bg + (size_t)row * KB + lch * 8);
        }
        cp_commit();
    };

    loadStage(0, 0);

    for (int c = 0; c < NCHUNKG; ++c) {
        cp_wait0();
        __syncthreads();                 // chunk c visible; compute of c-1 done everywhere
        if (c + 1 < NCHUNKG) loadStage(c + 1, (c + 1) & 1);

        const uint32_t st = base + (c & 1) * G_STAGE_BYTES;
        const uint32_t ahs = st;
        const uint32_t als = st + G_REGION;
        const uint32_t bsb = st + 2 * G_REGION;

        #pragma unroll
        for (int ks = 0; ks < 4; ++ks) {
            const int arow = wm * 64 + (lane & 15);
            const int ach  = ks * 2 + (lane >> 4);
            uint32_t ahfr[4][4], alfr[4][4];
            #pragma unroll
            for (int mt = 0; mt < 4; ++mt) {
                const int row = arow + mt * 16;
                const uint32_t off = row * 128 + ((ach ^ (row & 7)) << 4);
                ldsm_x4(ahfr[mt], ahs + off);
                ldsm_x4(alfr[mt], als + off);
            }
            uint32_t bfr[4][2];
            #pragma unroll
            for (int ntp = 0; ntp < 2; ++ntp) {
                const int row = wn * 32 + ntp * 16 + (lane & 7) + ((lane >> 4) << 3);
                const int ch  = ks * 2 + ((lane >> 3) & 1);
                uint32_t r[4];
                ldsm_x4(r, bsb + row * 128 + ((ch ^ (row & 7)) << 4));
                bfr[2 * ntp][0]     = r[0]; bfr[2 * ntp][1]     = r[1];
                bfr[2 * ntp + 1][0] = r[2]; bfr[2 * ntp + 1][1] = r[3];
            }
            #pragma unroll
            for (int mt = 0; mt < 4; ++mt)
                #pragma unroll
                for (int nt = 0; nt < 4; ++nt) {
                    mma_fp16(acc[mt][nt], ahfr[mt], bfr[nt]);
                    mma_fp16(acc[mt][nt], alfr[mt], bfr[nt]);
                }
        }
        __syncthreads();                 // all reads of stage c done before reload
    }

    // Epilogue
    const int erow = lane >> 2;
    const int ecol = (lane & 3) * 2;
    #pragma unroll
    for (int mt = 0; mt < 4; ++mt) {
        const int rA = rowBase + wm * 64 + mt * 16 + erow;
        #pragma unroll
        for (int nt = 0; nt < 4; ++nt) {
            const int col = colBase + wn * 32 + nt * 8 + ecol;
            const float b0 = bias[col], b1 = bias[col + 1];
            *(float2*)&C[(size_t)rA * N + col] =
                make_float2(acc[mt][nt][0] + b0, acc[mt][nt][1] + b1);
            *(float2*)&C[(size_t)(rA + 8) * N + col] =
                make_float2(acc[mt][nt][2] + b0, acc[mt][nt][3] + b1);
        }
    }
}

// ---------------------------------------------------------------------------
// Fused RMSNorm + K/V fp16 store. One warp per (token, slot).
// ---------------------------------------------------------------------------
__global__ __launch_bounds__(256) void rmskv_kernel(
    float* __restrict__ qkv,
    const float* __restrict__ qn_w, const float* __restrict__ kn_w,
    __half* __restrict__ ks, __half* __restrict__ vs)
{
    const int gwarp = (blockIdx.x * blockDim.x + threadIdx.x) >> 5;
    const int lane  = threadIdx.x & 31;
    const int token = gwarp >> 5;
    const int slot  = gwarp & 31;
    if (token >= TOKENS) return;

    const int h = slot & 15;

    if (slot < 16) {
        float* row = qkv + (size_t)token * QKVDIM + h * HDIM;
        float x0 = row[lane];
        float x1 = row[lane + 32];
        float ss = x0 * x0 + x1 * x1;
        #pragma unroll
        for (int off = 16; off; off >>= 1) ss += __shfl_xor_sync(0xffffffffu, ss, off);
        const float inv = rsqrtf(ss * (1.0f / 64.0f) + 1e-6f);
        row[lane]      = x0 * inv * qn_w[lane];
        row[lane + 32] = x1 * inv * qn_w[lane + 32];
    } else {
        const int b = token >> 11;
        const int n = token & 2047;
        const size_t dstRow = ((size_t)(b * HEADS + h) * SEQ + n) * 64;

        {   // K: rmsnorm + fp16
            const float* row = qkv + (size_t)token * QKVDIM + CDIM + h * HDIM;
            float x0 = row[lane];
            float x1 = row[lane + 32];
            float ss = x0 * x0 + x1 * x1;
            #pragma unroll
            for (int off = 16; off; off >>= 1) ss += __shfl_xor_sync(0xffffffffu, ss, off);
            const float inv = rsqrtf(ss * (1.0f / 64.0f) + 1e-6f);
            ks[dstRow + lane]      = __float2half_rn(x0 * inv * kn_w[lane]);
            ks[dstRow + lane + 32] = __float2half_rn(x1 * inv * kn_w[lane + 32]);
        }
        {   // V: fp16
            const float* row = qkv + (size_t)token * QKVDIM + 2 * CDIM + h * HDIM;
            vs[dstRow + lane]      = __float2half_rn(row[lane]);
            vs[dstRow + lane + 32] = __float2half_rn(row[lane + 32]);
        }
    }
}

// ---------------------------------------------------------------------------
// FlashAttention-2 style mma.sync fp16 attention (unchanged from R7).
// ---------------------------------------------------------------------------
#define ATT_NT (SEQ / 128)            // 16 key tiles
#define ATT_TILE_B 16384              // one matrix tile: 128 rows * 128B
#define ATT_BUF_B  32768              // K + V per stage
#define ATT_STAGES 3
#define ATT_SMEM   (ATT_STAGES * ATT_BUF_B)   // 98304

__global__ __launch_bounds__(256) void attn_mma_kernel(
    const float* __restrict__ qkv,
    const __half* __restrict__ ks, const __half* __restrict__ vs,
    __half* __restrict__ outA)
{
    extern __shared__ __align__(256) char sm[];
    const uint32_t smBase = smem_u32(sm);

    const int tid  = threadIdx.x;
    const int wq   = tid >> 5;
    const int lane = tid & 31;

    const int bh = blockIdx.y;
    const int b  = bh >> 4;
    const int h  = bh & 15;
    const int qBase = blockIdx.x * 128;

    // ---- Q fragments (hi/lo fp16), scale folded: 0.125 * log2(e) ----
    const float SC = 0.125f * 1.44269504088896340736f;
    uint32_t qh[4][4], ql[4][4];
    {
        const float* qg = qkv + ((size_t)(b * SEQ + qBase + wq * 16)) * QKVDIM + h * HDIM;
        const int rr = lane >> 2;
        const int cb = (lane & 3) * 2;
        #pragma unroll
        for (int kd = 0; kd < 4; ++kd) {
            const int d0 = kd * 16;
            float2 v0 = *(const float2*)&qg[(size_t)rr * QKVDIM + d0 + cb];
            float2 v1 = *(const float2*)&qg[(size_t)(rr + 8) * QKVDIM + d0 + cb];
            float2 v2 = *(const float2*)&qg[(size_t)rr * QKVDIM + d0 + cb + 8];
            float2 v3 = *(const float2*)&qg[(size_t)(rr + 8) * QKVDIM + d0 + cb + 8];
            v0.x *= SC; v0.y *= SC; v1.x *= SC; v1.y *= SC;
            v2.x *= SC; v2.y *= SC; v3.x *= SC; v3.y *= SC;
            qh[kd][0] = h2pack(v0.x, v0.y); ql[kd][0] = h2pack_lo(v0.x, v0.y, qh[kd][0]);
            qh[kd][1] = h2pack(v1.x, v1.y); ql[kd][1] = h2pack_lo(v1.x, v1.y, qh[kd][1]);
            qh[kd][2] = h2pack(v2.x, v2.y); ql[kd][2] = h2pack_lo(v2.x, v2.y, qh[kd][2]);
            qh[kd][3] = h2pack(v3.x, v3.y); ql[kd][3] = h2pack_lo(v3.x, v3.y, qh[kd][3]);
        }
    }

    // ---- cp.async tile loader: 128 keys, K + V hi (128B rows, XOR swizzle) ----
    auto loadTile = [&](int kt, int st) {
        const __half* gk = ks + ((size_t)bh * SEQ + kt * 128) * 64;
        const __half* gv = vs + ((size_t)bh * SEQ + kt * 128) * 64;
        const uint32_t kb = smBase + st * ATT_BUF_B;
        const uint32_t vb = kb + ATT_TILE_B;
        #pragma unroll
        for (int m = 0; m < 4; ++m) {
            const int id = tid + m * 256;           // 0..1023
            const int c = id >> 3, j = id & 7;
            const uint32_t soff = c * 128 + ((j ^ (c & 7)) << 4);
            cp_async16(kb + soff, gk + (size_t)c * 64 + j * 8);
            cp_async16(vb + soff, gv + (size_t)c * 64 + j * 8);
        }
        cp_commit();
    };

    float m0 = -CUDART_INF_F, m1 = -CUDART_INF_F, l0 = 0.0f, l1 = 0.0f;
    float O[8][4] = {};

    loadTile(0, 0);
    loadTile(1, 1);

    for (int kt = 0; kt < ATT_NT; ++kt) {
        const int st = kt % ATT_STAGES;
        if (kt + 2 < ATT_NT) cp_wait1(); else cp_wait0();
        __syncthreads();
        if (kt + 2 < ATT_NT) loadTile(kt + 2, (kt + 2) % ATT_STAGES);

        const uint32_t Kb = smBase + st * ATT_BUF_B;
        const uint32_t Vb = Kb + ATT_TILE_B;

        // ---- S = (Qh+Ql) K^T, 128 keys ----
        float S[16][4] = {};
        #pragma unroll
        for (int kd = 0; kd < 4; ++kd) {
            #pragma unroll
            for (int t = 0; t < 8; ++t) {
                const int row = 16 * t + (lane & 7) + 8 * ((lane >> 4) & 1);
                const int j = kd * 2 + ((lane >> 3) & 1);
                uint32_t r[4];
                ldsm_x4(r, Kb + row * 128 + ((j ^ (row & 7)) << 4));
                mma_fp16(S[2 * t],     qh[kd], r);
                mma_fp16(S[2 * t],     ql[kd], r);
                mma_fp16(S[2 * t + 1], qh[kd], r + 2);
                mma_fp16(S[2 * t + 1], ql[kd], r + 2);
            }
        }

        // ---- Online softmax (base 2) ----
        float mt0 = -CUDART_INF_F, mt1 = -CUDART_INF_F;
        #pragma unroll
        for (int nc = 0; nc < 16; ++nc) {
            mt0 = fmaxf(mt0, fmaxf(S[nc][0], S[nc][1]));
            mt1 = fmaxf(mt1, fmaxf(S[nc][2], S[nc][3]));
        }
        mt0 = fmaxf(mt0, __shfl_xor_sync(0xffffffffu, mt0, 1));
        mt0 = fmaxf(mt0, __shfl_xor_sync(0xffffffffu, mt0, 2));
        mt1 = fmaxf(mt1, __shfl_xor_sync(0xffffffffu, mt1, 1));
        mt1 = fmaxf(mt1, __shfl_xor_sync(0xffffffffu, mt1, 2));
        const float mn0 = fmaxf(m0, mt0);
        const float mn1 = fmaxf(m1, mt1);
        const float c0 = ex2f(m0 - mn0);
        const float c1 = ex2f(m1 - mn1);
        m0 = mn0; m1 = mn1;
        float rs0 = 0.0f, rs1 = 0.0f;
        #pragma unroll
        for (int nc = 0; nc < 16; ++nc) {
            S[nc][0] = ex2f(S[nc][0] - mn0); rs0 += S[nc][0];
            S[nc][1] = ex2f(S[nc][1] - mn0); rs0 += S[nc][1];
            S[nc][2] = ex2f(S[nc][2] - mn1); rs1 += S[nc][2];
            S[nc][3] = ex2f(S[nc][3] - mn1); rs1 += S[nc][3];
        }
        rs0 += __shfl_xor_sync(0xffffffffu, rs0, 1);
        rs0 += __shfl_xor_sync(0xffffffffu, rs0, 2);
        rs1 += __shfl_xor_sync(0xffffffffu, rs1, 1);
        rs1 += __shfl_xor_sync(0xffffffffu, rs1, 2);
        l0 = l0 * c0 + rs0;
        l1 = l1 * c1 + rs1;
        #pragma unroll
        for (int nd = 0; nd < 8; ++nd) {
            O[nd][0] *= c0; O[nd][1] *= c0; O[nd][2] *= c1; O[nd][3] *= c1;
        }

        // ---- O += (Ph+Pl) V, 8 k16 chunks ----
        #pragma unroll
        for (int kc = 0; kc < 8; ++kc) {
            uint32_t ph[4], pl[4];
            {
                const float* s0 = S[2 * kc];
                const float* s1 = S[2 * kc + 1];
                ph[0] = h2pack(s0[0], s0[1]); pl[0] = h2pack_lo(s0[0], s0[1], ph[0]);
                ph[1] = h2pack(s0[2], s0[3]); pl[1] = h2pack_lo(s0[2], s0[3], ph[1]);
                ph[2] = h2pack(s1[0], s1[1]); pl[2] = h2pack_lo(s1[0], s1[1], ph[2]);
                ph[3] = h2pack(s1[2], s1[3]); pl[3] = h2pack_lo(s1[2], s1[3], ph[3]);
            }
            #pragma unroll
            for (int t = 0; t < 4; ++t) {
                const int row = kc * 16 + (lane & 7) + 8 * ((lane >> 3) & 1);
                const int j = 2 * t + ((lane >> 4) & 1);
                uint32_t r[4];
                ldsm_x4_t(r, Vb + row * 128 + ((j ^ (row & 7)) << 4));
                mma_fp16(O[2 * t],     ph, r);
                mma_fp16(O[2 * t],     pl, r);
                mma_fp16(O[2 * t + 1], ph, r + 2);
                mma_fp16(O[2 * t + 1], pl, r + 2);
            }
        }
    }

    // ---- Epilogue: normalize, write fp16 hi/lo split rows to outA ----
    const float inv0 = 1.0f / l0;
    const float inv1 = 1.0f / l1;
    const size_t row1 = (size_t)b * SEQ + qBase + wq * 16 + (lane >> 2);
    const int colBase = h * HDIM + (lane & 3) * 2;
    #pragma unroll
    for (int nd = 0; nd < 8; ++nd) {
        const int col = colBase + nd * 8;
        {
            const float x = O[nd][0] * inv0, y = O[nd][1] * inv0;
            __half* p = outA + row1 * KA + col;
            const uint32_t hp = h2pack(x, y);
            *(uint32_t*)p = hp;
            *(uint32_t*)(p + 1024) = h2pack_lo(x, y, hp);
        }
        {
            const float x = O[nd][2] * inv1, y = O[nd][3] * inv1;
            __half* p = outA + (row1 + 8) * KA + col;
            const uint32_t hp = h2pack(x, y);
            *(uint32_t*)p = hp;
            *(uint32_t*)(p + 1024) = h2pack_lo(x, y, hp);
        }
    }
}

// ---------------------------------------------------------------------------
// Launch
// ---------------------------------------------------------------------------
extern "C" void kernel_launch(void* const* d_in, const int* in_sizes, int n_in,
                              void* d_out, int out_size)
{
    (void)in_sizes; (void)n_in; (void)out_size;
    const float* x      = (const float*)d_in[0];
    const float* W_qkv  = (const float*)d_in[1];
    const float* b_qkv  = (const float*)d_in[2];
    const float* W_proj = (const float*)d_in[3];
    const float* b_proj = (const float*)d_in[4];
    const float* qn_w   = (const float*)d_in[5];
    const float* kn_w   = (const float*)d_in[6];
    float* out = (float*)d_out;

    float *qkv = nullptr;
    __half *A1 = nullptr, *B1 = nullptr, *B2 = nullptr, *A2 = nullptr;
    __half *ksp = nullptr, *vsp = nullptr;
    cudaGetSymbolAddress((void**)&qkv, g_qkv);
    cudaGetSymbolAddress((void**)&A1,  g_A1);
    cudaGetSymbolAddress((void**)&B1,  g_B1);
    cudaGetSymbolAddress((void**)&B2,  g_B2);
    cudaGetSymbolAddress((void**)&A2,  g_A2);
    cudaGetSymbolAddress((void**)&ksp, g_ks);
    cudaGetSymbolAddress((void**)&vsp, g_vs);

    cudaFuncSetAttribute(gemm_mma_kernel, cudaFuncAttributeMaxDynamicSharedMemorySize, G_SMEM);
    cudaFuncSetAttribute(attn_mma_kernel, cudaFuncAttributeMaxDynamicSharedMemorySize, ATT_SMEM);

    // 0) Conversions to fp16 formats
    convX_kernel<<<(TOKENS * CDIM) / 256, 256>>>(x, A1);
    convW_kernel<<<dim3(QKVDIM / 32, CDIM / 32), 256>>>(W_qkv, B1, QKVDIM);
    convW_kernel<<<dim3(CDIM / 32, CDIM / 32), 256>>>(W_proj, B2, CDIM);

    // 1) QKV projection: [8192, 3072] = (A1hi+A1lo) @ B1^T + b_qkv
    gemm_mma_kernel<<<dim3(QKVDIM / BN, TOKENS / BM), 256, G_SMEM>>>(A1, B1, b_qkv, qkv, QKVDIM);

    // 2) Fused RMSNorm (q in place, k) + K/V fp16 store
    rmskv_kernel<<<(TOKENS * 32) / 8, 256>>>(qkv, qn_w, kn_w, ksp, vsp);

    // 3) Attention (tensor cores) -> g_A2 (fp16 hi/lo, proj-ready)
    attn_mma_kernel<<<dim3(SEQ / 128, BATCH * HEADS), 256, ATT_SMEM>>>(qkv, ksp, vsp, A2);

    // 4) Output projection: [8192, 1024] = (A2hi+A2lo) @ B2^T + b_proj
    gemm_mma_kernel<<<dim3(CDIM / BN, TOKENS / BM), 256, G_SMEM>>>(A2, B2, b_proj, out, CDIM);
}

// round 9
// speedup vs baseline: 5.9307x; 1.1081x over previous
#include <cuda_runtime.h>
#include <cuda_fp16.h>
#include <math_constants.h>
#include <cstdint>

// Problem constants
#define BATCH 4
#define SEQ   2048
#define CDIM  1024
#define HEADS 16
#define HDIM  64
#define TOKENS (BATCH * SEQ)         // 8192
#define QKVDIM (3 * CDIM)            // 3072
#define KA    2048                   // A-side split K (hi|lo)
#define KB    1024                   // B-side K (hi only)

// ---------------------------------------------------------------------------
// Scratch (device globals — no allocation allowed)
// ---------------------------------------------------------------------------
__device__ float g_qkv[(size_t)TOKENS * QKVDIM];                    // QKV output fp32
__device__ __align__(256) __half g_A1[(size_t)TOKENS * KA];        // x split      [m, hi|lo]
__device__ __align__(256) __half g_B1[(size_t)QKVDIM * KB];        // W_qkv^T hi   [n, k]
__device__ __align__(256) __half g_B2[(size_t)CDIM * KB];          // W_proj^T hi
__device__ __align__(256) __half g_A2[(size_t)TOKENS * KA];        // attn out split [m, hi|lo]
__device__ __align__(256) __half g_ks[(size_t)BATCH * HEADS * SEQ * 64]; // K hi [bh, n, d]
__device__ __align__(256) __half g_vs[(size_t)BATCH * HEADS * SEQ * 64]; // V hi

// ---------------------------------------------------------------------------
// PTX helpers (portable sm_80+ features only)
// ---------------------------------------------------------------------------
__device__ __forceinline__ uint32_t smem_u32(const void* p) {
    uint32_t a;
    asm("{ .reg .u64 t; cvta.to.shared.u64 t, %1; cvt.u32.u64 %0, t; }" : "=r"(a) : "l"(p));
    return a;
}
__device__ __forceinline__ void cp_async16(uint32_t dst, const void* src) {
    asm volatile("cp.async.cg.shared.global [%0], [%1], 16;" :: "r"(dst), "l"(src));
}
__device__ __forceinline__ void cp_commit() {
    asm volatile("cp.async.commit_group;" ::: "memory");
}
__device__ __forceinline__ void cp_wait0() {
    asm volatile("cp.async.wait_group 0;" ::: "memory");
}
__device__ __forceinline__ void cp_wait1() {
    asm volatile("cp.async.wait_group 1;" ::: "memory");
}
__device__ __forceinline__ void ldsm_x4(uint32_t* r, uint32_t addr) {
    asm volatile("ldmatrix.sync.aligned.m8n8.x4.shared.b16 {%0,%1,%2,%3}, [%4];"
                 : "=r"(r[0]), "=r"(r[1]), "=r"(r[2]), "=r"(r[3]) : "r"(addr));
}
__device__ __forceinline__ void ldsm_x4_t(uint32_t* r, uint32_t addr) {
    asm volatile("ldmatrix.sync.aligned.m8n8.x4.trans.shared.b16 {%0,%1,%2,%3}, [%4];"
                 : "=r"(r[0]), "=r"(r[1]), "=r"(r[2]), "=r"(r[3]) : "r"(addr));
}
__device__ __forceinline__ void mma_fp16(float* c, const uint32_t* a, const uint32_t* b) {
    asm volatile(
        "mma.sync.aligned.m16n8k16.row.col.f32.f16.f16.f32 "
        "{%0,%1,%2,%3}, {%4,%5,%6,%7}, {%8,%9}, {%0,%1,%2,%3};"
        : "+f"(c[0]), "+f"(c[1]), "+f"(c[2]), "+f"(c[3])
        : "r"(a[0]), "r"(a[1]), "r"(a[2]), "r"(a[3]), "r"(b[0]), "r"(b[1]));
}
__device__ __forceinline__ float ex2f(float x) {
    float y; asm("ex2.approx.ftz.f32 %0, %1;" : "=f"(y) : "f"(x)); return y;
}
__device__ __forceinline__ uint32_t h2pack(float a, float b) {
    __half2 h;
    h.x = __float2half_rn(a);
    h.y = __float2half_rn(b);
    return *(uint32_t*)&h;
}
__device__ __forceinline__ uint32_t h2pack_lo(float a, float b, uint32_t hipack) {
    __half2 h = *(__half2*)&hipack;
    return h2pack(a - __half2float(h.x), b - __half2float(h.y));
}

// ---------------------------------------------------------------------------
// Conversion kernels (fp32 -> fp16 hi/lo split)
// ---------------------------------------------------------------------------
__global__ __launch_bounds__(256) void convX_kernel(const float* __restrict__ x,
                                                    __half* __restrict__ A)
{
    const int idx = blockIdx.x * 256 + threadIdx.x;      // over TOKENS*CDIM
    const int m = idx >> 10;
    const int k = idx & 1023;
    const float v = x[idx];
    const __half hi = __float2half_rn(v);
    __half* row = A + (size_t)m * KA;
    row[k]        = hi;
    row[1024 + k] = __float2half_rn(v - __half2float(hi));
}

// Transpose: W [K=1024, N] fp32 -> B [N, 1024] fp16 (hi only)
__global__ __launch_bounds__(256) void convW_kernel(const float* __restrict__ W,
                                                    __half* __restrict__ B, int N)
{
    __shared__ float t[32][33];
    const int n0 = blockIdx.x * 32;
    const int k0 = blockIdx.y * 32;
    const int tx = threadIdx.x & 31;
    const int ty = threadIdx.x >> 5;          // 0..7
    #pragma unroll
    for (int i = 0; i < 4; ++i)
        t[ty + 8 * i][tx] = W[(size_t)(k0 + ty + 8 * i) * N + n0 + tx];
    __syncthreads();
    #pragma unroll
    for (int i = 0; i < 4; ++i) {
        const int n = n0 + ty + 8 * i;
        const int k = k0 + tx;
        B[(size_t)n * KB + k] = __float2half_rn(t[tx][ty + 8 * i]);
    }
}

// ---------------------------------------------------------------------------
// mma.sync fp16 GEMM:  C[M,N] = (A_hi + A_lo) @ B_hi^T + bias
// Stage holds {A_hi, A_lo, B} for ONE k64 range. 16 chunks, 2-stage double
// buffer, one barrier per chunk. CTA 128x128, 8 warps (2x4), warp tile 64x32.
// ---------------------------------------------------------------------------
#define BM 128
#define BN 128
#define BK 64
#define G_REGION (BM * BK * 2)           // 16384 bytes per matrix region
#define G_STAGE_BYTES (3 * G_REGION)     // 49152 (Ahi + Alo + B)
#define G_SMEM (2 * G_STAGE_BYTES)       // 98304
#define NCHUNKG (KB / BK)                // 16

__global__ __launch_bounds__(256, 2) void gemm_mma_kernel(
    const __half* __restrict__ A, const __half* __restrict__ Bm,
    const float* __restrict__ bias, float* __restrict__ C, int N)
{
    extern __shared__ __align__(256) char gsm[];
    const uint32_t base = smem_u32(gsm);

    const int tid  = threadIdx.x;
    const int wid  = tid >> 5;
    const int lane = tid & 31;
    const int wm   = wid >> 2;           // 0..1
    const int wn   = wid & 3;            // 0..3
    const int rowBase = blockIdx.y * BM;
    const int colBase = blockIdx.x * BN;

    float acc[4][4][4] = {};

    const int lrow = tid >> 3;           // 0..31 (x4 via +32)
    const int lch  = tid & 7;

    auto loadStage = [&](int c, int s) {
        const __half* Ah = A + (size_t)rowBase * KA + c * BK;          // hi cols
        const __half* Al = Ah + 1024;                                   // lo cols
        const __half* Bg = Bm + (size_t)colBase * KB + c * BK;
        const uint32_t st = base + s * G_STAGE_BYTES;
        #pragma unroll
        for (int m = 0; m < 4; ++m) {
            const int row = lrow + m * 32;
            const uint32_t soff = row * 128 + ((lch ^ (row & 7)) << 4);
            cp_async16(st + soff,                Ah + (size_t)row * KA + lch * 8);
            cp_async16(st + G_REGION + soff,     Al + (size_t)row * KA + lch * 8);
            cp_async16(st + 2 * G_REGION + soff, Bg + (size_t)row * KB + lch * 8);
        }
        cp_commit();
    };

    loadStage(0, 0);

    for (int c = 0; c < NCHUNKG; ++c) {
        cp_wait0();
        __syncthreads();                 // chunk c visible; compute of c-1 done everywhere
        if (c + 1 < NCHUNKG) loadStage(c + 1, (c + 1) & 1);

        const uint32_t st = base + (c & 1) * G_STAGE_BYTES;
        const uint32_t ahs = st;
        const uint32_t als = st + G_REGION;
        const uint32_t bsb = st + 2 * G_REGION;

        #pragma unroll
        for (int ks = 0; ks < 4; ++ks) {
            const int arow = wm * 64 + (lane & 15);
            const int ach  = ks * 2 + (lane >> 4);
            uint32_t ahfr[4][4], alfr[4][4];
            #pragma unroll
            for (int mt = 0; mt < 4; ++mt) {
                const int row = arow + mt * 16;
                const uint32_t off = row * 128 + ((ach ^ (row & 7)) << 4);
                ldsm_x4(ahfr[mt], ahs + off);
                ldsm_x4(alfr[mt], als + off);
            }
            uint32_t bfr[4][2];
            #pragma unroll
            for (int ntp = 0; ntp < 2; ++ntp) {
                const int row = wn * 32 + ntp * 16 + (lane & 7) + ((lane >> 4) << 3);
                const int ch  = ks * 2 + ((lane >> 3) & 1);
                uint32_t r[4];
                ldsm_x4(r, bsb + row * 128 + ((ch ^ (row & 7)) << 4));
                bfr[2 * ntp][0]     = r[0]; bfr[2 * ntp][1]     = r[1];
                bfr[2 * ntp + 1][0] = r[2]; bfr[2 * ntp + 1][1] = r[3];
            }
            #pragma unroll
            for (int mt = 0; mt < 4; ++mt)
                #pragma unroll
                for (int nt = 0; nt < 4; ++nt) {
                    mma_fp16(acc[mt][nt], ahfr[mt], bfr[nt]);
                    mma_fp16(acc[mt][nt], alfr[mt], bfr[nt]);
                }
        }
        __syncthreads();                 // all reads of stage c done before reload
    }

    // Epilogue
    const int erow = lane >> 2;
    const int ecol = (lane & 3) * 2;
    #pragma unroll
    for (int mt = 0; mt < 4; ++mt) {
        const int rA = rowBase + wm * 64 + mt * 16 + erow;
        #pragma unroll
        for (int nt = 0; nt < 4; ++nt) {
            const int col = colBase + wn * 32 + nt * 8 + ecol;
            const float b0 = bias[col], b1 = bias[col + 1];
            *(float2*)&C[(size_t)rA * N + col] =
                make_float2(acc[mt][nt][0] + b0, acc[mt][nt][1] + b1);
            *(float2*)&C[(size_t)(rA + 8) * N + col] =
                make_float2(acc[mt][nt][2] + b0, acc[mt][nt][3] + b1);
        }
    }
}

// ---------------------------------------------------------------------------
// Fused RMSNorm + K/V fp16 store. One warp per (token, slot).
// ---------------------------------------------------------------------------
__global__ __launch_bounds__(256) void rmskv_kernel(
    float* __restrict__ qkv,
    const float* __restrict__ qn_w, const float* __restrict__ kn_w,
    __half* __restrict__ ks, __half* __restrict__ vs)
{
    const int gwarp = (blockIdx.x * blockDim.x + threadIdx.x) >> 5;
    const int lane  = threadIdx.x & 31;
    const int token = gwarp >> 5;
    const int slot  = gwarp & 31;
    if (token >= TOKENS) return;

    const int h = slot & 15;

    if (slot < 16) {
        float* row = qkv + (size_t)token * QKVDIM + h * HDIM;
        float x0 = row[lane];
        float x1 = row[lane + 32];
        float ss = x0 * x0 + x1 * x1;
        #pragma unroll
        for (int off = 16; off; off >>= 1) ss += __shfl_xor_sync(0xffffffffu, ss, off);
        const float inv = rsqrtf(ss * (1.0f / 64.0f) + 1e-6f);
        row[lane]      = x0 * inv * qn_w[lane];
        row[lane + 32] = x1 * inv * qn_w[lane + 32];
    } else {
        const int b = token >> 11;
        const int n = token & 2047;
        const size_t dstRow = ((size_t)(b * HEADS + h) * SEQ + n) * 64;

        {   // K: rmsnorm + fp16
            const float* row = qkv + (size_t)token * QKVDIM + CDIM + h * HDIM;
            float x0 = row[lane];
            float x1 = row[lane + 32];
            float ss = x0 * x0 + x1 * x1;
            #pragma unroll
            for (int off = 16; off; off >>= 1) ss += __shfl_xor_sync(0xffffffffu, ss, off);
            const float inv = rsqrtf(ss * (1.0f / 64.0f) + 1e-6f);
            ks[dstRow + lane]      = __float2half_rn(x0 * inv * kn_w[lane]);
            ks[dstRow + lane + 32] = __float2half_rn(x1 * inv * kn_w[lane + 32]);
        }
        {   // V: fp16
            const float* row = qkv + (size_t)token * QKVDIM + 2 * CDIM + h * HDIM;
            vs[dstRow + lane]      = __float2half_rn(row[lane]);
            vs[dstRow + lane + 32] = __float2half_rn(row[lane + 32]);
        }
    }
}

// ---------------------------------------------------------------------------
// FlashAttention-2 style mma.sync fp16 attention. Bc=128, 3-stage pipeline.
// Q carried as 2-term fp16 (hi+lo); K, V, and P as fp16 hi only.
// CTA = 128 q-rows x (b,h); 8 warps x 16 rows. K/V tiles: 128 rows x 128B.
// ---------------------------------------------------------------------------
#define ATT_NT (SEQ / 128)            // 16 key tiles
#define ATT_TILE_B 16384              // one matrix tile: 128 rows * 128B
#define ATT_BUF_B  32768              // K + V per stage
#define ATT_STAGES 3
#define ATT_SMEM   (ATT_STAGES * ATT_BUF_B)   // 98304

__global__ __launch_bounds__(256) void attn_mma_kernel(
    const float* __restrict__ qkv,
    const __half* __restrict__ ks, const __half* __restrict__ vs,
    __half* __restrict__ outA)
{
    extern __shared__ __align__(256) char sm[];
    const uint32_t smBase = smem_u32(sm);

    const int tid  = threadIdx.x;
    const int wq   = tid >> 5;
    const int lane = tid & 31;

    const int bh = blockIdx.y;
    const int b  = bh >> 4;
    const int h  = bh & 15;
    const int qBase = blockIdx.x * 128;

    // ---- Q fragments (hi/lo fp16), scale folded: 0.125 * log2(e) ----
    const float SC = 0.125f * 1.44269504088896340736f;
    uint32_t qh[4][4], ql[4][4];
    {
        const float* qg = qkv + ((size_t)(b * SEQ + qBase + wq * 16)) * QKVDIM + h * HDIM;
        const int rr = lane >> 2;
        const int cb = (lane & 3) * 2;
        #pragma unroll
        for (int kd = 0; kd < 4; ++kd) {
            const int d0 = kd * 16;
            float2 v0 = *(const float2*)&qg[(size_t)rr * QKVDIM + d0 + cb];
            float2 v1 = *(const float2*)&qg[(size_t)(rr + 8) * QKVDIM + d0 + cb];
            float2 v2 = *(const float2*)&qg[(size_t)rr * QKVDIM + d0 + cb + 8];
            float2 v3 = *(const float2*)&qg[(size_t)(rr + 8) * QKVDIM + d0 + cb + 8];
            v0.x *= SC; v0.y *= SC; v1.x *= SC; v1.y *= SC;
            v2.x *= SC; v2.y *= SC; v3.x *= SC; v3.y *= SC;
            qh[kd][0] = h2pack(v0.x, v0.y); ql[kd][0] = h2pack_lo(v0.x, v0.y, qh[kd][0]);
            qh[kd][1] = h2pack(v1.x, v1.y); ql[kd][1] = h2pack_lo(v1.x, v1.y, qh[kd][1]);
            qh[kd][2] = h2pack(v2.x, v2.y); ql[kd][2] = h2pack_lo(v2.x, v2.y, qh[kd][2]);
            qh[kd][3] = h2pack(v3.x, v3.y); ql[kd][3] = h2pack_lo(v3.x, v3.y, qh[kd][3]);
        }
    }

    // ---- cp.async tile loader: 128 keys, K + V hi (128B rows, XOR swizzle) ----
    auto loadTile = [&](int kt, int st) {
        const __half* gk = ks + ((size_t)bh * SEQ + kt * 128) * 64;
        const __half* gv = vs + ((size_t)bh * SEQ + kt * 128) * 64;
        const uint32_t kb = smBase + st * ATT_BUF_B;
        const uint32_t vb = kb + ATT_TILE_B;
        #pragma unroll
        for (int m = 0; m < 4; ++m) {
            const int id = tid + m * 256;           // 0..1023
            const int c = id >> 3, j = id & 7;
            const uint32_t soff = c * 128 + ((j ^ (c & 7)) << 4);
            cp_async16(kb + soff, gk + (size_t)c * 64 + j * 8);
            cp_async16(vb + soff, gv + (size_t)c * 64 + j * 8);
        }
        cp_commit();
    };

    float m0 = -CUDART_INF_F, m1 = -CUDART_INF_F, l0 = 0.0f, l1 = 0.0f;
    float O[8][4] = {};

    loadTile(0, 0);
    loadTile(1, 1);

    for (int kt = 0; kt < ATT_NT; ++kt) {
        const int st = kt % ATT_STAGES;
        if (kt + 2 < ATT_NT) cp_wait1(); else cp_wait0();
        __syncthreads();
        if (kt + 2 < ATT_NT) loadTile(kt + 2, (kt + 2) % ATT_STAGES);

        const uint32_t Kb = smBase + st * ATT_BUF_B;
        const uint32_t Vb = Kb + ATT_TILE_B;

        // ---- S = (Qh+Ql) K^T, 128 keys ----
        float S[16][4] = {};
        #pragma unroll
        for (int kd = 0; kd < 4; ++kd) {
            #pragma unroll
            for (int t = 0; t < 8; ++t) {
                const int row = 16 * t + (lane & 7) + 8 * ((lane >> 4) & 1);
                const int j = kd * 2 + ((lane >> 3) & 1);
                uint32_t r[4];
                ldsm_x4(r, Kb + row * 128 + ((j ^ (row & 7)) << 4));
                mma_fp16(S[2 * t],     qh[kd], r);
                mma_fp16(S[2 * t],     ql[kd], r);
                mma_fp16(S[2 * t + 1], qh[kd], r + 2);
                mma_fp16(S[2 * t + 1], ql[kd], r + 2);
            }
        }

        // ---- Online softmax (base 2) ----
        float mt0 = -CUDART_INF_F, mt1 = -CUDART_INF_F;
        #pragma unroll
        for (int nc = 0; nc < 16; ++nc) {
            mt0 = fmaxf(mt0, fmaxf(S[nc][0], S[nc][1]));
            mt1 = fmaxf(mt1, fmaxf(S[nc][2], S[nc][3]));
        }
        mt0 = fmaxf(mt0, __shfl_xor_sync(0xffffffffu, mt0, 1));
        mt0 = fmaxf(mt0, __shfl_xor_sync(0xffffffffu, mt0, 2));
        mt1 = fmaxf(mt1, __shfl_xor_sync(0xffffffffu, mt1, 1));
        mt1 = fmaxf(mt1, __shfl_xor_sync(0xffffffffu, mt1, 2));
        const float mn0 = fmaxf(m0, mt0);
        const float mn1 = fmaxf(m1, mt1);
        const float c0 = ex2f(m0 - mn0);
        const float c1 = ex2f(m1 - mn1);
        m0 = mn0; m1 = mn1;
        float rs0 = 0.0f, rs1 = 0.0f;
        #pragma unroll
        for (int nc = 0; nc < 16; ++nc) {
            S[nc][0] = ex2f(S[nc][0] - mn0); rs0 += S[nc][0];
            S[nc][1] = ex2f(S[nc][1] - mn0); rs0 += S[nc][1];
            S[nc][2] = ex2f(S[nc][2] - mn1); rs1 += S[nc][2];
            S[nc][3] = ex2f(S[nc][3] - mn1); rs1 += S[nc][3];
        }
        rs0 += __shfl_xor_sync(0xffffffffu, rs0, 1);
        rs0 += __shfl_xor_sync(0xffffffffu, rs0, 2);
        rs1 += __shfl_xor_sync(0xffffffffu, rs1, 1);
        rs1 += __shfl_xor_sync(0xffffffffu, rs1, 2);
        l0 = l0 * c0 + rs0;
        l1 = l1 * c1 + rs1;
        #pragma unroll
        for (int nd = 0; nd < 8; ++nd) {
            O[nd][0] *= c0; O[nd][1] *= c0; O[nd][2] *= c1; O[nd][3] *= c1;
        }

        // ---- O += P V (P fp16 hi only), 8 k16 chunks ----
        #pragma unroll
        for (int kc = 0; kc < 8; ++kc) {
            uint32_t ph[4];
            {
                const float* s0 = S[2 * kc];
                const float* s1 = S[2 * kc + 1];
                ph[0] = h2pack(s0[0], s0[1]);
                ph[1] = h2pack(s0[2], s0[3]);
                ph[2] = h2pack(s1[0], s1[1]);
                ph[3] = h2pack(s1[2], s1[3]);
            }
            #pragma unroll
            for (int t = 0; t < 4; ++t) {
                const int row = kc * 16 + (lane & 7) + 8 * ((lane >> 3) & 1);
                const int j = 2 * t + ((lane >> 4) & 1);
                uint32_t r[4];
                ldsm_x4_t(r, Vb + row * 128 + ((j ^ (row & 7)) << 4));
                mma_fp16(O[2 * t],     ph, r);
                mma_fp16(O[2 * t + 1], ph, r + 2);
            }
        }
    }

    // ---- Epilogue: normalize, write fp16 hi/lo split rows to outA ----
    const float inv0 = 1.0f / l0;
    const float inv1 = 1.0f / l1;
    const size_t row1 = (size_t)b * SEQ + qBase + wq * 16 + (lane >> 2);
    const int colBase = h * HDIM + (lane & 3) * 2;
    #pragma unroll
    for (int nd = 0; nd < 8; ++nd) {
        const int col = colBase + nd * 8;
        {
            const float x = O[nd][0] * inv0, y = O[nd][1] * inv0;
            __half* p = outA + row1 * KA + col;
            const uint32_t hp = h2pack(x, y);
            *(uint32_t*)p = hp;
            *(uint32_t*)(p + 1024) = h2pack_lo(x, y, hp);
        }
        {
            const float x = O[nd][2] * inv1, y = O[nd][3] * inv1;
            __half* p = outA + (row1 + 8) * KA + col;
            const uint32_t hp = h2pack(x, y);
            *(uint32_t*)p = hp;
            *(uint32_t*)(p + 1024) = h2pack_lo(x, y, hp);
        }
    }
}

// ---------------------------------------------------------------------------
// Launch
// ---------------------------------------------------------------------------
extern "C" void kernel_launch(void* const* d_in, const int* in_sizes, int n_in,
                              void* d_out, int out_size)
{
    (void)in_sizes; (void)n_in; (void)out_size;
    const float* x      = (const float*)d_in[0];
    const float* W_qkv  = (const float*)d_in[1];
    const float* b_qkv  = (const float*)d_in[2];
    const float* W_proj = (const float*)d_in[3];
    const float* b_proj = (const float*)d_in[4];
    const float* qn_w   = (const float*)d_in[5];
    const float* kn_w   = (const float*)d_in[6];
    float* out = (float*)d_out;

    float *qkv = nullptr;
    __half *A1 = nullptr, *B1 = nullptr, *B2 = nullptr, *A2 = nullptr;
    __half *ksp = nullptr, *vsp = nullptr;
    cudaGetSymbolAddress((void**)&qkv, g_qkv);
    cudaGetSymbolAddress((void**)&A1,  g_A1);
    cudaGetSymbolAddress((void**)&B1,  g_B1);
    cudaGetSymbolAddress((void**)&B2,  g_B2);
    cudaGetSymbolAddress((void**)&A2,  g_A2);
    cudaGetSymbolAddress((void**)&ksp, g_ks);
    cudaGetSymbolAddress((void**)&vsp, g_vs);

    cudaFuncSetAttribute(gemm_mma_kernel, cudaFuncAttributeMaxDynamicSharedMemorySize, G_SMEM);
    cudaFuncSetAttribute(attn_mma_kernel, cudaFuncAttributeMaxDynamicSharedMemorySize, ATT_SMEM);

    // 0) Conversions to fp16 formats
    convX_kernel<<<(TOKENS * CDIM) / 256, 256>>>(x, A1);
    convW_kernel<<<dim3(QKVDIM / 32, CDIM / 32), 256>>>(W_qkv, B1, QKVDIM);
    convW_kernel<<<dim3(CDIM / 32, CDIM / 32), 256>>>(W_proj, B2, CDIM);

    // 1) QKV projection: [8192, 3072] = (A1hi+A1lo) @ B1^T + b_qkv
    gemm_mma_kernel<<<dim3(QKVDIM / BN, TOKENS / BM), 256, G_SMEM>>>(A1, B1, b_qkv, qkv, QKVDIM);

    // 2) Fused RMSNorm (q in place, k) + K/V fp16 store
    rmskv_kernel<<<(TOKENS * 32) / 8, 256>>>(qkv, qn_w, kn_w, ksp, vsp);

    // 3) Attention (tensor cores) -> g_A2 (fp16 hi/lo, proj-ready)
    attn_mma_kernel<<<dim3(SEQ / 128, BATCH * HEADS), 256, ATT_SMEM>>>(qkv, ksp, vsp, A2);

    // 4) Output projection: [8192, 1024] = (A2hi+A2lo) @ B2^T + b_proj
    gemm_mma_kernel<<<dim3(CDIM / BN, TOKENS / BM), 256, G_SMEM>>>(A2, B2, b_proj, out, CDIM);
}

// round 10
// speedup vs baseline: 5.9870x; 1.0095x over previous
#include <cuda_runtime.h>
#include <cuda_fp16.h>
#include <math_constants.h>
#include <cstdint>

// Problem constants
#define BATCH 4
#define SEQ   2048
#define CDIM  1024
#define HEADS 16
#define HDIM  64
#define TOKENS (BATCH * SEQ)         // 8192
#define QKVDIM (3 * CDIM)            // 3072
#define KA    2048                   // A-side split K (hi|lo)
#define KB    1024                   // B-side K (hi only)

// ---------------------------------------------------------------------------
// Scratch (device globals — no allocation allowed)
// ---------------------------------------------------------------------------
__device__ float g_qkv[(size_t)TOKENS * QKVDIM];                    // QKV output fp32
__device__ __align__(256) __half g_A1[(size_t)TOKENS * KA];        // x split      [m, hi|lo]
__device__ __align__(256) __half g_B1[(size_t)QKVDIM * KB];        // W_qkv^T hi   [n, k]
__device__ __align__(256) __half g_B2[(size_t)CDIM * KB];          // W_proj^T hi
__device__ __align__(256) __half g_A2[(size_t)TOKENS * KA];        // attn out split [m, hi|lo]
__device__ __align__(256) __half g_ks[(size_t)BATCH * HEADS * SEQ * 64]; // K hi [bh, n, d]
__device__ __align__(256) __half g_vs[(size_t)BATCH * HEADS * SEQ * 64]; // V hi

// ---------------------------------------------------------------------------
// PTX helpers (portable sm_80+ features only)
// ---------------------------------------------------------------------------
__device__ __forceinline__ uint32_t smem_u32(const void* p) {
    uint32_t a;
    asm("{ .reg .u64 t; cvta.to.shared.u64 t, %1; cvt.u32.u64 %0, t; }" : "=r"(a) : "l"(p));
    return a;
}
__device__ __forceinline__ void cp_async16(uint32_t dst, const void* src) {
    asm volatile("cp.async.cg.shared.global [%0], [%1], 16;" :: "r"(dst), "l"(src));
}
__device__ __forceinline__ void cp_commit() {
    asm volatile("cp.async.commit_group;" ::: "memory");
}
__device__ __forceinline__ void cp_wait0() {
    asm volatile("cp.async.wait_group 0;" ::: "memory");
}
__device__ __forceinline__ void cp_wait1() {
    asm volatile("cp.async.wait_group 1;" ::: "memory");
}
__device__ __forceinline__ void cp_wait2() {
    asm volatile("cp.async.wait_group 2;" ::: "memory");
}
__device__ __forceinline__ void ldsm_x4(uint32_t* r, uint32_t addr) {
    asm volatile("ldmatrix.sync.aligned.m8n8.x4.shared.b16 {%0,%1,%2,%3}, [%4];"
                 : "=r"(r[0]), "=r"(r[1]), "=r"(r[2]), "=r"(r[3]) : "r"(addr));
}
__device__ __forceinline__ void ldsm_x4_t(uint32_t* r, uint32_t addr) {
    asm volatile("ldmatrix.sync.aligned.m8n8.x4.trans.shared.b16 {%0,%1,%2,%3}, [%4];"
                 : "=r"(r[0]), "=r"(r[1]), "=r"(r[2]), "=r"(r[3]) : "r"(addr));
}
__device__ __forceinline__ void mma_fp16(float* c, const uint32_t* a, const uint32_t* b) {
    asm volatile(
        "mma.sync.aligned.m16n8k16.row.col.f32.f16.f16.f32 "
        "{%0,%1,%2,%3}, {%4,%5,%6,%7}, {%8,%9}, {%0,%1,%2,%3};"
        : "+f"(c[0]), "+f"(c[1]), "+f"(c[2]), "+f"(c[3])
        : "r"(a[0]), "r"(a[1]), "r"(a[2]), "r"(a[3]), "r"(b[0]), "r"(b[1]));
}
__device__ __forceinline__ float ex2f(float x) {
    float y; asm("ex2.approx.ftz.f32 %0, %1;" : "=f"(y) : "f"(x)); return y;
}
__device__ __forceinline__ uint32_t h2pack(float a, float b) {
    __half2 h;
    h.x = __float2half_rn(a);
    h.y = __float2half_rn(b);
    return *(uint32_t*)&h;
}
__device__ __forceinline__ uint32_t h2pack_lo(float a, float b, uint32_t hipack) {
    __half2 h = *(__half2*)&hipack;
    return h2pack(a - __half2float(h.x), b - __half2float(h.y));
}

// ---------------------------------------------------------------------------
// Conversion kernels (fp32 -> fp16 hi/lo split)
// ---------------------------------------------------------------------------
__global__ __launch_bounds__(256) void convX_kernel(const float* __restrict__ x,
                                                    __half* __restrict__ A)
{
    const int idx = blockIdx.x * 256 + threadIdx.x;      // over TOKENS*CDIM
    const int m = idx >> 10;
    const int k = idx & 1023;
    const float v = x[idx];
    const __half hi = __float2half_rn(v);
    __half* row = A + (size_t)m * KA;
    row[k]        = hi;
    row[1024 + k] = __float2half_rn(v - __half2float(hi));
}

// Transpose: W [K=1024, N] fp32 -> B [N, 1024] fp16 (hi only)
__global__ __launch_bounds__(256) void convW_kernel(const float* __restrict__ W,
                                                    __half* __restrict__ B, int N)
{
    __shared__ float t[32][33];
    const int n0 = blockIdx.x * 32;
    const int k0 = blockIdx.y * 32;
    const int tx = threadIdx.x & 31;
    const int ty = threadIdx.x >> 5;          // 0..7
    #pragma unroll
    for (int i = 0; i < 4; ++i)
        t[ty + 8 * i][tx] = W[(size_t)(k0 + ty + 8 * i) * N + n0 + tx];
    __syncthreads();
    #pragma unroll
    for (int i = 0; i < 4; ++i) {
        const int n = n0 + ty + 8 * i;
        const int k = k0 + tx;
        B[(size_t)n * KB + k] = __float2half_rn(t[tx][ty + 8 * i]);
    }
}

// ---------------------------------------------------------------------------
// mma.sync fp16 GEMM:  C[M,N] = (A_hi + A_lo) @ B_hi^T + bias
// Stage holds {A_hi, A_lo, B} for ONE k64 range. 16 chunks, 2-stage double
// buffer, one barrier per chunk. CTA 128x128, 8 warps (2x4), warp tile 64x32.
// ---------------------------------------------------------------------------
#define BM 128
#define BN 128
#define BK 64
#define G_REGION (BM * BK * 2)           // 16384 bytes per matrix region
#define G_STAGE_BYTES (3 * G_REGION)     // 49152 (Ahi + Alo + B)
#define G_SMEM (2 * G_STAGE_BYTES)       // 98304
#define NCHUNKG (KB / BK)                // 16

__global__ __launch_bounds__(256, 2) void gemm_mma_kernel(
    const __half* __restrict__ A, const __half* __restrict__ Bm,
    const float* __restrict__ bias, float* __restrict__ C, int N)
{
    extern __shared__ __align__(256) char gsm[];
    const uint32_t base = smem_u32(gsm);

    const int tid  = threadIdx.x;
    const int wid  = tid >> 5;
    const int lane = tid & 31;
    const int wm   = wid >> 2;           // 0..1
    const int wn   = wid & 3;            // 0..3
    const int rowBase = blockIdx.y * BM;
    const int colBase = blockIdx.x * BN;

    float acc[4][4][4] = {};

    const int lrow = tid >> 3;           // 0..31 (x4 via +32)
    const int lch  = tid & 7;

    auto loadStage = [&](int c, int s) {
        const __half* Ah = A + (size_t)rowBase * KA + c * BK;          // hi cols
        const __half* Al = Ah + 1024;                                   // lo cols
        const __half* Bg = Bm + (size_t)colBase * KB + c * BK;
        const uint32_t st = base + s * G_STAGE_BYTES;
        #pragma unroll
        for (int m = 0; m < 4; ++m) {
            const int row = lrow + m * 32;
            const uint32_t soff = row * 128 + ((lch ^ (row & 7)) << 4);
            cp_async16(st + soff,                Ah + (size_t)row * KA + lch * 8);
            cp_async16(st + G_REGION + soff,     Al + (size_t)row * KA + lch * 8);
            cp_async16(st + 2 * G_REGION + soff, Bg + (size_t)row * KB + lch * 8);
        }
        cp_commit();
    };

    loadStage(0, 0);

    for (int c = 0; c < NCHUNKG; ++c) {
        cp_wait0();
        __syncthreads();                 // chunk c visible; compute of c-1 done everywhere
        if (c + 1 < NCHUNKG) loadStage(c + 1, (c + 1) & 1);

        const uint32_t st = base + (c & 1) * G_STAGE_BYTES;
        const uint32_t ahs = st;
        const uint32_t als = st + G_REGION;
        const uint32_t bsb = st + 2 * G_REGION;

        #pragma unroll
        for (int ks = 0; ks < 4; ++ks) {
            const int arow = wm * 64 + (lane & 15);
            const int ach  = ks * 2 + (lane >> 4);
            uint32_t ahfr[4][4], alfr[4][4];
            #pragma unroll
            for (int mt = 0; mt < 4; ++mt) {
                const int row = arow + mt * 16;
                const uint32_t off = row * 128 + ((ach ^ (row & 7)) << 4);
                ldsm_x4(ahfr[mt], ahs + off);
                ldsm_x4(alfr[mt], als + off);
            }
            uint32_t bfr[4][2];
            #pragma unroll
            for (int ntp = 0; ntp < 2; ++ntp) {
                const int row = wn * 32 + ntp * 16 + (lane & 7) + ((lane >> 4) << 3);
                const int ch  = ks * 2 + ((lane >> 3) & 1);
                uint32_t r[4];
                ldsm_x4(r, bsb + row * 128 + ((ch ^ (row & 7)) << 4));
                bfr[2 * ntp][0]     = r[0]; bfr[2 * ntp][1]     = r[1];
                bfr[2 * ntp + 1][0] = r[2]; bfr[2 * ntp + 1][1] = r[3];
            }
            #pragma unroll
            for (int mt = 0; mt < 4; ++mt)
                #pragma unroll
                for (int nt = 0; nt < 4; ++nt) {
                    mma_fp16(acc[mt][nt], ahfr[mt], bfr[nt]);
                    mma_fp16(acc[mt][nt], alfr[mt], bfr[nt]);
                }
        }
        __syncthreads();                 // all reads of stage c done before reload
    }

    // Epilogue
    const int erow = lane >> 2;
    const int ecol = (lane & 3) * 2;
    #pragma unroll
    for (int mt = 0; mt < 4; ++mt) {
        const int rA = rowBase + wm * 64 + mt * 16 + erow;
        #pragma unroll
        for (int nt = 0; nt < 4; ++nt) {
            const int col = colBase + wn * 32 + nt * 8 + ecol;
            const float b0 = bias[col], b1 = bias[col + 1];
            *(float2*)&C[(size_t)rA * N + col] =
                make_float2(acc[mt][nt][0] + b0, acc[mt][nt][1] + b1);
            *(float2*)&C[(size_t)(rA + 8) * N + col] =
                make_float2(acc[mt][nt][2] + b0, acc[mt][nt][3] + b1);
        }
    }
}

// ---------------------------------------------------------------------------
// Fused RMSNorm + K/V fp16 store. One warp per (token, slot).
// ---------------------------------------------------------------------------
__global__ __launch_bounds__(256) void rmskv_kernel(
    float* __restrict__ qkv,
    const float* __restrict__ qn_w, const float* __restrict__ kn_w,
    __half* __restrict__ ks, __half* __restrict__ vs)
{
    const int gwarp = (blockIdx.x * blockDim.x + threadIdx.x) >> 5;
    const int lane  = threadIdx.x & 31;
    const int token = gwarp >> 5;
    const int slot  = gwarp & 31;
    if (token >= TOKENS) return;

    const int h = slot & 15;

    if (slot < 16) {
        float* row = qkv + (size_t)token * QKVDIM + h * HDIM;
        float x0 = row[lane];
        float x1 = row[lane + 32];
        float ss = x0 * x0 + x1 * x1;
        #pragma unroll
        for (int off = 16; off; off >>= 1) ss += __shfl_xor_sync(0xffffffffu, ss, off);
        const float inv = rsqrtf(ss * (1.0f / 64.0f) + 1e-6f);
        row[lane]      = x0 * inv * qn_w[lane];
        row[lane + 32] = x1 * inv * qn_w[lane + 32];
    } else {
        const int b = token >> 11;
        const int n = token & 2047;
        const size_t dstRow = ((size_t)(b * HEADS + h) * SEQ + n) * 64;

        {   // K: rmsnorm + fp16
            const float* row = qkv + (size_t)token * QKVDIM + CDIM + h * HDIM;
            float x0 = row[lane];
            float x1 = row[lane + 32];
            float ss = x0 * x0 + x1 * x1;
            #pragma unroll
            for (int off = 16; off; off >>= 1) ss += __shfl_xor_sync(0xffffffffu, ss, off);
            const float inv = rsqrtf(ss * (1.0f / 64.0f) + 1e-6f);
            ks[dstRow + lane]      = __float2half_rn(x0 * inv * kn_w[lane]);
            ks[dstRow + lane + 32] = __float2half_rn(x1 * inv * kn_w[lane + 32]);
        }
        {   // V: fp16
            const float* row = qkv + (size_t)token * QKVDIM + 2 * CDIM + h * HDIM;
            vs[dstRow + lane]      = __float2half_rn(row[lane]);
            vs[dstRow + lane + 32] = __float2half_rn(row[lane + 32]);
        }
    }
}

// ---------------------------------------------------------------------------
// FlashAttention-2 style mma.sync fp16 attention. Bc=64, 4-stage pipeline,
// 2 CTAs/SM (reg-capped). Q carried as 2-term fp16 (hi+lo); K, V, P hi only.
// CTA = 128 q-rows x (b,h); 8 warps x 16 rows. K/V tiles: 64 rows x 128B.
// ---------------------------------------------------------------------------
#define ATT_NT (SEQ / 64)             // 32 key tiles
#define ATT_TILE_B 8192               // one matrix tile: 64 rows * 128B
#define ATT_BUF_B  16384              // K + V per stage
#define ATT_STAGES 4
#define ATT_SMEM   (ATT_STAGES * ATT_BUF_B)   // 65536

__global__ __launch_bounds__(256, 2) void attn_mma_kernel(
    const float* __restrict__ qkv,
    const __half* __restrict__ ks, const __half* __restrict__ vs,
    __half* __restrict__ outA)
{
    extern __shared__ __align__(256) char sm[];
    const uint32_t smBase = smem_u32(sm);

    const int tid  = threadIdx.x;
    const int wq   = tid >> 5;
    const int lane = tid & 31;

    const int bh = blockIdx.y;
    const int b  = bh >> 4;
    const int h  = bh & 15;
    const int qBase = blockIdx.x * 128;

    // ---- Q fragments (hi/lo fp16), scale folded: 0.125 * log2(e) ----
    const float SC = 0.125f * 1.44269504088896340736f;
    uint32_t qh[4][4], ql[4][4];
    {
        const float* qg = qkv + ((size_t)(b * SEQ + qBase + wq * 16)) * QKVDIM + h * HDIM;
        const int rr = lane >> 2;
        const int cb = (lane & 3) * 2;
        #pragma unroll
        for (int kd = 0; kd < 4; ++kd) {
            const int d0 = kd * 16;
            float2 v0 = *(const float2*)&qg[(size_t)rr * QKVDIM + d0 + cb];
            float2 v1 = *(const float2*)&qg[(size_t)(rr + 8) * QKVDIM + d0 + cb];
            float2 v2 = *(const float2*)&qg[(size_t)rr * QKVDIM + d0 + cb + 8];
            float2 v3 = *(const float2*)&qg[(size_t)(rr + 8) * QKVDIM + d0 + cb + 8];
            v0.x *= SC; v0.y *= SC; v1.x *= SC; v1.y *= SC;
            v2.x *= SC; v2.y *= SC; v3.x *= SC; v3.y *= SC;
            qh[kd][0] = h2pack(v0.x, v0.y); ql[kd][0] = h2pack_lo(v0.x, v0.y, qh[kd][0]);
            qh[kd][1] = h2pack(v1.x, v1.y); ql[kd][1] = h2pack_lo(v1.x, v1.y, qh[kd][1]);
            qh[kd][2] = h2pack(v2.x, v2.y); ql[kd][2] = h2pack_lo(v2.x, v2.y, qh[kd][2]);
            qh[kd][3] = h2pack(v3.x, v3.y); ql[kd][3] = h2pack_lo(v3.x, v3.y, qh[kd][3]);
        }
    }

    // ---- cp.async tile loader: 64 keys, K + V hi (128B rows, XOR swizzle) ----
    auto loadTile = [&](int kt, int st) {
        const __half* gk = ks + ((size_t)bh * SEQ + kt * 64) * 64;
        const __half* gv = vs + ((size_t)bh * SEQ + kt * 64) * 64;
        const uint32_t kb = smBase + st * ATT_BUF_B;
        const uint32_t vb = kb + ATT_TILE_B;
        #pragma unroll
        for (int m = 0; m < 2; ++m) {
            const int id = tid + m * 256;           // 0..511
            const int c = id >> 3, j = id & 7;
            const uint32_t soff = c * 128 + ((j ^ (c & 7)) << 4);
            cp_async16(kb + soff, gk + (size_t)c * 64 + j * 8);
            cp_async16(vb + soff, gv + (size_t)c * 64 + j * 8);
        }
        cp_commit();
    };

    float m0 = -CUDART_INF_F, m1 = -CUDART_INF_F, l0 = 0.0f, l1 = 0.0f;
    float O[8][4] = {};

    loadTile(0, 0);
    loadTile(1, 1);
    loadTile(2, 2);

    for (int kt = 0; kt < ATT_NT; ++kt) {
        const int st = kt & 3;
        if (kt + 2 < ATT_NT)      cp_wait2();
        else if (kt + 1 < ATT_NT) cp_wait1();
        else                      cp_wait0();
        __syncthreads();
        if (kt + 3 < ATT_NT) loadTile(kt + 3, (kt + 3) & 3);

        const uint32_t Kb = smBase + st * ATT_BUF_B;
        const uint32_t Vb = Kb + ATT_TILE_B;

        // ---- S = (Qh+Ql) K^T, 64 keys ----
        float S[8][4] = {};
        #pragma unroll
        for (int kd = 0; kd < 4; ++kd) {
            #pragma unroll
            for (int t = 0; t < 4; ++t) {
                const int row = 16 * t + (lane & 7) + 8 * ((lane >> 4) & 1);
                const int j = kd * 2 + ((lane >> 3) & 1);
                uint32_t r[4];
                ldsm_x4(r, Kb + row * 128 + ((j ^ (row & 7)) << 4));
                mma_fp16(S[2 * t],     qh[kd], r);
                mma_fp16(S[2 * t],     ql[kd], r);
                mma_fp16(S[2 * t + 1], qh[kd], r + 2);
                mma_fp16(S[2 * t + 1], ql[kd], r + 2);
            }
        }

        // ---- Online softmax (base 2) ----
        float mt0 = -CUDART_INF_F, mt1 = -CUDART_INF_F;
        #pragma unroll
        for (int nc = 0; nc < 8; ++nc) {
            mt0 = fmaxf(mt0, fmaxf(S[nc][0], S[nc][1]));
            mt1 = fmaxf(mt1, fmaxf(S[nc][2], S[nc][3]));
        }
        mt0 = fmaxf(mt0, __shfl_xor_sync(0xffffffffu, mt0, 1));
        mt0 = fmaxf(mt0, __shfl_xor_sync(0xffffffffu, mt0, 2));
        mt1 = fmaxf(mt1, __shfl_xor_sync(0xffffffffu, mt1, 1));
        mt1 = fmaxf(mt1, __shfl_xor_sync(0xffffffffu, mt1, 2));
        const float mn0 = fmaxf(m0, mt0);
        const float mn1 = fmaxf(m1, mt1);
        const float c0 = ex2f(m0 - mn0);
        const float c1 = ex2f(m1 - mn1);
        m0 = mn0; m1 = mn1;
        float rs0 = 0.0f, rs1 = 0.0f;
        #pragma unroll
        for (int nc = 0; nc < 8; ++nc) {
            S[nc][0] = ex2f(S[nc][0] - mn0); rs0 += S[nc][0];
            S[nc][1] = ex2f(S[nc][1] - mn0); rs0 += S[nc][1];
            S[nc][2] = ex2f(S[nc][2] - mn1); rs1 += S[nc][2];
            S[nc][3] = ex2f(S[nc][3] - mn1); rs1 += S[nc][3];
        }
        rs0 += __shfl_xor_sync(0xffffffffu, rs0, 1);
        rs0 += __shfl_xor_sync(0xffffffffu, rs0, 2);
        rs1 += __shfl_xor_sync(0xffffffffu, rs1, 1);
        rs1 += __shfl_xor_sync(0xffffffffu, rs1, 2);
        l0 = l0 * c0 + rs0;
        l1 = l1 * c1 + rs1;
        #pragma unroll
        for (int nd = 0; nd < 8; ++nd) {
            O[nd][0] *= c0; O[nd][1] *= c0; O[nd][2] *= c1; O[nd][3] *= c1;
        }

        // ---- O += P V (P fp16 hi only), 4 k16 chunks ----
        #pragma unroll
        for (int kc = 0; kc < 4; ++kc) {
            uint32_t ph[4];
            {
                const float* s0 = S[2 * kc];
                const float* s1 = S[2 * kc + 1];
                ph[0] = h2pack(s0[0], s0[1]);
                ph[1] = h2pack(s0[2], s0[3]);
                ph[2] = h2pack(s1[0], s1[1]);
                ph[3] = h2pack(s1[2], s1[3]);
            }
            #pragma unroll
            for (int t = 0; t < 4; ++t) {
                const int row = kc * 16 + (lane & 7) + 8 * ((lane >> 3) & 1);
                const int j = 2 * t + ((lane >> 4) & 1);
                uint32_t r[4];
                ldsm_x4_t(r, Vb + row * 128 + ((j ^ (row & 7)) << 4));
                mma_fp16(O[2 * t],     ph, r);
                mma_fp16(O[2 * t + 1], ph, r + 2);
            }
        }
    }

    // ---- Epilogue: normalize, write fp16 hi/lo split rows to outA ----
    const float inv0 = 1.0f / l0;
    const float inv1 = 1.0f / l1;
    const size_t row1 = (size_t)b * SEQ + qBase + wq * 16 + (lane >> 2);
    const int colBase = h * HDIM + (lane & 3) * 2;
    #pragma unroll
    for (int nd = 0; nd < 8; ++nd) {
        const int col = colBase + nd * 8;
        {
            const float x = O[nd][0] * inv0, y = O[nd][1] * inv0;
            __half* p = outA + row1 * KA + col;
            const uint32_t hp = h2pack(x, y);
            *(uint32_t*)p = hp;
            *(uint32_t*)(p + 1024) = h2pack_lo(x, y, hp);
        }
        {
            const float x = O[nd][2] * inv1, y = O[nd][3] * inv1;
            __half* p = outA + (row1 + 8) * KA + col;
            const uint32_t hp = h2pack(x, y);
            *(uint32_t*)p = hp;
            *(uint32_t*)(p + 1024) = h2pack_lo(x, y, hp);
        }
    }
}

// ---------------------------------------------------------------------------
// Launch
// ---------------------------------------------------------------------------
extern "C" void kernel_launch(void* const* d_in, const int* in_sizes, int n_in,
                              void* d_out, int out_size)
{
    (void)in_sizes; (void)n_in; (void)out_size;
    const float* x      = (const float*)d_in[0];
    const float* W_qkv  = (const float*)d_in[1];
    const float* b_qkv  = (const float*)d_in[2];
    const float* W_proj = (const float*)d_in[3];
    const float* b_proj = (const float*)d_in[4];
    const float* qn_w   = (const float*)d_in[5];
    const float* kn_w   = (const float*)d_in[6];
    float* out = (float*)d_out;

    float *qkv = nullptr;
    __half *A1 = nullptr, *B1 = nullptr, *B2 = nullptr, *A2 = nullptr;
    __half *ksp = nullptr, *vsp = nullptr;
    cudaGetSymbolAddress((void**)&qkv, g_qkv);
    cudaGetSymbolAddress((void**)&A1,  g_A1);
    cudaGetSymbolAddress((void**)&B1,  g_B1);
    cudaGetSymbolAddress((void**)&B2,  g_B2);
    cudaGetSymbolAddress((void**)&A2,  g_A2);
    cudaGetSymbolAddress((void**)&ksp, g_ks);
    cudaGetSymbolAddress((void**)&vsp, g_vs);

    cudaFuncSetAttribute(gemm_mma_kernel, cudaFuncAttributeMaxDynamicSharedMemorySize, G_SMEM);
    cudaFuncSetAttribute(attn_mma_kernel, cudaFuncAttributeMaxDynamicSharedMemorySize, ATT_SMEM);

    // 0) Conversions to fp16 formats
    convX_kernel<<<(TOKENS * CDIM) / 256, 256>>>(x, A1);
    convW_kernel<<<dim3(QKVDIM / 32, CDIM / 32), 256>>>(W_qkv, B1, QKVDIM);
    convW_kernel<<<dim3(CDIM / 32, CDIM / 32), 256>>>(W_proj, B2, CDIM);

    // 1) QKV projection: [8192, 3072] = (A1hi+A1lo) @ B1^T + b_qkv
    gemm_mma_kernel<<<dim3(QKVDIM / BN, TOKENS / BM), 256, G_SMEM>>>(A1, B1, b_qkv, qkv, QKVDIM);

    // 2) Fused RMSNorm (q in place, k) + K/V fp16 store
    rmskv_kernel<<<(TOKENS * 32) / 8, 256>>>(qkv, qn_w, kn_w, ksp, vsp);

    // 3) Attention (tensor cores) -> g_A2 (fp16 hi/lo, proj-ready)
    attn_mma_kernel<<<dim3(SEQ / 128, BATCH * HEADS), 256, ATT_SMEM>>>(qkv, ksp, vsp, A2);

    // 4) Output projection: [8192, 1024] = (A2hi+A2lo) @ B2^T + b_proj
    gemm_mma_kernel<<<dim3(CDIM / BN, TOKENS / BM), 256, G_SMEM>>>(A2, B2, b_proj, out, CDIM);
}

// round 11
// speedup vs baseline: 6.5275x; 1.0903x over previous
#include <cuda_runtime.h>
#include <cuda_fp16.h>
#include <math_constants.h>
#include <cstdint>

// Problem constants
#define BATCH 4
#define SEQ   2048
#define CDIM  1024
#define HEADS 16
#define HDIM  64
#define TOKENS (BATCH * SEQ)         // 8192
#define QKVDIM (3 * CDIM)            // 3072
#define KA    2048                   // A-side split K (hi|lo)
#define KB    1024                   // B-side K (hi only)

// ---------------------------------------------------------------------------
// Scratch (device globals — no allocation allowed)
// ---------------------------------------------------------------------------
__device__ float g_qkv[(size_t)TOKENS * QKVDIM];                    // QKV output fp32
__device__ __align__(256) __half g_A1[(size_t)TOKENS * KA];        // x split      [m, hi|lo]
__device__ __align__(256) __half g_B1[(size_t)QKVDIM * KB];        // W_qkv^T hi   [n, k]
__device__ __align__(256) __half g_B2[(size_t)CDIM * KB];          // W_proj^T hi
__device__ __align__(256) __half g_A2[(size_t)TOKENS * KA];        // attn out split [m, hi|lo]
__device__ __align__(256) __half g_ks[(size_t)BATCH * HEADS * SEQ * 64]; // K hi [bh, n, d]
__device__ __align__(256) __half g_vs[(size_t)BATCH * HEADS * SEQ * 64]; // V hi

// ---------------------------------------------------------------------------
// PTX helpers (portable sm_80+ features only)
// ---------------------------------------------------------------------------
__device__ __forceinline__ uint32_t smem_u32(const void* p) {
    uint32_t a;
    asm("{ .reg .u64 t; cvta.to.shared.u64 t, %1; cvt.u32.u64 %0, t; }" : "=r"(a) : "l"(p));
    return a;
}
__device__ __forceinline__ void cp_async16(uint32_t dst, const void* src) {
    asm volatile("cp.async.cg.shared.global [%0], [%1], 16;" :: "r"(dst), "l"(src));
}
__device__ __forceinline__ void cp_commit() {
    asm volatile("cp.async.commit_group;" ::: "memory");
}
__device__ __forceinline__ void cp_wait0() {
    asm volatile("cp.async.wait_group 0;" ::: "memory");
}
__device__ __forceinline__ void cp_wait1() {
    asm volatile("cp.async.wait_group 1;" ::: "memory");
}
__device__ __forceinline__ void cp_wait2() {
    asm volatile("cp.async.wait_group 2;" ::: "memory");
}
__device__ __forceinline__ void ldsm_x4(uint32_t* r, uint32_t addr) {
    asm volatile("ldmatrix.sync.aligned.m8n8.x4.shared.b16 {%0,%1,%2,%3}, [%4];"
                 : "=r"(r[0]), "=r"(r[1]), "=r"(r[2]), "=r"(r[3]) : "r"(addr));
}
__device__ __forceinline__ void ldsm_x4_t(uint32_t* r, uint32_t addr) {
    asm volatile("ldmatrix.sync.aligned.m8n8.x4.trans.shared.b16 {%0,%1,%2,%3}, [%4];"
                 : "=r"(r[0]), "=r"(r[1]), "=r"(r[2]), "=r"(r[3]) : "r"(addr));
}
__device__ __forceinline__ void mma_fp16(float* c, const uint32_t* a, const uint32_t* b) {
    asm volatile(
        "mma.sync.aligned.m16n8k16.row.col.f32.f16.f16.f32 "
        "{%0,%1,%2,%3}, {%4,%5,%6,%7}, {%8,%9}, {%0,%1,%2,%3};"
        : "+f"(c[0]), "+f"(c[1]), "+f"(c[2]), "+f"(c[3])
        : "r"(a[0]), "r"(a[1]), "r"(a[2]), "r"(a[3]), "r"(b[0]), "r"(b[1]));
}
__device__ __forceinline__ float ex2f(float x) {
    float y; asm("ex2.approx.ftz.f32 %0, %1;" : "=f"(y) : "f"(x)); return y;
}
__device__ __forceinline__ uint32_t h2pack(float a, float b) {
    __half2 h;
    h.x = __float2half_rn(a);
    h.y = __float2half_rn(b);
    return *(uint32_t*)&h;
}
__device__ __forceinline__ uint32_t h2pack_lo(float a, float b, uint32_t hipack) {
    __half2 h = *(__half2*)&hipack;
    return h2pack(a - __half2float(h.x), b - __half2float(h.y));
}

// ---------------------------------------------------------------------------
// Conversion kernels (fp32 -> fp16 hi/lo split)
// ---------------------------------------------------------------------------
__global__ __launch_bounds__(256) void convX_kernel(const float* __restrict__ x,
                                                    __half* __restrict__ A)
{
    const int idx = blockIdx.x * 256 + threadIdx.x;      // over TOKENS*CDIM
    const int m = idx >> 10;
    const int k = idx & 1023;
    const float v = x[idx];
    const __half hi = __float2half_rn(v);
    __half* row = A + (size_t)m * KA;
    row[k]        = hi;
    row[1024 + k] = __float2half_rn(v - __half2float(hi));
}

// Transpose: W [K=1024, N] fp32 -> B [N, 1024] fp16 (hi only)
__global__ __launch_bounds__(256) void convW_kernel(const float* __restrict__ W,
                                                    __half* __restrict__ B, int N)
{
    __shared__ float t[32][33];
    const int n0 = blockIdx.x * 32;
    const int k0 = blockIdx.y * 32;
    const int tx = threadIdx.x & 31;
    const int ty = threadIdx.x >> 5;          // 0..7
    #pragma unroll
    for (int i = 0; i < 4; ++i)
        t[ty + 8 * i][tx] = W[(size_t)(k0 + ty + 8 * i) * N + n0 + tx];
    __syncthreads();
    #pragma unroll
    for (int i = 0; i < 4; ++i) {
        const int n = n0 + ty + 8 * i;
        const int k = k0 + tx;
        B[(size_t)n * KB + k] = __float2half_rn(t[tx][ty + 8 * i]);
    }
}

// ---------------------------------------------------------------------------
// mma.sync fp16 GEMM:  C[M,N] = (A_hi [+ A_lo]) @ B_hi^T + bias
// The lo-term is applied only to output columns < loN (CTA-uniform branch):
// for the QKV GEMM, K and V outputs are truncated to fp16 downstream, so
// their lo contribution is below the noise floor and skipped.
// Stage holds {A_hi, A_lo, B} for ONE k64 range. 16 chunks, 2-stage double
// buffer, one barrier per chunk. CTA 128x128, 8 warps (2x4), warp tile 64x32.
// ---------------------------------------------------------------------------
#define BM 128
#define BN 128
#define BK 64
#define G_REGION (BM * BK * 2)           // 16384 bytes per matrix region
#define G_STAGE_BYTES (3 * G_REGION)     // 49152 (Ahi + Alo + B)
#define G_SMEM (2 * G_STAGE_BYTES)       // 98304
#define NCHUNKG (KB / BK)                // 16

__global__ __launch_bounds__(256, 2) void gemm_mma_kernel(
    const __half* __restrict__ A, const __half* __restrict__ Bm,
    const float* __restrict__ bias, float* __restrict__ C, int N, int loN)
{
    extern __shared__ __align__(256) char gsm[];
    const uint32_t base = smem_u32(gsm);

    const int tid  = threadIdx.x;
    const int wid  = tid >> 5;
    const int lane = tid & 31;
    const int wm   = wid >> 2;           // 0..1
    const int wn   = wid & 3;            // 0..3
    const int rowBase = blockIdx.y * BM;
    const int colBase = blockIdx.x * BN;
    const bool useLo = (colBase < loN);  // CTA-uniform

    float acc[4][4][4] = {};

    const int lrow = tid >> 3;           // 0..31 (x4 via +32)
    const int lch  = tid & 7;

    auto loadStage = [&](int c, int s) {
        const __half* Ah = A + (size_t)rowBase * KA + c * BK;          // hi cols
        const __half* Al = Ah + 1024;                                   // lo cols
        const __half* Bg = Bm + (size_t)colBase * KB + c * BK;
        const uint32_t st = base + s * G_STAGE_BYTES;
        #pragma unroll
        for (int m = 0; m < 4; ++m) {
            const int row = lrow + m * 32;
            const uint32_t soff = row * 128 + ((lch ^ (row & 7)) << 4);
            cp_async16(st + soff,                Ah + (size_t)row * KA + lch * 8);
            if (useLo)
                cp_async16(st + G_REGION + soff, Al + (size_t)row * KA + lch * 8);
            cp_async16(st + 2 * G_REGION + soff, Bg + (size_t)row * KB + lch * 8);
        }
        cp_commit();
    };

    loadStage(0, 0);

    for (int c = 0; c < NCHUNKG; ++c) {
        cp_wait0();
        __syncthreads();                 // chunk c visible; compute of c-1 done everywhere
        if (c + 1 < NCHUNKG) loadStage(c + 1, (c + 1) & 1);

        const uint32_t st = base + (c & 1) * G_STAGE_BYTES;
        const uint32_t ahs = st;
        const uint32_t als = st + G_REGION;
        const uint32_t bsb = st + 2 * G_REGION;

        #pragma unroll
        for (int ks = 0; ks < 4; ++ks) {
            const int arow = wm * 64 + (lane & 15);
            const int ach  = ks * 2 + (lane >> 4);
            uint32_t ahfr[4][4], alfr[4][4];
            #pragma unroll
            for (int mt = 0; mt < 4; ++mt) {
                const int row = arow + mt * 16;
                const uint32_t off = row * 128 + ((ach ^ (row & 7)) << 4);
                ldsm_x4(ahfr[mt], ahs + off);
                if (useLo) ldsm_x4(alfr[mt], als + off);
            }
            uint32_t bfr[4][2];
            #pragma unroll
            for (int ntp = 0; ntp < 2; ++ntp) {
                const int row = wn * 32 + ntp * 16 + (lane & 7) + ((lane >> 4) << 3);
                const int ch  = ks * 2 + ((lane >> 3) & 1);
                uint32_t r[4];
                ldsm_x4(r, bsb + row * 128 + ((ch ^ (row & 7)) << 4));
                bfr[2 * ntp][0]     = r[0]; bfr[2 * ntp][1]     = r[1];
                bfr[2 * ntp + 1][0] = r[2]; bfr[2 * ntp + 1][1] = r[3];
            }
            #pragma unroll
            for (int mt = 0; mt < 4; ++mt)
                #pragma unroll
                for (int nt = 0; nt < 4; ++nt)
                    mma_fp16(acc[mt][nt], ahfr[mt], bfr[nt]);
            if (useLo) {
                #pragma unroll
                for (int mt = 0; mt < 4; ++mt)
                    #pragma unroll
                    for (int nt = 0; nt < 4; ++nt)
                        mma_fp16(acc[mt][nt], alfr[mt], bfr[nt]);
            }
        }
        __syncthreads();                 // all reads of stage c done before reload
    }

    // Epilogue
    const int erow = lane >> 2;
    const int ecol = (lane & 3) * 2;
    #pragma unroll
    for (int mt = 0; mt < 4; ++mt) {
        const int rA = rowBase + wm * 64 + mt * 16 + erow;
        #pragma unroll
        for (int nt = 0; nt < 4; ++nt) {
            const int col = colBase + wn * 32 + nt * 8 + ecol;
            const float b0 = bias[col], b1 = bias[col + 1];
            *(float2*)&C[(size_t)rA * N + col] =
                make_float2(acc[mt][nt][0] + b0, acc[mt][nt][1] + b1);
            *(float2*)&C[(size_t)(rA + 8) * N + col] =
                make_float2(acc[mt][nt][2] + b0, acc[mt][nt][3] + b1);
        }
    }
}

// ---------------------------------------------------------------------------
// Fused RMSNorm + K/V fp16 store. One warp per (token, slot).
// ---------------------------------------------------------------------------
__global__ __launch_bounds__(256) void rmskv_kernel(
    float* __restrict__ qkv,
    const float* __restrict__ qn_w, const float* __restrict__ kn_w,
    __half* __restrict__ ks, __half* __restrict__ vs)
{
    const int gwarp = (blockIdx.x * blockDim.x + threadIdx.x) >> 5;
    const int lane  = threadIdx.x & 31;
    const int token = gwarp >> 5;
    const int slot  = gwarp & 31;
    if (token >= TOKENS) return;

    const int h = slot & 15;

    if (slot < 16) {
        float* row = qkv + (size_t)token * QKVDIM + h * HDIM;
        float x0 = row[lane];
        float x1 = row[lane + 32];
        float ss = x0 * x0 + x1 * x1;
        #pragma unroll
        for (int off = 16; off; off >>= 1) ss += __shfl_xor_sync(0xffffffffu, ss, off);
        const float inv = rsqrtf(ss * (1.0f / 64.0f) + 1e-6f);
        row[lane]      = x0 * inv * qn_w[lane];
        row[lane + 32] = x1 * inv * qn_w[lane + 32];
    } else {
        const int b = token >> 11;
        const int n = token & 2047;
        const size_t dstRow = ((size_t)(b * HEADS + h) * SEQ + n) * 64;

        {   // K: rmsnorm + fp16
            const float* row = qkv + (size_t)token * QKVDIM + CDIM + h * HDIM;
            float x0 = row[lane];
            float x1 = row[lane + 32];
            float ss = x0 * x0 + x1 * x1;
            #pragma unroll
            for (int off = 16; off; off >>= 1) ss += __shfl_xor_sync(0xffffffffu, ss, off);
            const float inv = rsqrtf(ss * (1.0f / 64.0f) + 1e-6f);
            ks[dstRow + lane]      = __float2half_rn(x0 * inv * kn_w[lane]);
            ks[dstRow + lane + 32] = __float2half_rn(x1 * inv * kn_w[lane + 32]);
        }
        {   // V: fp16
            const float* row = qkv + (size_t)token * QKVDIM + 2 * CDIM + h * HDIM;
            vs[dstRow + lane]      = __float2half_rn(row[lane]);
            vs[dstRow + lane + 32] = __float2half_rn(row[lane + 32]);
        }
    }
}

// ---------------------------------------------------------------------------
// FlashAttention-2 style mma.sync fp16 attention. Bc=64, 4-stage pipeline,
// 2 CTAs/SM (reg-capped). Q carried as 2-term fp16 (hi+lo); K, V, P hi only.
// CTA = 128 q-rows x (b,h); 8 warps x 16 rows. K/V tiles: 64 rows x 128B.
// ---------------------------------------------------------------------------
#define ATT_NT (SEQ / 64)             // 32 key tiles
#define ATT_TILE_B 8192               // one matrix tile: 64 rows * 128B
#define ATT_BUF_B  16384              // K + V per stage
#define ATT_STAGES 4
#define ATT_SMEM   (ATT_STAGES * ATT_BUF_B)   // 65536

__global__ __launch_bounds__(256, 2) void attn_mma_kernel(
    const float* __restrict__ qkv,
    const __half* __restrict__ ks, const __half* __restrict__ vs,
    __half* __restrict__ outA)
{
    extern __shared__ __align__(256) char sm[];
    const uint32_t smBase = smem_u32(sm);

    const int tid  = threadIdx.x;
    const int wq   = tid >> 5;
    const int lane = tid & 31;

    const int bh = blockIdx.y;
    const int b  = bh >> 4;
    const int h  = bh & 15;
    const int qBase = blockIdx.x * 128;

    // ---- Q fragments (hi/lo fp16), scale folded: 0.125 * log2(e) ----
    const float SC = 0.125f * 1.44269504088896340736f;
    uint32_t qh[4][4], ql[4][4];
    {
        const float* qg = qkv + ((size_t)(b * SEQ + qBase + wq * 16)) * QKVDIM + h * HDIM;
        const int rr = lane >> 2;
        const int cb = (lane & 3) * 2;
        #pragma unroll
        for (int kd = 0; kd < 4; ++kd) {
            const int d0 = kd * 16;
            float2 v0 = *(const float2*)&qg[(size_t)rr * QKVDIM + d0 + cb];
            float2 v1 = *(const float2*)&qg[(size_t)(rr + 8) * QKVDIM + d0 + cb];
            float2 v2 = *(const float2*)&qg[(size_t)rr * QKVDIM + d0 + cb + 8];
            float2 v3 = *(const float2*)&qg[(size_t)(rr + 8) * QKVDIM + d0 + cb + 8];
            v0.x *= SC; v0.y *= SC; v1.x *= SC; v1.y *= SC;
            v2.x *= SC; v2.y *= SC; v3.x *= SC; v3.y *= SC;
            qh[kd][0] = h2pack(v0.x, v0.y); ql[kd][0] = h2pack_lo(v0.x, v0.y, qh[kd][0]);
            qh[kd][1] = h2pack(v1.x, v1.y); ql[kd][1] = h2pack_lo(v1.x, v1.y, qh[kd][1]);
            qh[kd][2] = h2pack(v2.x, v2.y); ql[kd][2] = h2pack_lo(v2.x, v2.y, qh[kd][2]);
            qh[kd][3] = h2pack(v3.x, v3.y); ql[kd][3] = h2pack_lo(v3.x, v3.y, qh[kd][3]);
        }
    }

    // ---- cp.async tile loader: 64 keys, K + V hi (128B rows, XOR swizzle) ----
    auto loadTile = [&](int kt, int st) {
        const __half* gk = ks + ((size_t)bh * SEQ + kt * 64) * 64;
        const __half* gv = vs + ((size_t)bh * SEQ + kt * 64) * 64;
        const uint32_t kb = smBase + st * ATT_BUF_B;
        const uint32_t vb = kb + ATT_TILE_B;
        #pragma unroll
        for (int m = 0; m < 2; ++m) {
            const int id = tid + m * 256;           // 0..511
            const int c = id >> 3, j = id & 7;
            const uint32_t soff = c * 128 + ((j ^ (c & 7)) << 4);
            cp_async16(kb + soff, gk + (size_t)c * 64 + j * 8);
            cp_async16(vb + soff, gv + (size_t)c * 64 + j * 8);
        }
        cp_commit();
    };

    float m0 = -CUDART_INF_F, m1 = -CUDART_INF_F, l0 = 0.0f, l1 = 0.0f;
    float O[8][4] = {};

    loadTile(0, 0);
    loadTile(1, 1);
    loadTile(2, 2);

    for (int kt = 0; kt < ATT_NT; ++kt) {
        const int st = kt & 3;
        if (kt + 2 < ATT_NT)      cp_wait2();
        else if (kt + 1 < ATT_NT) cp_wait1();
        else                      cp_wait0();
        __syncthreads();
        if (kt + 3 < ATT_NT) loadTile(kt + 3, (kt + 3) & 3);

        const uint32_t Kb = smBase + st * ATT_BUF_B;
        const uint32_t Vb = Kb + ATT_TILE_B;

        // ---- S = (Qh+Ql) K^T, 64 keys ----
        float S[8][4] = {};
        #pragma unroll
        for (int kd = 0; kd < 4; ++kd) {
            #pragma unroll
            for (int t = 0; t < 4; ++t) {
                const int row = 16 * t + (lane & 7) + 8 * ((lane >> 4) & 1);
                const int j = kd * 2 + ((lane >> 3) & 1);
                uint32_t r[4];
                ldsm_x4(r, Kb + row * 128 + ((j ^ (row & 7)) << 4));
                mma_fp16(S[2 * t],     qh[kd], r);
                mma_fp16(S[2 * t],     ql[kd], r);
                mma_fp16(S[2 * t + 1], qh[kd], r + 2);
                mma_fp16(S[2 * t + 1], ql[kd], r + 2);
            }
        }

        // ---- Online softmax (base 2) ----
        float mt0 = -CUDART_INF_F, mt1 = -CUDART_INF_F;
        #pragma unroll
        for (int nc = 0; nc < 8; ++nc) {
            mt0 = fmaxf(mt0, fmaxf(S[nc][0], S[nc][1]));
            mt1 = fmaxf(mt1, fmaxf(S[nc][2], S[nc][3]));
        }
        mt0 = fmaxf(mt0, __shfl_xor_sync(0xffffffffu, mt0, 1));
        mt0 = fmaxf(mt0, __shfl_xor_sync(0xffffffffu, mt0, 2));
        mt1 = fmaxf(mt1, __shfl_xor_sync(0xffffffffu, mt1, 1));
        mt1 = fmaxf(mt1, __shfl_xor_sync(0xffffffffu, mt1, 2));
        const float mn0 = fmaxf(m0, mt0);
        const float mn1 = fmaxf(m1, mt1);
        const float c0 = ex2f(m0 - mn0);
        const float c1 = ex2f(m1 - mn1);
        m0 = mn0; m1 = mn1;
        float rs0 = 0.0f, rs1 = 0.0f;
        #pragma unroll
        for (int nc = 0; nc < 8; ++nc) {
            S[nc][0] = ex2f(S[nc][0] - mn0); rs0 += S[nc][0];
            S[nc][1] = ex2f(S[nc][1] - mn0); rs0 += S[nc][1];
            S[nc][2] = ex2f(S[nc][2] - mn1); rs1 += S[nc][2];
            S[nc][3] = ex2f(S[nc][3] - mn1); rs1 += S[nc][3];
        }
        rs0 += __shfl_xor_sync(0xffffffffu, rs0, 1);
        rs0 += __shfl_xor_sync(0xffffffffu, rs0, 2);
        rs1 += __shfl_xor_sync(0xffffffffu, rs1, 1);
        rs1 += __shfl_xor_sync(0xffffffffu, rs1, 2);
        l0 = l0 * c0 + rs0;
        l1 = l1 * c1 + rs1;
        #pragma unroll
        for (int nd = 0; nd < 8; ++nd) {
            O[nd][0] *= c0; O[nd][1] *= c0; O[nd][2] *= c1; O[nd][3] *= c1;
        }

        // ---- O += P V (P fp16 hi only), 4 k16 chunks ----
        #pragma unroll
        for (int kc = 0; kc < 4; ++kc) {
            uint32_t ph[4];
            {
                const float* s0 = S[2 * kc];
                const float* s1 = S[2 * kc + 1];
                ph[0] = h2pack(s0[0], s0[1]);
                ph[1] = h2pack(s0[2], s0[3]);
                ph[2] = h2pack(s1[0], s1[1]);
                ph[3] = h2pack(s1[2], s1[3]);
            }
            #pragma unroll
            for (int t = 0; t < 4; ++t) {
                const int row = kc * 16 + (lane & 7) + 8 * ((lane >> 3) & 1);
                const int j = 2 * t + ((lane >> 4) & 1);
                uint32_t r[4];
                ldsm_x4_t(r, Vb + row * 128 + ((j ^ (row & 7)) << 4));
                mma_fp16(O[2 * t],     ph, r);
                mma_fp16(O[2 * t + 1], ph, r + 2);
            }
        }
    }

    // ---- Epilogue: normalize, write fp16 hi/lo split rows to outA ----
    const float inv0 = 1.0f / l0;
    const float inv1 = 1.0f / l1;
    const size_t row1 = (size_t)b * SEQ + qBase + wq * 16 + (lane >> 2);
    const int colBase = h * HDIM + (lane & 3) * 2;
    #pragma unroll
    for (int nd = 0; nd < 8; ++nd) {
        const int col = colBase + nd * 8;
        {
            const float x = O[nd][0] * inv0, y = O[nd][1] * inv0;
            __half* p = outA + row1 * KA + col;
            const uint32_t hp = h2pack(x, y);
            *(uint32_t*)p = hp;
            *(uint32_t*)(p + 1024) = h2pack_lo(x, y, hp);
        }
        {
            const float x = O[nd][2] * inv1, y = O[nd][3] * inv1;
            __half* p = outA + (row1 + 8) * KA + col;
            const uint32_t hp = h2pack(x, y);
            *(uint32_t*)p = hp;
            *(uint32_t*)(p + 1024) = h2pack_lo(x, y, hp);
        }
    }
}

// ---------------------------------------------------------------------------
// Launch
// ---------------------------------------------------------------------------
extern "C" void kernel_launch(void* const* d_in, const int* in_sizes, int n_in,
                              void* d_out, int out_size)
{
    (void)in_sizes; (void)n_in; (void)out_size;
    const float* x      = (const float*)d_in[0];
    const float* W_qkv  = (const float*)d_in[1];
    const float* b_qkv  = (const float*)d_in[2];
    const float* W_proj = (const float*)d_in[3];
    const float* b_proj = (const float*)d_in[4];
    const float* qn_w   = (const float*)d_in[5];
    const float* kn_w   = (const float*)d_in[6];
    float* out = (float*)d_out;

    float *qkv = nullptr;
    __half *A1 = nullptr, *B1 = nullptr, *B2 = nullptr, *A2 = nullptr;
    __half *ksp = nullptr, *vsp = nullptr;
    cudaGetSymbolAddress((void**)&qkv, g_qkv);
    cudaGetSymbolAddress((void**)&A1,  g_A1);
    cudaGetSymbolAddress((void**)&B1,  g_B1);
    cudaGetSymbolAddress((void**)&B2,  g_B2);
    cudaGetSymbolAddress((void**)&A2,  g_A2);
    cudaGetSymbolAddress((void**)&ksp, g_ks);
    cudaGetSymbolAddress((void**)&vsp, g_vs);

    cudaFuncSetAttribute(gemm_mma_kernel, cudaFuncAttributeMaxDynamicSharedMemorySize, G_SMEM);
    cudaFuncSetAttribute(attn_mma_kernel, cudaFuncAttributeMaxDynamicSharedMemorySize, ATT_SMEM);

    // 0) Conversions to fp16 formats
    convX_kernel<<<(TOKENS * CDIM) / 256, 256>>>(x, A1);
    convW_kernel<<<dim3(QKVDIM / 32, CDIM / 32), 256>>>(W_qkv, B1, QKVDIM);
    convW_kernel<<<dim3(CDIM / 32, CDIM / 32), 256>>>(W_proj, B2, CDIM);

    // 1) QKV projection: lo-term only for Q columns (K/V truncated to fp16 anyway)
    gemm_mma_kernel<<<dim3(QKVDIM / BN, TOKENS / BM), 256, G_SMEM>>>(
        A1, B1, b_qkv, qkv, QKVDIM, CDIM);

    // 2) Fused RMSNorm (q in place, k) + K/V fp16 store
    rmskv_kernel<<<(TOKENS * 32) / 8, 256>>>(qkv, qn_w, kn_w, ksp, vsp);

    // 3) Attention (tensor cores) -> g_A2 (fp16 hi/lo, proj-ready)
    attn_mma_kernel<<<dim3(SEQ / 128, BATCH * HEADS), 256, ATT_SMEM>>>(qkv, ksp, vsp, A2);

    // 4) Output projection: full hi+lo everywhere (fp32 output)
    gemm_mma_kernel<<<dim3(CDIM / BN, TOKENS / BM), 256, G_SMEM>>>(
        A2, B2, b_proj, out, CDIM, CDIM);
}

// round 12
// speedup vs baseline: 7.2270x; 1.1072x over previous
#include <cuda_runtime.h>
#include <cuda_fp16.h>
#include <math_constants.h>
#include <cstdint>

// Problem constants
#define BATCH 4
#define SEQ   2048
#define CDIM  1024
#define HEADS 16
#define HDIM  64
#define TOKENS (BATCH * SEQ)         // 8192
#define QKVDIM (3 * CDIM)            // 3072
#define KA    2048                   // A-side split K (hi|lo)
#define KB    1024                   // B-side K (hi only)

// ---------------------------------------------------------------------------
// Scratch (device globals — no allocation allowed)
// ---------------------------------------------------------------------------
__device__ float g_qkv[(size_t)TOKENS * QKVDIM];                    // QKV output fp32
__device__ __align__(256) __half g_A1[(size_t)TOKENS * KA];        // x split      [m, hi|lo]
__device__ __align__(256) __half g_B1[(size_t)QKVDIM * KB];        // W_qkv^T hi   [n, k]
__device__ __align__(256) __half g_B2[(size_t)CDIM * KB];          // W_proj^T hi
__device__ __align__(256) __half g_A2[(size_t)TOKENS * KA];        // attn out split [m, hi|lo]
__device__ __align__(256) __half g_ks[(size_t)BATCH * HEADS * SEQ * 64]; // K hi [bh, n, d]
__device__ __align__(256) __half g_vs[(size_t)BATCH * HEADS * SEQ * 64]; // V hi

// ---------------------------------------------------------------------------
// PTX helpers (portable sm_80+ features only)
// ---------------------------------------------------------------------------
__device__ __forceinline__ uint32_t smem_u32(const void* p) {
    uint32_t a;
    asm("{ .reg .u64 t; cvta.to.shared.u64 t, %1; cvt.u32.u64 %0, t; }" : "=r"(a) : "l"(p));
    return a;
}
__device__ __forceinline__ void cp_async16(uint32_t dst, const void* src) {
    asm volatile("cp.async.cg.shared.global [%0], [%1], 16;" :: "r"(dst), "l"(src));
}
__device__ __forceinline__ void cp_commit() {
    asm volatile("cp.async.commit_group;" ::: "memory");
}
__device__ __forceinline__ void cp_wait0() {
    asm volatile("cp.async.wait_group 0;" ::: "memory");
}
__device__ __forceinline__ void cp_wait1() {
    asm volatile("cp.async.wait_group 1;" ::: "memory");
}
__device__ __forceinline__ void cp_wait2() {
    asm volatile("cp.async.wait_group 2;" ::: "memory");
}
__device__ __forceinline__ void ldsm_x4(uint32_t* r, uint32_t addr) {
    asm volatile("ldmatrix.sync.aligned.m8n8.x4.shared.b16 {%0,%1,%2,%3}, [%4];"
                 : "=r"(r[0]), "=r"(r[1]), "=r"(r[2]), "=r"(r[3]) : "r"(addr));
}
__device__ __forceinline__ void ldsm_x4_t(uint32_t* r, uint32_t addr) {
    asm volatile("ldmatrix.sync.aligned.m8n8.x4.trans.shared.b16 {%0,%1,%2,%3}, [%4];"
                 : "=r"(r[0]), "=r"(r[1]), "=r"(r[2]), "=r"(r[3]) : "r"(addr));
}
__device__ __forceinline__ void mma_fp16(float* c, const uint32_t* a, const uint32_t* b) {
    asm volatile(
        "mma.sync.aligned.m16n8k16.row.col.f32.f16.f16.f32 "
        "{%0,%1,%2,%3}, {%4,%5,%6,%7}, {%8,%9}, {%0,%1,%2,%3};"
        : "+f"(c[0]), "+f"(c[1]), "+f"(c[2]), "+f"(c[3])
        : "r"(a[0]), "r"(a[1]), "r"(a[2]), "r"(a[3]), "r"(b[0]), "r"(b[1]));
}
__device__ __forceinline__ float ex2f(float x) {
    float y; asm("ex2.approx.ftz.f32 %0, %1;" : "=f"(y) : "f"(x)); return y;
}
__device__ __forceinline__ uint32_t h2pack(float a, float b) {
    __half2 h;
    h.x = __float2half_rn(a);
    h.y = __float2half_rn(b);
    return *(uint32_t*)&h;
}
__device__ __forceinline__ uint32_t h2pack_lo(float a, float b, uint32_t hipack) {
    __half2 h = *(__half2*)&hipack;
    return h2pack(a - __half2float(h.x), b - __half2float(h.y));
}

// ---------------------------------------------------------------------------
// Conversion kernels (fp32 -> fp16 hi/lo split)
// ---------------------------------------------------------------------------
__global__ __launch_bounds__(256) void convX_kernel(const float* __restrict__ x,
                                                    __half* __restrict__ A)
{
    const int idx = blockIdx.x * 256 + threadIdx.x;      // over TOKENS*CDIM
    const int m = idx >> 10;
    const int k = idx & 1023;
    const float v = x[idx];
    const __half hi = __float2half_rn(v);
    __half* row = A + (size_t)m * KA;
    row[k]        = hi;
    row[1024 + k] = __float2half_rn(v - __half2float(hi));
}

// Transpose: W [K=1024, N] fp32 -> B [N, 1024] fp16 (hi only)
__global__ __launch_bounds__(256) void convW_kernel(const float* __restrict__ W,
                                                    __half* __restrict__ B, int N)
{
    __shared__ float t[32][33];
    const int n0 = blockIdx.x * 32;
    const int k0 = blockIdx.y * 32;
    const int tx = threadIdx.x & 31;
    const int ty = threadIdx.x >> 5;          // 0..7
    #pragma unroll
    for (int i = 0; i < 4; ++i)
        t[ty + 8 * i][tx] = W[(size_t)(k0 + ty + 8 * i) * N + n0 + tx];
    __syncthreads();
    #pragma unroll
    for (int i = 0; i < 4; ++i) {
        const int n = n0 + ty + 8 * i;
        const int k = k0 + tx;
        B[(size_t)n * KB + k] = __float2half_rn(t[tx][ty + 8 * i]);
    }
}

// ---------------------------------------------------------------------------
// mma.sync fp16 GEMM:  C[M,N] = (A_hi [+ A_lo]) @ B_hi^T + bias
// lo-term only for output columns < loN (CTA-uniform).
// ---------------------------------------------------------------------------
#define BM 128
#define BN 128
#define BK 64
#define G_REGION (BM * BK * 2)           // 16384 bytes per matrix region
#define G_STAGE_BYTES (3 * G_REGION)     // 49152 (Ahi + Alo + B)
#define G_SMEM (2 * G_STAGE_BYTES)       // 98304
#define NCHUNKG (KB / BK)                // 16

__global__ __launch_bounds__(256, 2) void gemm_mma_kernel(
    const __half* __restrict__ A, const __half* __restrict__ Bm,
    const float* __restrict__ bias, float* __restrict__ C, int N, int loN)
{
    extern __shared__ __align__(256) char gsm[];
    const uint32_t base = smem_u32(gsm);

    const int tid  = threadIdx.x;
    const int wid  = tid >> 5;
    const int lane = tid & 31;
    const int wm   = wid >> 2;           // 0..1
    const int wn   = wid & 3;            // 0..3
    const int rowBase = blockIdx.y * BM;
    const int colBase = blockIdx.x * BN;
    const bool useLo = (colBase < loN);  // CTA-uniform

    float acc[4][4][4] = {};

    const int lrow = tid >> 3;           // 0..31 (x4 via +32)
    const int lch  = tid & 7;

    auto loadStage = [&](int c, int s) {
        const __half* Ah = A + (size_t)rowBase * KA + c * BK;          // hi cols
        const __half* Al = Ah + 1024;                                   // lo cols
        const __half* Bg = Bm + (size_t)colBase * KB + c * BK;
        const uint32_t st = base + s * G_STAGE_BYTES;
        #pragma unroll
        for (int m = 0; m < 4; ++m) {
            const int row = lrow + m * 32;
            const uint32_t soff = row * 128 + ((lch ^ (row & 7)) << 4);
            cp_async16(st + soff,                Ah + (size_t)row * KA + lch * 8);
            if (useLo)
                cp_async16(st + G_REGION + soff, Al + (size_t)row * KA + lch * 8);
            cp_async16(st + 2 * G_REGION + soff, Bg + (size_t)row * KB + lch * 8);
        }
        cp_commit();
    };

    loadStage(0, 0);

    for (int c = 0; c < NCHUNKG; ++c) {
        cp_wait0();
        __syncthreads();                 // chunk c visible; compute of c-1 done everywhere
        if (c + 1 < NCHUNKG) loadStage(c + 1, (c + 1) & 1);

        const uint32_t st = base + (c & 1) * G_STAGE_BYTES;
        const uint32_t ahs = st;
        const uint32_t als = st + G_REGION;
        const uint32_t bsb = st + 2 * G_REGION;

        #pragma unroll
        for (int ks = 0; ks < 4; ++ks) {
            const int arow = wm * 64 + (lane & 15);
            const int ach  = ks * 2 + (lane >> 4);
            uint32_t ahfr[4][4], alfr[4][4];
            #pragma unroll
            for (int mt = 0; mt < 4; ++mt) {
                const int row = arow + mt * 16;
                const uint32_t off = row * 128 + ((ach ^ (row & 7)) << 4);
                ldsm_x4(ahfr[mt], ahs + off);
                if (useLo) ldsm_x4(alfr[mt], als + off);
            }
            uint32_t bfr[4][2];
            #pragma unroll
            for (int ntp = 0; ntp < 2; ++ntp) {
                const int row = wn * 32 + ntp * 16 + (lane & 7) + ((lane >> 4) << 3);
                const int ch  = ks * 2 + ((lane >> 3) & 1);
                uint32_t r[4];
                ldsm_x4(r, bsb + row * 128 + ((ch ^ (row & 7)) << 4));
                bfr[2 * ntp][0]     = r[0]; bfr[2 * ntp][1]     = r[1];
                bfr[2 * ntp + 1][0] = r[2]; bfr[2 * ntp + 1][1] = r[3];
            }
            #pragma unroll
            for (int mt = 0; mt < 4; ++mt)
                #pragma unroll
                for (int nt = 0; nt < 4; ++nt)
                    mma_fp16(acc[mt][nt], ahfr[mt], bfr[nt]);
            if (useLo) {
                #pragma unroll
                for (int mt = 0; mt < 4; ++mt)
                    #pragma unroll
                    for (int nt = 0; nt < 4; ++nt)
                        mma_fp16(acc[mt][nt], alfr[mt], bfr[nt]);
            }
        }
        __syncthreads();                 // all reads of stage c done before reload
    }

    // Epilogue
    const int erow = lane >> 2;
    const int ecol = (lane & 3) * 2;
    #pragma unroll
    for (int mt = 0; mt < 4; ++mt) {
        const int rA = rowBase + wm * 64 + mt * 16 + erow;
        #pragma unroll
        for (int nt = 0; nt < 4; ++nt) {
            const int col = colBase + wn * 32 + nt * 8 + ecol;
            const float b0 = bias[col], b1 = bias[col + 1];
            *(float2*)&C[(size_t)rA * N + col] =
                make_float2(acc[mt][nt][0] + b0, acc[mt][nt][1] + b1);
            *(float2*)&C[(size_t)(rA + 8) * N + col] =
                make_float2(acc[mt][nt][2] + b0, acc[mt][nt][3] + b1);
        }
    }
}

// ---------------------------------------------------------------------------
// Fused RMSNorm + K/V fp16 store. One warp per (token, slot).
// ---------------------------------------------------------------------------
__global__ __launch_bounds__(256) void rmskv_kernel(
    float* __restrict__ qkv,
    const float* __restrict__ qn_w, const float* __restrict__ kn_w,
    __half* __restrict__ ks, __half* __restrict__ vs)
{
    const int gwarp = (blockIdx.x * blockDim.x + threadIdx.x) >> 5;
    const int lane  = threadIdx.x & 31;
    const int token = gwarp >> 5;
    const int slot  = gwarp & 31;
    if (token >= TOKENS) return;

    const int h = slot & 15;

    if (slot < 16) {
        float* row = qkv + (size_t)token * QKVDIM + h * HDIM;
        float x0 = row[lane];
        float x1 = row[lane + 32];
        float ss = x0 * x0 + x1 * x1;
        #pragma unroll
        for (int off = 16; off; off >>= 1) ss += __shfl_xor_sync(0xffffffffu, ss, off);
        const float inv = rsqrtf(ss * (1.0f / 64.0f) + 1e-6f);
        row[lane]      = x0 * inv * qn_w[lane];
        row[lane + 32] = x1 * inv * qn_w[lane + 32];
    } else {
        const int b = token >> 11;
        const int n = token & 2047;
        const size_t dstRow = ((size_t)(b * HEADS + h) * SEQ + n) * 64;

        {   // K: rmsnorm + fp16
            const float* row = qkv + (size_t)token * QKVDIM + CDIM + h * HDIM;
            float x0 = row[lane];
            float x1 = row[lane + 32];
            float ss = x0 * x0 + x1 * x1;
            #pragma unroll
            for (int off = 16; off; off >>= 1) ss += __shfl_xor_sync(0xffffffffu, ss, off);
            const float inv = rsqrtf(ss * (1.0f / 64.0f) + 1e-6f);
            ks[dstRow + lane]      = __float2half_rn(x0 * inv * kn_w[lane]);
            ks[dstRow + lane + 32] = __float2half_rn(x1 * inv * kn_w[lane + 32]);
        }
        {   // V: fp16
            const float* row = qkv + (size_t)token * QKVDIM + 2 * CDIM + h * HDIM;
            vs[dstRow + lane]      = __float2half_rn(row[lane]);
            vs[dstRow + lane + 32] = __float2half_rn(row[lane + 32]);
        }
    }
}

// ---------------------------------------------------------------------------
// FlashAttention-2 style mma.sync fp16 attention. Bc=64, 4-stage pipeline,
// 2 CTAs/SM. Q, K, V, P all fp16 hi only (error model in round notes).
// CTA = 128 q-rows x (b,h); 8 warps x 16 rows. K/V tiles: 64 rows x 128B.
// ---------------------------------------------------------------------------
#define ATT_NT (SEQ / 64)             // 32 key tiles
#define ATT_TILE_B 8192               // one matrix tile: 64 rows * 128B
#define ATT_BUF_B  16384              // K + V per stage
#define ATT_STAGES 4
#define ATT_SMEM   (ATT_STAGES * ATT_BUF_B)   // 65536

__global__ __launch_bounds__(256, 2) void attn_mma_kernel(
    const float* __restrict__ qkv,
    const __half* __restrict__ ks, const __half* __restrict__ vs,
    __half* __restrict__ outA)
{
    extern __shared__ __align__(256) char sm[];
    const uint32_t smBase = smem_u32(sm);

    const int tid  = threadIdx.x;
    const int wq   = tid >> 5;
    const int lane = tid & 31;

    const int bh = blockIdx.y;
    const int b  = bh >> 4;
    const int h  = bh & 15;
    const int qBase = blockIdx.x * 128;

    // ---- Q fragments (fp16 hi), scale folded: 0.125 * log2(e) ----
    const float SC = 0.125f * 1.44269504088896340736f;
    uint32_t qh[4][4];
    {
        const float* qg = qkv + ((size_t)(b * SEQ + qBase + wq * 16)) * QKVDIM + h * HDIM;
        const int rr = lane >> 2;
        const int cb = (lane & 3) * 2;
        #pragma unroll
        for (int kd = 0; kd < 4; ++kd) {
            const int d0 = kd * 16;
            float2 v0 = *(const float2*)&qg[(size_t)rr * QKVDIM + d0 + cb];
            float2 v1 = *(const float2*)&qg[(size_t)(rr + 8) * QKVDIM + d0 + cb];
            float2 v2 = *(const float2*)&qg[(size_t)rr * QKVDIM + d0 + cb + 8];
            float2 v3 = *(const float2*)&qg[(size_t)(rr + 8) * QKVDIM + d0 + cb + 8];
            qh[kd][0] = h2pack(v0.x * SC, v0.y * SC);
            qh[kd][1] = h2pack(v1.x * SC, v1.y * SC);
            qh[kd][2] = h2pack(v2.x * SC, v2.y * SC);
            qh[kd][3] = h2pack(v3.x * SC, v3.y * SC);
        }
    }

    // ---- cp.async tile loader: 64 keys, K + V hi (128B rows, XOR swizzle) ----
    auto loadTile = [&](int kt, int st) {
        const __half* gk = ks + ((size_t)bh * SEQ + kt * 64) * 64;
        const __half* gv = vs + ((size_t)bh * SEQ + kt * 64) * 64;
        const uint32_t kb = smBase + st * ATT_BUF_B;
        const uint32_t vb = kb + ATT_TILE_B;
        #pragma unroll
        for (int m = 0; m < 2; ++m) {
            const int id = tid + m * 256;           // 0..511
            const int c = id >> 3, j = id & 7;
            const uint32_t soff = c * 128 + ((j ^ (c & 7)) << 4);
            cp_async16(kb + soff, gk + (size_t)c * 64 + j * 8);
            cp_async16(vb + soff, gv + (size_t)c * 64 + j * 8);
        }
        cp_commit();
    };

    float m0 = -CUDART_INF_F, m1 = -CUDART_INF_F, l0 = 0.0f, l1 = 0.0f;
    float O[8][4] = {};

    loadTile(0, 0);
    loadTile(1, 1);
    loadTile(2, 2);

    for (int kt = 0; kt < ATT_NT; ++kt) {
        const int st = kt & 3;
        if (kt + 2 < ATT_NT)      cp_wait2();
        else if (kt + 1 < ATT_NT) cp_wait1();
        else                      cp_wait0();
        __syncthreads();
        if (kt + 3 < ATT_NT) loadTile(kt + 3, (kt + 3) & 3);

        const uint32_t Kb = smBase + st * ATT_BUF_B;
        const uint32_t Vb = Kb + ATT_TILE_B;

        // ---- S = Qh K^T, 64 keys ----
        float S[8][4] = {};
        #pragma unroll
        for (int kd = 0; kd < 4; ++kd) {
            #pragma unroll
            for (int t = 0; t < 4; ++t) {
                const int row = 16 * t + (lane & 7) + 8 * ((lane >> 4) & 1);
                const int j = kd * 2 + ((lane >> 3) & 1);
                uint32_t r[4];
                ldsm_x4(r, Kb + row * 128 + ((j ^ (row & 7)) << 4));
                mma_fp16(S[2 * t],     qh[kd], r);
                mma_fp16(S[2 * t + 1], qh[kd], r + 2);
            }
        }

        // ---- Online softmax (base 2) ----
        float mt0 = -CUDART_INF_F, mt1 = -CUDART_INF_F;
        #pragma unroll
        for (int nc = 0; nc < 8; ++nc) {
            mt0 = fmaxf(mt0, fmaxf(S[nc][0], S[nc][1]));
            mt1 = fmaxf(mt1, fmaxf(S[nc][2], S[nc][3]));
        }
        mt0 = fmaxf(mt0, __shfl_xor_sync(0xffffffffu, mt0, 1));
        mt0 = fmaxf(mt0, __shfl_xor_sync(0xffffffffu, mt0, 2));
        mt1 = fmaxf(mt1, __shfl_xor_sync(0xffffffffu, mt1, 1));
        mt1 = fmaxf(mt1, __shfl_xor_sync(0xffffffffu, mt1, 2));
        const float mn0 = fmaxf(m0, mt0);
        const float mn1 = fmaxf(m1, mt1);
        const float c0 = ex2f(m0 - mn0);
        const float c1 = ex2f(m1 - mn1);
        m0 = mn0; m1 = mn1;
        float rs0 = 0.0f, rs1 = 0.0f;
        #pragma unroll
        for (int nc = 0; nc < 8; ++nc) {
            S[nc][0] = ex2f(S[nc][0] - mn0); rs0 += S[nc][0];
            S[nc][1] = ex2f(S[nc][1] - mn0); rs0 += S[nc][1];
            S[nc][2] = ex2f(S[nc][2] - mn1); rs1 += S[nc][2];
            S[nc][3] = ex2f(S[nc][3] - mn1); rs1 += S[nc][3];
        }
        rs0 += __shfl_xor_sync(0xffffffffu, rs0, 1);
        rs0 += __shfl_xor_sync(0xffffffffu, rs0, 2);
        rs1 += __shfl_xor_sync(0xffffffffu, rs1, 1);
        rs1 += __shfl_xor_sync(0xffffffffu, rs1, 2);
        l0 = l0 * c0 + rs0;
        l1 = l1 * c1 + rs1;
        #pragma unroll
        for (int nd = 0; nd < 8; ++nd) {
            O[nd][0] *= c0; O[nd][1] *= c0; O[nd][2] *= c1; O[nd][3] *= c1;
        }

        // ---- O += P V (P fp16 hi only), 4 k16 chunks ----
        #pragma unroll
        for (int kc = 0; kc < 4; ++kc) {
            uint32_t ph[4];
            {
                const float* s0 = S[2 * kc];
                const float* s1 = S[2 * kc + 1];
                ph[0] = h2pack(s0[0], s0[1]);
                ph[1] = h2pack(s0[2], s0[3]);
                ph[2] = h2pack(s1[0], s1[1]);
                ph[3] = h2pack(s1[2], s1[3]);
            }
            #pragma unroll
            for (int t = 0; t < 4; ++t) {
                const int row = kc * 16 + (lane & 7) + 8 * ((lane >> 3) & 1);
                const int j = 2 * t + ((lane >> 4) & 1);
                uint32_t r[4];
                ldsm_x4_t(r, Vb + row * 128 + ((j ^ (row & 7)) << 4));
                mma_fp16(O[2 * t],     ph, r);
                mma_fp16(O[2 * t + 1], ph, r + 2);
            }
        }
    }

    // ---- Epilogue: normalize, write fp16 hi/lo split rows to outA ----
    const float inv0 = 1.0f / l0;
    const float inv1 = 1.0f / l1;
    const size_t row1 = (size_t)b * SEQ + qBase + wq * 16 + (lane >> 2);
    const int colBase = h * HDIM + (lane & 3) * 2;
    #pragma unroll
    for (int nd = 0; nd < 8; ++nd) {
        const int col = colBase + nd * 8;
        {
            const float x = O[nd][0] * inv0, y = O[nd][1] * inv0;
            __half* p = outA + row1 * KA + col;
            const uint32_t hp = h2pack(x, y);
            *(uint32_t*)p = hp;
            *(uint32_t*)(p + 1024) = h2pack_lo(x, y, hp);
        }
        {
            const float x = O[nd][2] * inv1, y = O[nd][3] * inv1;
            __half* p = outA + (row1 + 8) * KA + col;
            const uint32_t hp = h2pack(x, y);
            *(uint32_t*)p = hp;
            *(uint32_t*)(p + 1024) = h2pack_lo(x, y, hp);
        }
    }
}

// ---------------------------------------------------------------------------
// Launch
// ---------------------------------------------------------------------------
extern "C" void kernel_launch(void* const* d_in, const int* in_sizes, int n_in,
                              void* d_out, int out_size)
{
    (void)in_sizes; (void)n_in; (void)out_size;
    const float* x      = (const float*)d_in[0];
    const float* W_qkv  = (const float*)d_in[1];
    const float* b_qkv  = (const float*)d_in[2];
    const float* W_proj = (const float*)d_in[3];
    const float* b_proj = (const float*)d_in[4];
    const float* qn_w   = (const float*)d_in[5];
    const float* kn_w   = (const float*)d_in[6];
    float* out = (float*)d_out;

    float *qkv = nullptr;
    __half *A1 = nullptr, *B1 = nullptr, *B2 = nullptr, *A2 = nullptr;
    __half *ksp = nullptr, *vsp = nullptr;
    cudaGetSymbolAddress((void**)&qkv, g_qkv);
    cudaGetSymbolAddress((void**)&A1,  g_A1);
    cudaGetSymbolAddress((void**)&B1,  g_B1);
    cudaGetSymbolAddress((void**)&B2,  g_B2);
    cudaGetSymbolAddress((void**)&A2,  g_A2);
    cudaGetSymbolAddress((void**)&ksp, g_ks);
    cudaGetSymbolAddress((void**)&vsp, g_vs);

    cudaFuncSetAttribute(gemm_mma_kernel, cudaFuncAttributeMaxDynamicSharedMemorySize, G_SMEM);
    cudaFuncSetAttribute(attn_mma_kernel, cudaFuncAttributeMaxDynamicSharedMemorySize, ATT_SMEM);

    // 0) Conversions to fp16 formats
    convX_kernel<<<(TOKENS * CDIM) / 256, 256>>>(x, A1);
    convW_kernel<<<dim3(QKVDIM / 32, CDIM / 32), 256>>>(W_qkv, B1, QKVDIM);
    convW_kernel<<<dim3(CDIM / 32, CDIM / 32), 256>>>(W_proj, B2, CDIM);

    // 1) QKV projection: lo-term only for Q columns (K/V truncated to fp16 anyway)
    gemm_mma_kernel<<<dim3(QKVDIM / BN, TOKENS / BM), 256, G_SMEM>>>(
        A1, B1, b_qkv, qkv, QKVDIM, CDIM);

    // 2) Fused RMSNorm (q in place, k) + K/V fp16 store
    rmskv_kernel<<<(TOKENS * 32) / 8, 256>>>(qkv, qn_w, kn_w, ksp, vsp);

    // 3) Attention (tensor cores) -> g_A2 (fp16 hi/lo, proj-ready)
    attn_mma_kernel<<<dim3(SEQ / 128, BATCH * HEADS), 256, ATT_SMEM>>>(qkv, ksp, vsp, A2);

    // 4) Output projection: full hi+lo everywhere (fp32 output)
    gemm_mma_kernel<<<dim3(CDIM / BN, TOKENS / BM), 256, G_SMEM>>>(
        A2, B2, b_proj, out, CDIM, CDIM);
}

// round 13
// speedup vs baseline: 8.1391x; 1.1262x over previous
#include <cuda_runtime.h>
#include <cuda_fp16.h>
#include <math_constants.h>
#include <cstdint>

// Problem constants
#define BATCH 4
#define SEQ   2048
#define CDIM  1024
#define HEADS 16
#define HDIM  64
#define TOKENS (BATCH * SEQ)         // 8192
#define QKVDIM (3 * CDIM)            // 3072
#define KA    2048                   // x split stride (hi|lo)
#define KB    1024                   // hi-only K

// ---------------------------------------------------------------------------
// Scratch (device globals — no allocation allowed)
// ---------------------------------------------------------------------------
__device__ float g_qkv[(size_t)TOKENS * QKVDIM];                    // QKV output fp32
__device__ __align__(256) __half g_A1[(size_t)TOKENS * KA];        // x split      [m, hi|lo]
__device__ __align__(256) __half g_B1[(size_t)QKVDIM * KB];        // W_qkv^T hi   [n, k]
__device__ __align__(256) __half g_B2[(size_t)CDIM * KB];          // W_proj^T hi
__device__ __align__(256) __half g_A2[(size_t)TOKENS * KB];        // attn out hi  [m, k]
__device__ __align__(256) __half g_ks[(size_t)BATCH * HEADS * SEQ * 64]; // K hi [bh, n, d]
__device__ __align__(256) __half g_vs[(size_t)BATCH * HEADS * SEQ * 64]; // V hi

// ---------------------------------------------------------------------------
// PTX helpers (portable sm_80+ features only)
// ---------------------------------------------------------------------------
__device__ __forceinline__ uint32_t smem_u32(const void* p) {
    uint32_t a;
    asm("{ .reg .u64 t; cvta.to.shared.u64 t, %1; cvt.u32.u64 %0, t; }" : "=r"(a) : "l"(p));
    return a;
}
__device__ __forceinline__ void cp_async16(uint32_t dst, const void* src) {
    asm volatile("cp.async.cg.shared.global [%0], [%1], 16;" :: "r"(dst), "l"(src));
}
__device__ __forceinline__ void cp_commit() {
    asm volatile("cp.async.commit_group;" ::: "memory");
}
__device__ __forceinline__ void cp_wait0() {
    asm volatile("cp.async.wait_group 0;" ::: "memory");
}
__device__ __forceinline__ void cp_wait1() {
    asm volatile("cp.async.wait_group 1;" ::: "memory");
}
__device__ __forceinline__ void cp_wait2() {
    asm volatile("cp.async.wait_group 2;" ::: "memory");
}
__device__ __forceinline__ void ldsm_x4(uint32_t* r, uint32_t addr) {
    asm volatile("ldmatrix.sync.aligned.m8n8.x4.shared.b16 {%0,%1,%2,%3}, [%4];"
                 : "=r"(r[0]), "=r"(r[1]), "=r"(r[2]), "=r"(r[3]) : "r"(addr));
}
__device__ __forceinline__ void ldsm_x4_t(uint32_t* r, uint32_t addr) {
    asm volatile("ldmatrix.sync.aligned.m8n8.x4.trans.shared.b16 {%0,%1,%2,%3}, [%4];"
                 : "=r"(r[0]), "=r"(r[1]), "=r"(r[2]), "=r"(r[3]) : "r"(addr));
}
__device__ __forceinline__ void mma_fp16(float* c, const uint32_t* a, const uint32_t* b) {
    asm volatile(
        "mma.sync.aligned.m16n8k16.row.col.f32.f16.f16.f32 "
        "{%0,%1,%2,%3}, {%4,%5,%6,%7}, {%8,%9}, {%0,%1,%2,%3};"
        : "+f"(c[0]), "+f"(c[1]), "+f"(c[2]), "+f"(c[3])
        : "r"(a[0]), "r"(a[1]), "r"(a[2]), "r"(a[3]), "r"(b[0]), "r"(b[1]));
}
__device__ __forceinline__ float ex2f(float x) {
    float y; asm("ex2.approx.ftz.f32 %0, %1;" : "=f"(y) : "f"(x)); return y;
}
__device__ __forceinline__ uint32_t h2pack(float a, float b) {
    __half2 h;
    h.x = __float2half_rn(a);
    h.y = __float2half_rn(b);
    return *(uint32_t*)&h;
}

// ---------------------------------------------------------------------------
// Conversion kernels (fp32 -> fp16 hi/lo split)
// ---------------------------------------------------------------------------
__global__ __launch_bounds__(256) void convX_kernel(const float* __restrict__ x,
                                                    __half* __restrict__ A)
{
    const int idx = blockIdx.x * 256 + threadIdx.x;      // over TOKENS*CDIM
    const int m = idx >> 10;
    const int k = idx & 1023;
    const float v = x[idx];
    const __half hi = __float2half_rn(v);
    __half* row = A + (size_t)m * KA;
    row[k]        = hi;
    row[1024 + k] = __float2half_rn(v - __half2float(hi));
}

// Transpose: W [K=1024, N] fp32 -> B [N, 1024] fp16 (hi only)
__global__ __launch_bounds__(256) void convW_kernel(const float* __restrict__ W,
                                                    __half* __restrict__ B, int N)
{
    __shared__ float t[32][33];
    const int n0 = blockIdx.x * 32;
    const int k0 = blockIdx.y * 32;
    const int tx = threadIdx.x & 31;
    const int ty = threadIdx.x >> 5;          // 0..7
    #pragma unroll
    for (int i = 0; i < 4; ++i)
        t[ty + 8 * i][tx] = W[(size_t)(k0 + ty + 8 * i) * N + n0 + tx];
    __syncthreads();
    #pragma unroll
    for (int i = 0; i < 4; ++i) {
        const int n = n0 + ty + 8 * i;
        const int k = k0 + tx;
        B[(size_t)n * KB + k] = __float2half_rn(t[tx][ty + 8 * i]);
    }
}

// ---------------------------------------------------------------------------
// mma.sync fp16 GEMM:  C[M,N] = (A_hi [+ A_lo]) @ B_hi^T + bias
// lo-term only for output columns < loN (CTA-uniform); A row stride = strideA,
// lo plane at fixed +1024 offset (valid only when useLo).
// ---------------------------------------------------------------------------
#define BM 128
#define BN 128
#define BK 64
#define G_REGION (BM * BK * 2)           // 16384 bytes per matrix region
#define G_STAGE_BYTES (3 * G_REGION)     // 49152 (Ahi + Alo + B)
#define G_SMEM (2 * G_STAGE_BYTES)       // 98304
#define NCHUNKG (KB / BK)                // 16

__global__ __launch_bounds__(256, 2) void gemm_mma_kernel(
    const __half* __restrict__ A, const __half* __restrict__ Bm,
    const float* __restrict__ bias, float* __restrict__ C, int N, int loN,
    int strideA)
{
    extern __shared__ __align__(256) char gsm[];
    const uint32_t base = smem_u32(gsm);

    const int tid  = threadIdx.x;
    const int wid  = tid >> 5;
    const int lane = tid & 31;
    const int wm   = wid >> 2;           // 0..1
    const int wn   = wid & 3;            // 0..3
    const int rowBase = blockIdx.y * BM;
    const int colBase = blockIdx.x * BN;
    const bool useLo = (colBase < loN);  // CTA-uniform

    float acc[4][4][4] = {};

    const int lrow = tid >> 3;           // 0..31 (x4 via +32)
    const int lch  = tid & 7;

    auto loadStage = [&](int c, int s) {
        const __half* Ah = A + (size_t)rowBase * strideA + c * BK;     // hi cols
        const __half* Al = Ah + 1024;                                   // lo cols
        const __half* Bg = Bm + (size_t)colBase * KB + c * BK;
        const uint32_t st = base + s * G_STAGE_BYTES;
        #pragma unroll
        for (int m = 0; m < 4; ++m) {
            const int row = lrow + m * 32;
            const uint32_t soff = row * 128 + ((lch ^ (row & 7)) << 4);
            cp_async16(st + soff,                Ah + (size_t)row * strideA + lch * 8);
            if (useLo)
                cp_async16(st + G_REGION + soff, Al + (size_t)row * strideA + lch * 8);
            cp_async16(st + 2 * G_REGION + soff, Bg + (size_t)row * KB + lch * 8);
        }
        cp_commit();
    };

    loadStage(0, 0);

    for (int c = 0; c < NCHUNKG; ++c) {
        cp_wait0();
        __syncthreads();                 // chunk c visible; compute of c-1 done everywhere
        if (c + 1 < NCHUNKG) loadStage(c + 1, (c + 1) & 1);

        const uint32_t st = base + (c & 1) * G_STAGE_BYTES;
        const uint32_t ahs = st;
        const uint32_t als = st + G_REGION;
        const uint32_t bsb = st + 2 * G_REGION;

        #pragma unroll
        for (int ks = 0; ks < 4; ++ks) {
            const int arow = wm * 64 + (lane & 15);
            const int ach  = ks * 2 + (lane >> 4);
            uint32_t ahfr[4][4], alfr[4][4];
            #pragma unroll
            for (int mt = 0; mt < 4; ++mt) {
                const int row = arow + mt * 16;
                const uint32_t off = row * 128 + ((ach ^ (row & 7)) << 4);
                ldsm_x4(ahfr[mt], ahs + off);
                if (useLo) ldsm_x4(alfr[mt], als + off);
            }
            uint32_t bfr[4][2];
            #pragma unroll
            for (int ntp = 0; ntp < 2; ++ntp) {
                const int row = wn * 32 + ntp * 16 + (lane & 7) + ((lane >> 4) << 3);
                const int ch  = ks * 2 + ((lane >> 3) & 1);
                uint32_t r[4];
                ldsm_x4(r, bsb + row * 128 + ((ch ^ (row & 7)) << 4));
                bfr[2 * ntp][0]     = r[0]; bfr[2 * ntp][1]     = r[1];
                bfr[2 * ntp + 1][0] = r[2]; bfr[2 * ntp + 1][1] = r[3];
            }
            #pragma unroll
            for (int mt = 0; mt < 4; ++mt)
                #pragma unroll
                for (int nt = 0; nt < 4; ++nt)
                    mma_fp16(acc[mt][nt], ahfr[mt], bfr[nt]);
            if (useLo) {
                #pragma unroll
                for (int mt = 0; mt < 4; ++mt)
                    #pragma unroll
                    for (int nt = 0; nt < 4; ++nt)
                        mma_fp16(acc[mt][nt], alfr[mt], bfr[nt]);
            }
        }
        __syncthreads();                 // all reads of stage c done before reload
    }

    // Epilogue
    const int erow = lane >> 2;
    const int ecol = (lane & 3) * 2;
    #pragma unroll
    for (int mt = 0; mt < 4; ++mt) {
        const int rA = rowBase + wm * 64 + mt * 16 + erow;
        #pragma unroll
        for (int nt = 0; nt < 4; ++nt) {
            const int col = colBase + wn * 32 + nt * 8 + ecol;
            const float b0 = bias[col], b1 = bias[col + 1];
            *(float2*)&C[(size_t)rA * N + col] =
                make_float2(acc[mt][nt][0] + b0, acc[mt][nt][1] + b1);
            *(float2*)&C[(size_t)(rA + 8) * N + col] =
                make_float2(acc[mt][nt][2] + b0, acc[mt][nt][3] + b1);
        }
    }
}

// ---------------------------------------------------------------------------
// K/V prep: K rmsnorm + fp16 store, V fp16 store. One warp per (token, head).
// (Q rmsnorm is fused into the attention kernel's Q load.)
// ---------------------------------------------------------------------------
__global__ __launch_bounds__(256) void rmskv_kernel(
    const float* __restrict__ qkv,
    const float* __restrict__ kn_w,
    __half* __restrict__ ks, __half* __restrict__ vs)
{
    const int gwarp = (blockIdx.x * blockDim.x + threadIdx.x) >> 5;
    const int lane  = threadIdx.x & 31;
    const int token = gwarp >> 4;
    const int h     = gwarp & 15;
    if (token >= TOKENS) return;

    const int b = token >> 11;
    const int n = token & 2047;
    const size_t dstRow = ((size_t)(b * HEADS + h) * SEQ + n) * 64;

    {   // K: rmsnorm + fp16
        const float* row = qkv + (size_t)token * QKVDIM + CDIM + h * HDIM;
        float x0 = row[lane];
        float x1 = row[lane + 32];
        float ss = x0 * x0 + x1 * x1;
        #pragma unroll
        for (int off = 16; off; off >>= 1) ss += __shfl_xor_sync(0xffffffffu, ss, off);
        const float inv = rsqrtf(ss * (1.0f / 64.0f) + 1e-6f);
        ks[dstRow + lane]      = __float2half_rn(x0 * inv * kn_w[lane]);
        ks[dstRow + lane + 32] = __float2half_rn(x1 * inv * kn_w[lane + 32]);
    }
    {   // V: fp16
        const float* row = qkv + (size_t)token * QKVDIM + 2 * CDIM + h * HDIM;
        vs[dstRow + lane]      = __float2half_rn(row[lane]);
        vs[dstRow + lane + 32] = __float2half_rn(row[lane + 32]);
    }
}

// ---------------------------------------------------------------------------
// FlashAttention-2 style mma.sync fp16 attention. Bc=64, 4-stage pipeline,
// 2 CTAs/SM. Q rmsnorm fused into the Q load; Q, K, V, P all fp16 hi.
// CTA = 128 q-rows x (b,h); 8 warps x 16 rows. K/V tiles: 64 rows x 128B.
// ---------------------------------------------------------------------------
#define ATT_NT (SEQ / 64)             // 32 key tiles
#define ATT_TILE_B 8192               // one matrix tile: 64 rows * 128B
#define ATT_BUF_B  16384              // K + V per stage
#define ATT_STAGES 4
#define ATT_SMEM   (ATT_STAGES * ATT_BUF_B)   // 65536

__global__ __launch_bounds__(256, 2) void attn_mma_kernel(
    const float* __restrict__ qkv, const float* __restrict__ qn_w,
    const __half* __restrict__ ks, const __half* __restrict__ vs,
    __half* __restrict__ outA)
{
    extern __shared__ __align__(256) char sm[];
    const uint32_t smBase = smem_u32(sm);

    const int tid  = threadIdx.x;
    const int wq   = tid >> 5;
    const int lane = tid & 31;

    const int bh = blockIdx.y;
    const int b  = bh >> 4;
    const int h  = bh & 15;
    const int qBase = blockIdx.x * 128;

    // ---- Q load + fused RMSNorm + fp16 pack, scale folded: 0.125*log2(e) ----
    // Row rr (=lane>>2) is spread over lanes (rr*4..rr*4+3); reduce ss via
    // shfl xor 1,2. Row rr+8 likewise from the v1/v3 elements.
    const float SC = 0.125f * 1.44269504088896340736f;
    uint32_t qh[4][4];
    {
        const float* qg = qkv + ((size_t)(b * SEQ + qBase + wq * 16)) * QKVDIM + h * HDIM;
        const int rr = lane >> 2;
        const int cb = (lane & 3) * 2;
        float2 v0[4], v1[4], v2[4], v3[4];
        float ssa = 0.0f, ssb = 0.0f;
        #pragma unroll
        for (int kd = 0; kd < 4; ++kd) {
            const int d0 = kd * 16;
            v0[kd] = *(const float2*)&qg[(size_t)rr * QKVDIM + d0 + cb];
            v1[kd] = *(const float2*)&qg[(size_t)(rr + 8) * QKVDIM + d0 + cb];
            v2[kd] = *(const float2*)&qg[(size_t)rr * QKVDIM + d0 + cb + 8];
            v3[kd] = *(const float2*)&qg[(size_t)(rr + 8) * QKVDIM + d0 + cb + 8];
            ssa += v0[kd].x * v0[kd].x + v0[kd].y * v0[kd].y
                 + v2[kd].x * v2[kd].x + v2[kd].y * v2[kd].y;
            ssb += v1[kd].x * v1[kd].x + v1[kd].y * v1[kd].y
                 + v3[kd].x * v3[kd].x + v3[kd].y * v3[kd].y;
        }
        ssa += __shfl_xor_sync(0xffffffffu, ssa, 1);
        ssa += __shfl_xor_sync(0xffffffffu, ssa, 2);
        ssb += __shfl_xor_sync(0xffffffffu, ssb, 1);
        ssb += __shfl_xor_sync(0xffffffffu, ssb, 2);
        const float ia = rsqrtf(ssa * (1.0f / 64.0f) + 1e-6f) * SC;
        const float ib = rsqrtf(ssb * (1.0f / 64.0f) + 1e-6f) * SC;
        #pragma unroll
        for (int kd = 0; kd < 4; ++kd) {
            const int d0 = kd * 16;
            const float2 w0 = *(const float2*)&qn_w[d0 + cb];
            const float2 w1 = *(const float2*)&qn_w[d0 + cb + 8];
            qh[kd][0] = h2pack(v0[kd].x * ia * w0.x, v0[kd].y * ia * w0.y);
            qh[kd][1] = h2pack(v1[kd].x * ib * w0.x, v1[kd].y * ib * w0.y);
            qh[kd][2] = h2pack(v2[kd].x * ia * w1.x, v2[kd].y * ia * w1.y);
            qh[kd][3] = h2pack(v3[kd].x * ib * w1.x, v3[kd].y * ib * w1.y);
        }
    }

    // ---- cp.async tile loader: 64 keys, K + V hi (128B rows, XOR swizzle) ----
    auto loadTile = [&](int kt, int st) {
        const __half* gk = ks + ((size_t)bh * SEQ + kt * 64) * 64;
        const __half* gv = vs + ((size_t)bh * SEQ + kt * 64) * 64;
        const uint32_t kb = smBase + st * ATT_BUF_B;
        const uint32_t vb = kb + ATT_TILE_B;
        #pragma unroll
        for (int m = 0; m < 2; ++m) {
            const int id = tid + m * 256;           // 0..511
            const int c = id >> 3, j = id & 7;
            const uint32_t soff = c * 128 + ((j ^ (c & 7)) << 4);
            cp_async16(kb + soff, gk + (size_t)c * 64 + j * 8);
            cp_async16(vb + soff, gv + (size_t)c * 64 + j * 8);
        }
        cp_commit();
    };

    float m0 = -CUDART_INF_F, m1 = -CUDART_INF_F, l0 = 0.0f, l1 = 0.0f;
    float O[8][4] = {};

    loadTile(0, 0);
    loadTile(1, 1);
    loadTile(2, 2);

    for (int kt = 0; kt < ATT_NT; ++kt) {
        const int st = kt & 3;
        if (kt + 2 < ATT_NT)      cp_wait2();
        else if (kt + 1 < ATT_NT) cp_wait1();
        else                      cp_wait0();
        __syncthreads();
        if (kt + 3 < ATT_NT) loadTile(kt + 3, (kt + 3) & 3);

        const uint32_t Kb = smBase + st * ATT_BUF_B;
        const uint32_t Vb = Kb + ATT_TILE_B;

        // ---- S = Qh K^T, 64 keys ----
        float S[8][4] = {};
        #pragma unroll
        for (int kd = 0; kd < 4; ++kd) {
            #pragma unroll
            for (int t = 0; t < 4; ++t) {
                const int row = 16 * t + (lane & 7) + 8 * ((lane >> 4) & 1);
                const int j = kd * 2 + ((lane >> 3) & 1);
                uint32_t r[4];
                ldsm_x4(r, Kb + row * 128 + ((j ^ (row & 7)) << 4));
                mma_fp16(S[2 * t],     qh[kd], r);
                mma_fp16(S[2 * t + 1], qh[kd], r + 2);
            }
        }

        // ---- Online softmax (base 2) ----
        float mt0 = -CUDART_INF_F, mt1 = -CUDART_INF_F;
        #pragma unroll
        for (int nc = 0; nc < 8; ++nc) {
            mt0 = fmaxf(mt0, fmaxf(S[nc][0], S[nc][1]));
            mt1 = fmaxf(mt1, fmaxf(S[nc][2], S[nc][3]));
        }
        mt0 = fmaxf(mt0, __shfl_xor_sync(0xffffffffu, mt0, 1));
        mt0 = fmaxf(mt0, __shfl_xor_sync(0xffffffffu, mt0, 2));
        mt1 = fmaxf(mt1, __shfl_xor_sync(0xffffffffu, mt1, 1));
        mt1 = fmaxf(mt1, __shfl_xor_sync(0xffffffffu, mt1, 2));
        const float mn0 = fmaxf(m0, mt0);
        const float mn1 = fmaxf(m1, mt1);
        const float c0 = ex2f(m0 - mn0);
        const float c1 = ex2f(m1 - mn1);
        m0 = mn0; m1 = mn1;
        float rs0 = 0.0f, rs1 = 0.0f;
        #pragma unroll
        for (int nc = 0; nc < 8; ++nc) {
            S[nc][0] = ex2f(S[nc][0] - mn0); rs0 += S[nc][0];
            S[nc][1] = ex2f(S[nc][1] - mn0); rs0 += S[nc][1];
            S[nc][2] = ex2f(S[nc][2] - mn1); rs1 += S[nc][2];
            S[nc][3] = ex2f(S[nc][3] - mn1); rs1 += S[nc][3];
        }
        rs0 += __shfl_xor_sync(0xffffffffu, rs0, 1);
        rs0 += __shfl_xor_sync(0xffffffffu, rs0, 2);
        rs1 += __shfl_xor_sync(0xffffffffu, rs1, 1);
        rs1 += __shfl_xor_sync(0xffffffffu, rs1, 2);
        l0 = l0 * c0 + rs0;
        l1 = l1 * c1 + rs1;
        #pragma unroll
        for (int nd = 0; nd < 8; ++nd) {
            O[nd][0] *= c0; O[nd][1] *= c0; O[nd][2] *= c1; O[nd][3] *= c1;
        }

        // ---- O += P V (P fp16 hi only), 4 k16 chunks ----
        #pragma unroll
        for (int kc = 0; kc < 4; ++kc) {
            uint32_t ph[4];
            {
                const float* s0 = S[2 * kc];
                const float* s1 = S[2 * kc + 1];
                ph[0] = h2pack(s0[0], s0[1]);
                ph[1] = h2pack(s0[2], s0[3]);
                ph[2] = h2pack(s1[0], s1[1]);
                ph[3] = h2pack(s1[2], s1[3]);
            }
            #pragma unroll
            for (int t = 0; t < 4; ++t) {
                const int row = kc * 16 + (lane & 7) + 8 * ((lane >> 3) & 1);
                const int j = 2 * t + ((lane >> 4) & 1);
                uint32_t r[4];
                ldsm_x4_t(r, Vb + row * 128 + ((j ^ (row & 7)) << 4));
                mma_fp16(O[2 * t],     ph, r);
                mma_fp16(O[2 * t + 1], ph, r + 2);
            }
        }
    }

    // ---- Epilogue: normalize, write fp16 hi rows to outA (stride KB) ----
    const float inv0 = 1.0f / l0;
    const float inv1 = 1.0f / l1;
    const size_t row1 = (size_t)b * SEQ + qBase + wq * 16 + (lane >> 2);
    const int colBase = h * HDIM + (lane & 3) * 2;
    #pragma unroll
    for (int nd = 0; nd < 8; ++nd) {
        const int col = colBase + nd * 8;
        *(uint32_t*)(outA + row1 * KB + col) =
            h2pack(O[nd][0] * inv0, O[nd][1] * inv0);
        *(uint32_t*)(outA + (row1 + 8) * KB + col) =
            h2pack(O[nd][2] * inv1, O[nd][3] * inv1);
    }
}

// ---------------------------------------------------------------------------
// Launch
// ---------------------------------------------------------------------------
extern "C" void kernel_launch(void* const* d_in, const int* in_sizes, int n_in,
                              void* d_out, int out_size)
{
    (void)in_sizes; (void)n_in; (void)out_size;
    const float* x      = (const float*)d_in[0];
    const float* W_qkv  = (const float*)d_in[1];
    const float* b_qkv  = (const float*)d_in[2];
    const float* W_proj = (const float*)d_in[3];
    const float* b_proj = (const float*)d_in[4];
    const float* qn_w   = (const float*)d_in[5];
    const float* kn_w   = (const float*)d_in[6];
    float* out = (float*)d_out;

    float *qkv = nullptr;
    __half *A1 = nullptr, *B1 = nullptr, *B2 = nullptr, *A2 = nullptr;
    __half *ksp = nullptr, *vsp = nullptr;
    cudaGetSymbolAddress((void**)&qkv, g_qkv);
    cudaGetSymbolAddress((void**)&A1,  g_A1);
    cudaGetSymbolAddress((void**)&B1,  g_B1);
    cudaGetSymbolAddress((void**)&B2,  g_B2);
    cudaGetSymbolAddress((void**)&A2,  g_A2);
    cudaGetSymbolAddress((void**)&ksp, g_ks);
    cudaGetSymbolAddress((void**)&vsp, g_vs);

    cudaFuncSetAttribute(gemm_mma_kernel, cudaFuncAttributeMaxDynamicSharedMemorySize, G_SMEM);
    cudaFuncSetAttribute(attn_mma_kernel, cudaFuncAttributeMaxDynamicSharedMemorySize, ATT_SMEM);

    // 0) Conversions to fp16 formats
    convX_kernel<<<(TOKENS * CDIM) / 256, 256>>>(x, A1);
    convW_kernel<<<dim3(QKVDIM / 32, CDIM / 32), 256>>>(W_qkv, B1, QKVDIM);
    convW_kernel<<<dim3(CDIM / 32, CDIM / 32), 256>>>(W_proj, B2, CDIM);

    // 1) QKV projection: lo-term only for Q columns (K/V truncated to fp16 anyway)
    gemm_mma_kernel<<<dim3(QKVDIM / BN, TOKENS / BM), 256, G_SMEM>>>(
        A1, B1, b_qkv, qkv, QKVDIM, CDIM, KA);

    // 2) K rmsnorm + K/V fp16 store (Q rmsnorm fused into attention)
    rmskv_kernel<<<(TOKENS * 16) / 8, 256>>>(qkv, kn_w, ksp, vsp);

    // 3) Attention (tensor cores, fused Q rmsnorm) -> g_A2 (fp16 hi)
    attn_mma_kernel<<<dim3(SEQ / 128, BATCH * HEADS), 256, ATT_SMEM>>>(
        qkv, qn_w, ksp, vsp, A2);

    // 4) Output projection: A2 hi-only (stride 1024)
    gemm_mma_kernel<<<dim3(CDIM / BN, TOKENS / BM), 256, G_SMEM>>>(
        A2, B2, b_proj, out, CDIM, 0, KB);
}

// round 14
// speedup vs baseline: 8.8093x; 1.0823x over previous
#include <cuda_runtime.h>
#include <cuda_fp16.h>
#include <math_constants.h>
#include <cstdint>

// Problem constants
#define BATCH 4
#define SEQ   2048
#define CDIM  1024
#define HEADS 16
#define HDIM  64
#define TOKENS (BATCH * SEQ)         // 8192
#define QKVDIM (3 * CDIM)            // 3072
#define KB    1024                   // hi-only K

// ---------------------------------------------------------------------------
// Scratch (device globals — no allocation allowed)
// ---------------------------------------------------------------------------
__device__ float g_qkv[(size_t)TOKENS * QKVDIM];                    // QKV output fp32
__device__ __align__(256) __half g_A1[(size_t)TOKENS * KB];        // x hi        [m, k]
__device__ __align__(256) __half g_B1[(size_t)QKVDIM * KB];        // W_qkv^T hi  [n, k]
__device__ __align__(256) __half g_B2[(size_t)CDIM * KB];          // W_proj^T hi
__device__ __align__(256) __half g_A2[(size_t)TOKENS * KB];        // attn out hi [m, k]
__device__ __align__(256) __half g_ks[(size_t)BATCH * HEADS * SEQ * 64]; // K hi [bh, n, d]
__device__ __align__(256) __half g_vs[(size_t)BATCH * HEADS * SEQ * 64]; // V hi

// ---------------------------------------------------------------------------
// PTX helpers (portable sm_80+ features only)
// ---------------------------------------------------------------------------
__device__ __forceinline__ uint32_t smem_u32(const void* p) {
    uint32_t a;
    asm("{ .reg .u64 t; cvta.to.shared.u64 t, %1; cvt.u32.u64 %0, t; }" : "=r"(a) : "l"(p));
    return a;
}
__device__ __forceinline__ void cp_async16(uint32_t dst, const void* src) {
    asm volatile("cp.async.cg.shared.global [%0], [%1], 16;" :: "r"(dst), "l"(src));
}
__device__ __forceinline__ void cp_commit() {
    asm volatile("cp.async.commit_group;" ::: "memory");
}
__device__ __forceinline__ void cp_wait0() {
    asm volatile("cp.async.wait_group 0;" ::: "memory");
}
__device__ __forceinline__ void cp_wait1() {
    asm volatile("cp.async.wait_group 1;" ::: "memory");
}
__device__ __forceinline__ void cp_wait2() {
    asm volatile("cp.async.wait_group 2;" ::: "memory");
}
__device__ __forceinline__ void ldsm_x4(uint32_t* r, uint32_t addr) {
    asm volatile("ldmatrix.sync.aligned.m8n8.x4.shared.b16 {%0,%1,%2,%3}, [%4];"
                 : "=r"(r[0]), "=r"(r[1]), "=r"(r[2]), "=r"(r[3]) : "r"(addr));
}
__device__ __forceinline__ void ldsm_x4_t(uint32_t* r, uint32_t addr) {
    asm volatile("ldmatrix.sync.aligned.m8n8.x4.trans.shared.b16 {%0,%1,%2,%3}, [%4];"
                 : "=r"(r[0]), "=r"(r[1]), "=r"(r[2]), "=r"(r[3]) : "r"(addr));
}
__device__ __forceinline__ void mma_fp16(float* c, const uint32_t* a, const uint32_t* b) {
    asm volatile(
        "mma.sync.aligned.m16n8k16.row.col.f32.f16.f16.f32 "
        "{%0,%1,%2,%3}, {%4,%5,%6,%7}, {%8,%9}, {%0,%1,%2,%3};"
        : "+f"(c[0]), "+f"(c[1]), "+f"(c[2]), "+f"(c[3])
        : "r"(a[0]), "r"(a[1]), "r"(a[2]), "r"(a[3]), "r"(b[0]), "r"(b[1]));
}
__device__ __forceinline__ float ex2f(float x) {
    float y; asm("ex2.approx.ftz.f32 %0, %1;" : "=f"(y) : "f"(x)); return y;
}
__device__ __forceinline__ uint32_t h2pack(float a, float b) {
    __half2 h;
    h.x = __float2half_rn(a);
    h.y = __float2half_rn(b);
    return *(uint32_t*)&h;
}

// ---------------------------------------------------------------------------
// Conversion kernels (fp32 -> fp16 hi)
// ---------------------------------------------------------------------------
__global__ __launch_bounds__(256) void convX_kernel(const float* __restrict__ x,
                                                    __half* __restrict__ A)
{
    const int idx = blockIdx.x * 256 + threadIdx.x;      // over TOKENS*CDIM
    A[idx] = __float2half_rn(x[idx]);
}

// Transpose: W [K=1024, N] fp32 -> B [N, 1024] fp16 (hi only)
__global__ __launch_bounds__(256) void convW_kernel(const float* __restrict__ W,
                                                    __half* __restrict__ B, int N)
{
    __shared__ float t[32][33];
    const int n0 = blockIdx.x * 32;
    const int k0 = blockIdx.y * 32;
    const int tx = threadIdx.x & 31;
    const int ty = threadIdx.x >> 5;          // 0..7
    #pragma unroll
    for (int i = 0; i < 4; ++i)
        t[ty + 8 * i][tx] = W[(size_t)(k0 + ty + 8 * i) * N + n0 + tx];
    __syncthreads();
    #pragma unroll
    for (int i = 0; i < 4; ++i) {
        const int n = n0 + ty + 8 * i;
        const int k = k0 + tx;
        B[(size_t)n * KB + k] = __float2half_rn(t[tx][ty + 8 * i]);
    }
}

// ---------------------------------------------------------------------------
// mma.sync fp16 GEMM (pure hi):  C[M,N] = A_hi @ B_hi^T + bias
// Stage = {A, B} for one k64 range (32KB). 16 chunks, 2-stage double buffer,
// one barrier per chunk. CTA 128x128, 8 warps (2x4), warp tile 64x32.
// ---------------------------------------------------------------------------
#define BM 128
#define BN 128
#define BK 64
#define G_REGION (BM * BK * 2)           // 16384 bytes per matrix region
#define G_STAGE_BYTES (2 * G_REGION)     // 32768 (A + B)
#define G_SMEM (2 * G_STAGE_BYTES)       // 65536
#define NCHUNKG (KB / BK)                // 16

__global__ __launch_bounds__(256, 2) void gemm_mma_kernel(
    const __half* __restrict__ A, const __half* __restrict__ Bm,
    const float* __restrict__ bias, float* __restrict__ C, int N)
{
    extern __shared__ __align__(256) char gsm[];
    const uint32_t base = smem_u32(gsm);

    const int tid  = threadIdx.x;
    const int wid  = tid >> 5;
    const int lane = tid & 31;
    const int wm   = wid >> 2;           // 0..1
    const int wn   = wid & 3;            // 0..3
    const int rowBase = blockIdx.y * BM;
    const int colBase = blockIdx.x * BN;

    float acc[4][4][4] = {};

    const int lrow = tid >> 3;           // 0..31 (x4 via +32)
    const int lch  = tid & 7;

    auto loadStage = [&](int c, int s) {
        const __half* Ag = A + (size_t)rowBase * KB + c * BK;
        const __half* Bg = Bm + (size_t)colBase * KB + c * BK;
        const uint32_t st = base + s * G_STAGE_BYTES;
        #pragma unroll
        for (int m = 0; m < 4; ++m) {
            const int row = lrow + m * 32;
            const uint32_t soff = row * 128 + ((lch ^ (row & 7)) << 4);
            cp_async16(st + soff,            Ag + (size_t)row * KB + lch * 8);
            cp_async16(st + G_REGION + soff, Bg + (size_t)row * KB + lch * 8);
        }
        cp_commit();
    };

    loadStage(0, 0);

    for (int c = 0; c < NCHUNKG; ++c) {
        cp_wait0();
        __syncthreads();                 // chunk c visible; compute of c-1 done everywhere
        if (c + 1 < NCHUNKG) loadStage(c + 1, (c + 1) & 1);

        const uint32_t st  = base + (c & 1) * G_STAGE_BYTES;
        const uint32_t ahs = st;
        const uint32_t bsb = st + G_REGION;

        #pragma unroll
        for (int ks = 0; ks < 4; ++ks) {
            const int arow = wm * 64 + (lane & 15);
            const int ach  = ks * 2 + (lane >> 4);
            uint32_t afr[4][4];
            #pragma unroll
            for (int mt = 0; mt < 4; ++mt) {
                const int row = arow + mt * 16;
                ldsm_x4(afr[mt], ahs + row * 128 + ((ach ^ (row & 7)) << 4));
            }
            uint32_t bfr[4][2];
            #pragma unroll
            for (int ntp = 0; ntp < 2; ++ntp) {
                const int row = wn * 32 + ntp * 16 + (lane & 7) + ((lane >> 4) << 3);
                const int ch  = ks * 2 + ((lane >> 3) & 1);
                uint32_t r[4];
                ldsm_x4(r, bsb + row * 128 + ((ch ^ (row & 7)) << 4));
                bfr[2 * ntp][0]     = r[0]; bfr[2 * ntp][1]     = r[1];
                bfr[2 * ntp + 1][0] = r[2]; bfr[2 * ntp + 1][1] = r[3];
            }
            #pragma unroll
            for (int mt = 0; mt < 4; ++mt)
                #pragma unroll
                for (int nt = 0; nt < 4; ++nt)
                    mma_fp16(acc[mt][nt], afr[mt], bfr[nt]);
        }
        __syncthreads();                 // all reads of stage c done before reload
    }

    // Epilogue
    const int erow = lane >> 2;
    const int ecol = (lane & 3) * 2;
    #pragma unroll
    for (int mt = 0; mt < 4; ++mt) {
        const int rA = rowBase + wm * 64 + mt * 16 + erow;
        #pragma unroll
        for (int nt = 0; nt < 4; ++nt) {
            const int col = colBase + wn * 32 + nt * 8 + ecol;
            const float b0 = bias[col], b1 = bias[col + 1];
            *(float2*)&C[(size_t)rA * N + col] =
                make_float2(acc[mt][nt][0] + b0, acc[mt][nt][1] + b1);
            *(float2*)&C[(size_t)(rA + 8) * N + col] =
                make_float2(acc[mt][nt][2] + b0, acc[mt][nt][3] + b1);
        }
    }
}

// ---------------------------------------------------------------------------
// K/V prep: K rmsnorm + fp16 store, V fp16 store. One warp per (token, head).
// (Q rmsnorm is fused into the attention kernel's Q load.)
// ---------------------------------------------------------------------------
__global__ __launch_bounds__(256) void rmskv_kernel(
    const float* __restrict__ qkv,
    const float* __restrict__ kn_w,
    __half* __restrict__ ks, __half* __restrict__ vs)
{
    const int gwarp = (blockIdx.x * blockDim.x + threadIdx.x) >> 5;
    const int lane  = threadIdx.x & 31;
    const int token = gwarp >> 4;
    const int h     = gwarp & 15;
    if (token >= TOKENS) return;

    const int b = token >> 11;
    const int n = token & 2047;
    const size_t dstRow = ((size_t)(b * HEADS + h) * SEQ + n) * 64;

    {   // K: rmsnorm + fp16
        const float* row = qkv + (size_t)token * QKVDIM + CDIM + h * HDIM;
        float x0 = row[lane];
        float x1 = row[lane + 32];
        float ss = x0 * x0 + x1 * x1;
        #pragma unroll
        for (int off = 16; off; off >>= 1) ss += __shfl_xor_sync(0xffffffffu, ss, off);
        const float inv = rsqrtf(ss * (1.0f / 64.0f) + 1e-6f);
        ks[dstRow + lane]      = __float2half_rn(x0 * inv * kn_w[lane]);
        ks[dstRow + lane + 32] = __float2half_rn(x1 * inv * kn_w[lane + 32]);
    }
    {   // V: fp16
        const float* row = qkv + (size_t)token * QKVDIM + 2 * CDIM + h * HDIM;
        vs[dstRow + lane]      = __float2half_rn(row[lane]);
        vs[dstRow + lane + 32] = __float2half_rn(row[lane + 32]);
    }
}

// ---------------------------------------------------------------------------
// FlashAttention-2 style mma.sync fp16 attention. Bc=64, 4-stage pipeline,
// 2 CTAs/SM. Q rmsnorm fused into the Q load; Q, K, V, P all fp16 hi.
// CTA = 128 q-rows x (b,h); 8 warps x 16 rows. K/V tiles: 64 rows x 128B.
// ---------------------------------------------------------------------------
#define ATT_NT (SEQ / 64)             // 32 key tiles
#define ATT_TILE_B 8192               // one matrix tile: 64 rows * 128B
#define ATT_BUF_B  16384              // K + V per stage
#define ATT_STAGES 4
#define ATT_SMEM   (ATT_STAGES * ATT_BUF_B)   // 65536

__global__ __launch_bounds__(256, 2) void attn_mma_kernel(
    const float* __restrict__ qkv, const float* __restrict__ qn_w,
    const __half* __restrict__ ks, const __half* __restrict__ vs,
    __half* __restrict__ outA)
{
    extern __shared__ __align__(256) char sm[];
    const uint32_t smBase = smem_u32(sm);

    const int tid  = threadIdx.x;
    const int wq   = tid >> 5;
    const int lane = tid & 31;

    const int bh = blockIdx.y;
    const int b  = bh >> 4;
    const int h  = bh & 15;
    const int qBase = blockIdx.x * 128;

    // ---- Q load + fused RMSNorm + fp16 pack, scale folded: 0.125*log2(e) ----
    const float SC = 0.125f * 1.44269504088896340736f;
    uint32_t qh[4][4];
    {
        const float* qg = qkv + ((size_t)(b * SEQ + qBase + wq * 16)) * QKVDIM + h * HDIM;
        const int rr = lane >> 2;
        const int cb = (lane & 3) * 2;
        float2 v0[4], v1[4], v2[4], v3[4];
        float ssa = 0.0f, ssb = 0.0f;
        #pragma unroll
        for (int kd = 0; kd < 4; ++kd) {
            const int d0 = kd * 16;
            v0[kd] = *(const float2*)&qg[(size_t)rr * QKVDIM + d0 + cb];
            v1[kd] = *(const float2*)&qg[(size_t)(rr + 8) * QKVDIM + d0 + cb];
            v2[kd] = *(const float2*)&qg[(size_t)rr * QKVDIM + d0 + cb + 8];
            v3[kd] = *(const float2*)&qg[(size_t)(rr + 8) * QKVDIM + d0 + cb + 8];
            ssa += v0[kd].x * v0[kd].x + v0[kd].y * v0[kd].y
                 + v2[kd].x * v2[kd].x + v2[kd].y * v2[kd].y;
            ssb += v1[kd].x * v1[kd].x + v1[kd].y * v1[kd].y
                 + v3[kd].x * v3[kd].x + v3[kd].y * v3[kd].y;
        }
        ssa += __shfl_xor_sync(0xffffffffu, ssa, 1);
        ssa += __shfl_xor_sync(0xffffffffu, ssa, 2);
        ssb += __shfl_xor_sync(0xffffffffu, ssb, 1);
        ssb += __shfl_xor_sync(0xffffffffu, ssb, 2);
        const float ia = rsqrtf(ssa * (1.0f / 64.0f) + 1e-6f) * SC;
        const float ib = rsqrtf(ssb * (1.0f / 64.0f) + 1e-6f) * SC;
        #pragma unroll
        for (int kd = 0; kd < 4; ++kd) {
            const int d0 = kd * 16;
            const float2 w0 = *(const float2*)&qn_w[d0 + cb];
            const float2 w1 = *(const float2*)&qn_w[d0 + cb + 8];
            qh[kd][0] = h2pack(v0[kd].x * ia * w0.x, v0[kd].y * ia * w0.y);
            qh[kd][1] = h2pack(v1[kd].x * ib * w0.x, v1[kd].y * ib * w0.y);
            qh[kd][2] = h2pack(v2[kd].x * ia * w1.x, v2[kd].y * ia * w1.y);
            qh[kd][3] = h2pack(v3[kd].x * ib * w1.x, v3[kd].y * ib * w1.y);
        }
    }

    // ---- cp.async tile loader: 64 keys, K + V hi (128B rows, XOR swizzle) ----
    auto loadTile = [&](int kt, int st) {
        const __half* gk = ks + ((size_t)bh * SEQ + kt * 64) * 64;
        const __half* gv = vs + ((size_t)bh * SEQ + kt * 64) * 64;
        const uint32_t kb = smBase + st * ATT_BUF_B;
        const uint32_t vb = kb + ATT_TILE_B;
        #pragma unroll
        for (int m = 0; m < 2; ++m) {
            const int id = tid + m * 256;           // 0..511
            const int c = id >> 3, j = id & 7;
            const uint32_t soff = c * 128 + ((j ^ (c & 7)) << 4);
            cp_async16(kb + soff, gk + (size_t)c * 64 + j * 8);
            cp_async16(vb + soff, gv + (size_t)c * 64 + j * 8);
        }
        cp_commit();
    };

    float m0 = -CUDART_INF_F, m1 = -CUDART_INF_F, l0 = 0.0f, l1 = 0.0f;
    float O[8][4] = {};

    loadTile(0, 0);
    loadTile(1, 1);
    loadTile(2, 2);

    for (int kt = 0; kt < ATT_NT; ++kt) {
        const int st = kt & 3;
        if (kt + 2 < ATT_NT)      cp_wait2();
        else if (kt + 1 < ATT_NT) cp_wait1();
        else                      cp_wait0();
        __syncthreads();
        if (kt + 3 < ATT_NT) loadTile(kt + 3, (kt + 3) & 3);

        const uint32_t Kb = smBase + st * ATT_BUF_B;
        const uint32_t Vb = Kb + ATT_TILE_B;

        // ---- S = Qh K^T, 64 keys ----
        float S[8][4] = {};
        #pragma unroll
        for (int kd = 0; kd < 4; ++kd) {
            #pragma unroll
            for (int t = 0; t < 4; ++t) {
                const int row = 16 * t + (lane & 7) + 8 * ((lane >> 4) & 1);
                const int j = kd * 2 + ((lane >> 3) & 1);
                uint32_t r[4];
                ldsm_x4(r, Kb + row * 128 + ((j ^ (row & 7)) << 4));
                mma_fp16(S[2 * t],     qh[kd], r);
                mma_fp16(S[2 * t + 1], qh[kd], r + 2);
            }
        }

        // ---- Online softmax (base 2) ----
        float mt0 = -CUDART_INF_F, mt1 = -CUDART_INF_F;
        #pragma unroll
        for (int nc = 0; nc < 8; ++nc) {
            mt0 = fmaxf(mt0, fmaxf(S[nc][0], S[nc][1]));
            mt1 = fmaxf(mt1, fmaxf(S[nc][2], S[nc][3]));
        }
        mt0 = fmaxf(mt0, __shfl_xor_sync(0xffffffffu, mt0, 1));
        mt0 = fmaxf(mt0, __shfl_xor_sync(0xffffffffu, mt0, 2));
        mt1 = fmaxf(mt1, __shfl_xor_sync(0xffffffffu, mt1, 1));
        mt1 = fmaxf(mt1, __shfl_xor_sync(0xffffffffu, mt1, 2));
        const float mn0 = fmaxf(m0, mt0);
        const float mn1 = fmaxf(m1, mt1);
        const float c0 = ex2f(m0 - mn0);
        const float c1 = ex2f(m1 - mn1);
        m0 = mn0; m1 = mn1;
        float rs0 = 0.0f, rs1 = 0.0f;
        #pragma unroll
        for (int nc = 0; nc < 8; ++nc) {
            S[nc][0] = ex2f(S[nc][0] - mn0); rs0 += S[nc][0];
            S[nc][1] = ex2f(S[nc][1] - mn0); rs0 += S[nc][1];
            S[nc][2] = ex2f(S[nc][2] - mn1); rs1 += S[nc][2];
            S[nc][3] = ex2f(S[nc][3] - mn1); rs1 += S[nc][3];
        }
        rs0 += __shfl_xor_sync(0xffffffffu, rs0, 1);
        rs0 += __shfl_xor_sync(0xffffffffu, rs0, 2);
        rs1 += __shfl_xor_sync(0xffffffffu, rs1, 1);
        rs1 += __shfl_xor_sync(0xffffffffu, rs1, 2);
        l0 = l0 * c0 + rs0;
        l1 = l1 * c1 + rs1;
        #pragma unroll
        for (int nd = 0; nd < 8; ++nd) {
            O[nd][0] *= c0; O[nd][1] *= c0; O[nd][2] *= c1; O[nd][3] *= c1;
        }

        // ---- O += P V (P fp16 hi only), 4 k16 chunks ----
        #pragma unroll
        for (int kc = 0; kc < 4; ++kc) {
            uint32_t ph[4];
            {
                const float* s0 = S[2 * kc];
                const float* s1 = S[2 * kc + 1];
                ph[0] = h2pack(s0[0], s0[1]);
                ph[1] = h2pack(s0[2], s0[3]);
                ph[2] = h2pack(s1[0], s1[1]);
                ph[3] = h2pack(s1[2], s1[3]);
            }
            #pragma unroll
            for (int t = 0; t < 4; ++t) {
                const int row = kc * 16 + (lane & 7) + 8 * ((lane >> 3) & 1);
                const int j = 2 * t + ((lane >> 4) & 1);
                uint32_t r[4];
                ldsm_x4_t(r, Vb + row * 128 + ((j ^ (row & 7)) << 4));
                mma_fp16(O[2 * t],     ph, r);
                mma_fp16(O[2 * t + 1], ph, r + 2);
            }
        }
    }

    // ---- Epilogue: normalize, write fp16 hi rows to outA (stride KB) ----
    const float inv0 = 1.0f / l0;
    const float inv1 = 1.0f / l1;
    const size_t row1 = (size_t)b * SEQ + qBase + wq * 16 + (lane >> 2);
    const int colBase = h * HDIM + (lane & 3) * 2;
    #pragma unroll
    for (int nd = 0; nd < 8; ++nd) {
        const int col = colBase + nd * 8;
        *(uint32_t*)(outA + row1 * KB + col) =
            h2pack(O[nd][0] * inv0, O[nd][1] * inv0);
        *(uint32_t*)(outA + (row1 + 8) * KB + col) =
            h2pack(O[nd][2] * inv1, O[nd][3] * inv1);
    }
}

// ---------------------------------------------------------------------------
// Launch
// ---------------------------------------------------------------------------
extern "C" void kernel_launch(void* const* d_in, const int* in_sizes, int n_in,
                              void* d_out, int out_size)
{
    (void)in_sizes; (void)n_in; (void)out_size;
    const float* x      = (const float*)d_in[0];
    const float* W_qkv  = (const float*)d_in[1];
    const float* b_qkv  = (const float*)d_in[2];
    const float* W_proj = (const float*)d_in[3];
    const float* b_proj = (const float*)d_in[4];
    const float* qn_w   = (const float*)d_in[5];
    const float* kn_w   = (const float*)d_in[6];
    float* out = (float*)d_out;

    float *qkv = nullptr;
    __half *A1 = nullptr, *B1 = nullptr, *B2 = nullptr, *A2 = nullptr;
    __half *ksp = nullptr, *vsp = nullptr;
    cudaGetSymbolAddress((void**)&qkv, g_qkv);
    cudaGetSymbolAddress((void**)&A1,  g_A1);
    cudaGetSymbolAddress((void**)&B1,  g_B1);
    cudaGetSymbolAddress((void**)&B2,  g_B2);
    cudaGetSymbolAddress((void**)&A2,  g_A2);
    cudaGetSymbolAddress((void**)&ksp, g_ks);
    cudaGetSymbolAddress((void**)&vsp, g_vs);

    cudaFuncSetAttribute(gemm_mma_kernel, cudaFuncAttributeMaxDynamicSharedMemorySize, G_SMEM);
    cudaFuncSetAttribute(attn_mma_kernel, cudaFuncAttributeMaxDynamicSharedMemorySize, ATT_SMEM);

    // 0) Conversions to fp16
    convX_kernel<<<(TOKENS * CDIM) / 256, 256>>>(x, A1);
    convW_kernel<<<dim3(QKVDIM / 32, CDIM / 32), 256>>>(W_qkv, B1, QKVDIM);
    convW_kernel<<<dim3(CDIM / 32, CDIM / 32), 256>>>(W_proj, B2, CDIM);

    // 1) QKV projection (pure fp16 hi)
    gemm_mma_kernel<<<dim3(QKVDIM / BN, TOKENS / BM), 256, G_SMEM>>>(
        A1, B1, b_qkv, qkv, QKVDIM);

    // 2) K rmsnorm + K/V fp16 store (Q rmsnorm fused into attention)
    rmskv_kernel<<<(TOKENS * 16) / 8, 256>>>(qkv, kn_w, ksp, vsp);

    // 3) Attention (tensor cores, fused Q rmsnorm) -> g_A2 (fp16 hi)
    attn_mma_kernel<<<dim3(SEQ / 128, BATCH * HEADS), 256, ATT_SMEM>>>(
        qkv, qn_w, ksp, vsp, A2);

    // 4) Output projection (pure fp16 hi)
    gemm_mma_kernel<<<dim3(CDIM / BN, TOKENS / BM), 256, G_SMEM>>>(
        A2, B2, b_proj, out, CDIM);
}

// round 15
// speedup vs baseline: 9.0673x; 1.0293x over previous
#include <cuda_runtime.h>
#include <cuda_fp16.h>
#include <math_constants.h>
#include <cstdint>

// Problem constants
#define BATCH 4
#define SEQ   2048
#define CDIM  1024
#define HEADS 16
#define HDIM  64
#define TOKENS (BATCH * SEQ)         // 8192
#define QKVDIM (3 * CDIM)            // 3072
#define KB    1024                   // hi-only K

// ---------------------------------------------------------------------------
// Scratch (device globals — no allocation allowed)
// ---------------------------------------------------------------------------
__device__ float g_qkv[(size_t)TOKENS * QKVDIM];                    // QKV output fp32 (Q,K used)
__device__ __align__(256) __half g_A1[(size_t)TOKENS * KB];        // x hi        [m, k]
__device__ __align__(256) __half g_B1[(size_t)QKVDIM * KB];        // W_qkv^T hi  [n, k]
__device__ __align__(256) __half g_B2[(size_t)CDIM * KB];          // W_proj^T hi
__device__ __align__(256) __half g_A2[(size_t)TOKENS * KB];        // attn out hi [m, k]
__device__ __align__(256) __half g_ks[(size_t)BATCH * HEADS * SEQ * 64]; // K hi [bh, n, d]
__device__ __align__(256) __half g_vs[(size_t)BATCH * HEADS * SEQ * 64]; // V hi

// ---------------------------------------------------------------------------
// PTX helpers (portable sm_80+ features only)
// ---------------------------------------------------------------------------
__device__ __forceinline__ uint32_t smem_u32(const void* p) {
    uint32_t a;
    asm("{ .reg .u64 t; cvta.to.shared.u64 t, %1; cvt.u32.u64 %0, t; }" : "=r"(a) : "l"(p));
    return a;
}
__device__ __forceinline__ void cp_async16(uint32_t dst, const void* src) {
    asm volatile("cp.async.cg.shared.global [%0], [%1], 16;" :: "r"(dst), "l"(src));
}
__device__ __forceinline__ void cp_commit() {
    asm volatile("cp.async.commit_group;" ::: "memory");
}
__device__ __forceinline__ void cp_wait0() {
    asm volatile("cp.async.wait_group 0;" ::: "memory");
}
__device__ __forceinline__ void cp_wait1() {
    asm volatile("cp.async.wait_group 1;" ::: "memory");
}
__device__ __forceinline__ void cp_wait2() {
    asm volatile("cp.async.wait_group 2;" ::: "memory");
}
__device__ __forceinline__ void ldsm_x4(uint32_t* r, uint32_t addr) {
    asm volatile("ldmatrix.sync.aligned.m8n8.x4.shared.b16 {%0,%1,%2,%3}, [%4];"
                 : "=r"(r[0]), "=r"(r[1]), "=r"(r[2]), "=r"(r[3]) : "r"(addr));
}
__device__ __forceinline__ void ldsm_x4_t(uint32_t* r, uint32_t addr) {
    asm volatile("ldmatrix.sync.aligned.m8n8.x4.trans.shared.b16 {%0,%1,%2,%3}, [%4];"
                 : "=r"(r[0]), "=r"(r[1]), "=r"(r[2]), "=r"(r[3]) : "r"(addr));
}
__device__ __forceinline__ void mma_fp16(float* c, const uint32_t* a, const uint32_t* b) {
    asm volatile(
        "mma.sync.aligned.m16n8k16.row.col.f32.f16.f16.f32 "
        "{%0,%1,%2,%3}, {%4,%5,%6,%7}, {%8,%9}, {%0,%1,%2,%3};"
        : "+f"(c[0]), "+f"(c[1]), "+f"(c[2]), "+f"(c[3])
        : "r"(a[0]), "r"(a[1]), "r"(a[2]), "r"(a[3]), "r"(b[0]), "r"(b[1]));
}
__device__ __forceinline__ float ex2f(float x) {
    float y; asm("ex2.approx.ftz.f32 %0, %1;" : "=f"(y) : "f"(x)); return y;
}
__device__ __forceinline__ uint32_t h2pack(float a, float b) {
    __half2 h;
    h.x = __float2half_rn(a);
    h.y = __float2half_rn(b);
    return *(uint32_t*)&h;
}

// ---------------------------------------------------------------------------
// Conversion kernels (fp32 -> fp16 hi)
// ---------------------------------------------------------------------------
__global__ __launch_bounds__(256) void convX_kernel(const float* __restrict__ x,
                                                    __half* __restrict__ A)
{
    const int idx = blockIdx.x * 256 + threadIdx.x;      // over TOKENS*CDIM
    A[idx] = __float2half_rn(x[idx]);
}

// Transpose: W [K=1024, N] fp32 -> B [N, 1024] fp16 (hi only)
__global__ __launch_bounds__(256) void convW_kernel(const float* __restrict__ W,
                                                    __half* __restrict__ B, int N)
{
    __shared__ float t[32][33];
    const int n0 = blockIdx.x * 32;
    const int k0 = blockIdx.y * 32;
    const int tx = threadIdx.x & 31;
    const int ty = threadIdx.x >> 5;          // 0..7
    #pragma unroll
    for (int i = 0; i < 4; ++i)
        t[ty + 8 * i][tx] = W[(size_t)(k0 + ty + 8 * i) * N + n0 + tx];
    __syncthreads();
    #pragma unroll
    for (int i = 0; i < 4; ++i) {
        const int n = n0 + ty + 8 * i;
        const int k = k0 + tx;
        B[(size_t)n * KB + k] = __float2half_rn(t[tx][ty + 8 * i]);
    }
}

// ---------------------------------------------------------------------------
// mma.sync fp16 GEMM (pure hi):  C[M,N] = A_hi @ B_hi^T + bias
// 3-stage cp.async pipeline, ONE barrier per chunk. CTA 128x128, 8 warps.
// V-column CTAs (colBase >= vCol) write fp16 directly to vs[bh,n,d] instead
// of fp32 C (rounding identical to the old fp32-store + later fp16 round).
// ---------------------------------------------------------------------------
#define BM 128
#define BN 128
#define BK 64
#define G_REGION (BM * BK * 2)           // 16384 bytes per matrix region
#define G_STAGE_BYTES (2 * G_REGION)     // 32768 (A + B)
#define G_STAGES 3
#define G_SMEM (G_STAGES * G_STAGE_BYTES)// 98304
#define NCHUNKG (KB / BK)                // 16

__global__ __launch_bounds__(256, 2) void gemm_mma_kernel(
    const __half* __restrict__ A, const __half* __restrict__ Bm,
    const float* __restrict__ bias, float* __restrict__ C, int N,
    __half* __restrict__ vs, int vCol)
{
    extern __shared__ __align__(256) char gsm[];
    const uint32_t base = smem_u32(gsm);

    const int tid  = threadIdx.x;
    const int wid  = tid >> 5;
    const int lane = tid & 31;
    const int wm   = wid >> 2;           // 0..1
    const int wn   = wid & 3;            // 0..3
    const int rowBase = blockIdx.y * BM;
    const int colBase = blockIdx.x * BN;

    float acc[4][4][4] = {};

    const int lrow = tid >> 3;           // 0..31 (x4 via +32)
    const int lch  = tid & 7;

    auto loadStage = [&](int c, int s) {
        const __half* Ag = A + (size_t)rowBase * KB + c * BK;
        const __half* Bg = Bm + (size_t)colBase * KB + c * BK;
        const uint32_t st = base + s * G_STAGE_BYTES;
        #pragma unroll
        for (int m = 0; m < 4; ++m) {
            const int row = lrow + m * 32;
            const uint32_t soff = row * 128 + ((lch ^ (row & 7)) << 4);
            cp_async16(st + soff,            Ag + (size_t)row * KB + lch * 8);
            cp_async16(st + G_REGION + soff, Bg + (size_t)row * KB + lch * 8);
        }
        cp_commit();
    };

    loadStage(0, 0);
    loadStage(1, 1);

    for (int c = 0; c < NCHUNKG; ++c) {
        if (c < NCHUNKG - 1) cp_wait1(); else cp_wait0();
        __syncthreads();                 // chunk c ready; compute of c-1 done everywhere
        if (c + 2 < NCHUNKG) loadStage(c + 2, (c + 2) % G_STAGES);

        const uint32_t st  = base + (c % G_STAGES) * G_STAGE_BYTES;
        const uint32_t ahs = st;
        const uint32_t bsb = st + G_REGION;

        #pragma unroll
        for (int ks = 0; ks < 4; ++ks) {
            const int arow = wm * 64 + (lane & 15);
            const int ach  = ks * 2 + (lane >> 4);
            uint32_t afr[4][4];
            #pragma unroll
            for (int mt = 0; mt < 4; ++mt) {
                const int row = arow + mt * 16;
                ldsm_x4(afr[mt], ahs + row * 128 + ((ach ^ (row & 7)) << 4));
            }
            uint32_t bfr[4][2];
            #pragma unroll
            for (int ntp = 0; ntp < 2; ++ntp) {
                const int row = wn * 32 + ntp * 16 + (lane & 7) + ((lane >> 4) << 3);
                const int ch  = ks * 2 + ((lane >> 3) & 1);
                uint32_t r[4];
                ldsm_x4(r, bsb + row * 128 + ((ch ^ (row & 7)) << 4));
                bfr[2 * ntp][0]     = r[0]; bfr[2 * ntp][1]     = r[1];
                bfr[2 * ntp + 1][0] = r[2]; bfr[2 * ntp + 1][1] = r[3];
            }
            #pragma unroll
            for (int mt = 0; mt < 4; ++mt)
                #pragma unroll
                for (int nt = 0; nt < 4; ++nt)
                    mma_fp16(acc[mt][nt], afr[mt], bfr[nt]);
        }
    }

    // Epilogue
    const int erow = lane >> 2;
    const int ecol = (lane & 3) * 2;
    if (colBase >= vCol) {
        // V columns: write fp16 directly to vs[( (b*16+h)*SEQ + n )*64 + d]
        #pragma unroll
        for (int mt = 0; mt < 4; ++mt) {
            const int rA = rowBase + wm * 64 + mt * 16 + erow;   // token index
            const int b0i = rA >> 11, n0i = rA & 2047;
            const int b1i = (rA + 8) >> 11, n1i = (rA + 8) & 2047;
            #pragma unroll
            for (int nt = 0; nt < 4; ++nt) {
                const int col = colBase + wn * 32 + nt * 8 + ecol;
                const float bb0 = bias[col], bb1 = bias[col + 1];
                const int hd = col - vCol;            // 0..1023
                const int h = hd >> 6, d = hd & 63;
                __half* p0 = vs + ((size_t)(b0i * HEADS + h) * SEQ + n0i) * 64 + d;
                __half* p1 = vs + ((size_t)(b1i * HEADS + h) * SEQ + n1i) * 64 + d;
                *(uint32_t*)p0 = h2pack(acc[mt][nt][0] + bb0, acc[mt][nt][1] + bb1);
                *(uint32_t*)p1 = h2pack(acc[mt][nt][2] + bb0, acc[mt][nt][3] + bb1);
            }
        }
    } else {
        #pragma unroll
        for (int mt = 0; mt < 4; ++mt) {
            const int rA = rowBase + wm * 64 + mt * 16 + erow;
            #pragma unroll
            for (int nt = 0; nt < 4; ++nt) {
                const int col = colBase + wn * 32 + nt * 8 + ecol;
                const float b0 = bias[col], b1 = bias[col + 1];
                *(float2*)&C[(size_t)rA * N + col] =
                    make_float2(acc[mt][nt][0] + b0, acc[mt][nt][1] + b1);
                *(float2*)&C[(size_t)(rA + 8) * N + col] =
                    make_float2(acc[mt][nt][2] + b0, acc[mt][nt][3] + b1);
            }
        }
    }
}

// ---------------------------------------------------------------------------
// K prep: K rmsnorm + fp16 store. One warp per (token, head).
// (Q rmsnorm fused into attention; V store fused into the QKV GEMM epilogue.)
// ---------------------------------------------------------------------------
__global__ __launch_bounds__(256) void rmsk_kernel(
    const float* __restrict__ qkv,
    const float* __restrict__ kn_w,
    __half* __restrict__ ks)
{
    const int gwarp = (blockIdx.x * blockDim.x + threadIdx.x) >> 5;
    const int lane  = threadIdx.x & 31;
    const int token = gwarp >> 4;
    const int h     = gwarp & 15;
    if (token >= TOKENS) return;

    const int b = token >> 11;
    const int n = token & 2047;
    const size_t dstRow = ((size_t)(b * HEADS + h) * SEQ + n) * 64;

    const float* row = qkv + (size_t)token * QKVDIM + CDIM + h * HDIM;
    float x0 = row[lane];
    float x1 = row[lane + 32];
    float ss = x0 * x0 + x1 * x1;
    #pragma unroll
    for (int off = 16; off; off >>= 1) ss += __shfl_xor_sync(0xffffffffu, ss, off);
    const float inv = rsqrtf(ss * (1.0f / 64.0f) + 1e-6f);
    ks[dstRow + lane]      = __float2half_rn(x0 * inv * kn_w[lane]);
    ks[dstRow + lane + 32] = __float2half_rn(x1 * inv * kn_w[lane + 32]);
}

// ---------------------------------------------------------------------------
// FlashAttention-2 style mma.sync fp16 attention. Bc=64, 4-stage pipeline,
// 2 CTAs/SM. Q rmsnorm fused into the Q load; Q, K, V, P all fp16 hi.
// CTA = 128 q-rows x (b,h); 8 warps x 16 rows. K/V tiles: 64 rows x 128B.
// ---------------------------------------------------------------------------
#define ATT_NT (SEQ / 64)             // 32 key tiles
#define ATT_TILE_B 8192               // one matrix tile: 64 rows * 128B
#define ATT_BUF_B  16384              // K + V per stage
#define ATT_STAGES 4
#define ATT_SMEM   (ATT_STAGES * ATT_BUF_B)   // 65536

__global__ __launch_bounds__(256, 2) void attn_mma_kernel(
    const float* __restrict__ qkv, const float* __restrict__ qn_w,
    const __half* __restrict__ ks, const __half* __restrict__ vs,
    __half* __restrict__ outA)
{
    extern __shared__ __align__(256) char sm[];
    const uint32_t smBase = smem_u32(sm);

    const int tid  = threadIdx.x;
    const int wq   = tid >> 5;
    const int lane = tid & 31;

    const int bh = blockIdx.y;
    const int b  = bh >> 4;
    const int h  = bh & 15;
    const int qBase = blockIdx.x * 128;

    // ---- Q load + fused RMSNorm + fp16 pack, scale folded: 0.125*log2(e) ----
    const float SC = 0.125f * 1.44269504088896340736f;
    uint32_t qh[4][4];
    {
        const float* qg = qkv + ((size_t)(b * SEQ + qBase + wq * 16)) * QKVDIM + h * HDIM;
        const int rr = lane >> 2;
        const int cb = (lane & 3) * 2;
        float2 v0[4], v1[4], v2[4], v3[4];
        float ssa = 0.0f, ssb = 0.0f;
        #pragma unroll
        for (int kd = 0; kd < 4; ++kd) {
            const int d0 = kd * 16;
            v0[kd] = *(const float2*)&qg[(size_t)rr * QKVDIM + d0 + cb];
            v1[kd] = *(const float2*)&qg[(size_t)(rr + 8) * QKVDIM + d0 + cb];
            v2[kd] = *(const float2*)&qg[(size_t)rr * QKVDIM + d0 + cb + 8];
            v3[kd] = *(const float2*)&qg[(size_t)(rr + 8) * QKVDIM + d0 + cb + 8];
            ssa += v0[kd].x * v0[kd].x + v0[kd].y * v0[kd].y
                 + v2[kd].x * v2[kd].x + v2[kd].y * v2[kd].y;
            ssb += v1[kd].x * v1[kd].x + v1[kd].y * v1[kd].y
                 + v3[kd].x * v3[kd].x + v3[kd].y * v3[kd].y;
        }
        ssa += __shfl_xor_sync(0xffffffffu, ssa, 1);
        ssa += __shfl_xor_sync(0xffffffffu, ssa, 2);
        ssb += __shfl_xor_sync(0xffffffffu, ssb, 1);
        ssb += __shfl_xor_sync(0xffffffffu, ssb, 2);
        const float ia = rsqrtf(ssa * (1.0f / 64.0f) + 1e-6f) * SC;
        const float ib = rsqrtf(ssb * (1.0f / 64.0f) + 1e-6f) * SC;
        #pragma unroll
        for (int kd = 0; kd < 4; ++kd) {
            const int d0 = kd * 16;
            const float2 w0 = *(const float2*)&qn_w[d0 + cb];
            const float2 w1 = *(const float2*)&qn_w[d0 + cb + 8];
            qh[kd][0] = h2pack(v0[kd].x * ia * w0.x, v0[kd].y * ia * w0.y);
            qh[kd][1] = h2pack(v1[kd].x * ib * w0.x, v1[kd].y * ib * w0.y);
            qh[kd][2] = h2pack(v2[kd].x * ia * w1.x, v2[kd].y * ia * w1.y);
            qh[kd][3] = h2pack(v3[kd].x * ib * w1.x, v3[kd].y * ib * w1.y);
        }
    }

    // ---- cp.async tile loader: 64 keys, K + V hi (128B rows, XOR swizzle) ----
    auto loadTile = [&](int kt, int st) {
        const __half* gk = ks + ((size_t)bh * SEQ + kt * 64) * 64;
        const __half* gv = vs + ((size_t)bh * SEQ + kt * 64) * 64;
        const uint32_t kb = smBase + st * ATT_BUF_B;
        const uint32_t vb = kb + ATT_TILE_B;
        #pragma unroll
        for (int m = 0; m < 2; ++m) {
            const int id = tid + m * 256;           // 0..511
            const int c = id >> 3, j = id & 7;
            const uint32_t soff = c * 128 + ((j ^ (c & 7)) << 4);
            cp_async16(kb + soff, gk + (size_t)c * 64 + j * 8);
            cp_async16(vb + soff, gv + (size_t)c * 64 + j * 8);
        }
        cp_commit();
    };

    float m0 = -CUDART_INF_F, m1 = -CUDART_INF_F, l0 = 0.0f, l1 = 0.0f;
    float O[8][4] = {};

    loadTile(0, 0);
    loadTile(1, 1);
    loadTile(2, 2);

    for (int kt = 0; kt < ATT_NT; ++kt) {
        const int st = kt & 3;
        if (kt + 2 < ATT_NT)      cp_wait2();
        else if (kt + 1 < ATT_NT) cp_wait1();
        else                      cp_wait0();
        __syncthreads();
        if (kt + 3 < ATT_NT) loadTile(kt + 3, (kt + 3) & 3);

        const uint32_t Kb = smBase + st * ATT_BUF_B;
        const uint32_t Vb = Kb + ATT_TILE_B;

        // ---- S = Qh K^T, 64 keys ----
        float S[8][4] = {};
        #pragma unroll
        for (int kd = 0; kd < 4; ++kd) {
            #pragma unroll
            for (int t = 0; t < 4; ++t) {
                const int row = 16 * t + (lane & 7) + 8 * ((lane >> 4) & 1);
                const int j = kd * 2 + ((lane >> 3) & 1);
                uint32_t r[4];
                ldsm_x4(r, Kb + row * 128 + ((j ^ (row & 7)) << 4));
                mma_fp16(S[2 * t],     qh[kd], r);
                mma_fp16(S[2 * t + 1], qh[kd], r + 2);
            }
        }

        // ---- Online softmax (base 2) ----
        float mt0 = -CUDART_INF_F, mt1 = -CUDART_INF_F;
        #pragma unroll
        for (int nc = 0; nc < 8; ++nc) {
            mt0 = fmaxf(mt0, fmaxf(S[nc][0], S[nc][1]));
            mt1 = fmaxf(mt1, fmaxf(S[nc][2], S[nc][3]));
        }
        mt0 = fmaxf(mt0, __shfl_xor_sync(0xffffffffu, mt0, 1));
        mt0 = fmaxf(mt0, __shfl_xor_sync(0xffffffffu, mt0, 2));
        mt1 = fmaxf(mt1, __shfl_xor_sync(0xffffffffu, mt1, 1));
        mt1 = fmaxf(mt1, __shfl_xor_sync(0xffffffffu, mt1, 2));
        const float mn0 = fmaxf(m0, mt0);
        const float mn1 = fmaxf(m1, mt1);
        const float c0 = ex2f(m0 - mn0);
        const float c1 = ex2f(m1 - mn1);
        m0 = mn0; m1 = mn1;
        float rs0 = 0.0f, rs1 = 0.0f;
        #pragma unroll
        for (int nc = 0; nc < 8; ++nc) {
            S[nc][0] = ex2f(S[nc][0] - mn0); rs0 += S[nc][0];
            S[nc][1] = ex2f(S[nc][1] - mn0); rs0 += S[nc][1];
            S[nc][2] = ex2f(S[nc][2] - mn1); rs1 += S[nc][2];
            S[nc][3] = ex2f(S[nc][3] - mn1); rs1 += S[nc][3];
        }
        rs0 += __shfl_xor_sync(0xffffffffu, rs0, 1);
        rs0 += __shfl_xor_sync(0xffffffffu, rs0, 2);
        rs1 += __shfl_xor_sync(0xffffffffu, rs1, 1);
        rs1 += __shfl_xor_sync(0xffffffffu, rs1, 2);
        l0 = l0 * c0 + rs0;
        l1 = l1 * c1 + rs1;
        #pragma unroll
        for (int nd = 0; nd < 8; ++nd) {
            O[nd][0] *= c0; O[nd][1] *= c0; O[nd][2] *= c1; O[nd][3] *= c1;
        }

        // ---- O += P V (P fp16 hi only), 4 k16 chunks ----
        #pragma unroll
        for (int kc = 0; kc < 4; ++kc) {
            uint32_t ph[4];
            {
                const float* s0 = S[2 * kc];
                const float* s1 = S[2 * kc + 1];
                ph[0] = h2pack(s0[0], s0[1]);
                ph[1] = h2pack(s0[2], s0[3]);
                ph[2] = h2pack(s1[0], s1[1]);
                ph[3] = h2pack(s1[2], s1[3]);
            }
            #pragma unroll
            for (int t = 0; t < 4; ++t) {
                const int row = kc * 16 + (lane & 7) + 8 * ((lane >> 3) & 1);
                const int j = 2 * t + ((lane >> 4) & 1);
                uint32_t r[4];
                ldsm_x4_t(r, Vb + row * 128 + ((j ^ (row & 7)) << 4));
                mma_fp16(O[2 * t],     ph, r);
                mma_fp16(O[2 * t + 1], ph, r + 2);
            }
        }
    }

    // ---- Epilogue: normalize, write fp16 hi rows to outA (stride KB) ----
    const float inv0 = 1.0f / l0;
    const float inv1 = 1.0f / l1;
    const size_t row1 = (size_t)b * SEQ + qBase + wq * 16 + (lane >> 2);
    const int colBase = h * HDIM + (lane & 3) * 2;
    #pragma unroll
    for (int nd = 0; nd < 8; ++nd) {
        const int col = colBase + nd * 8;
        *(uint32_t*)(outA + row1 * KB + col) =
            h2pack(O[nd][0] * inv0, O[nd][1] * inv0);
        *(uint32_t*)(outA + (row1 + 8) * KB + col) =
            h2pack(O[nd][2] * inv1, O[nd][3] * inv1);
    }
}

// ---------------------------------------------------------------------------
// Launch
// ---------------------------------------------------------------------------
extern "C" void kernel_launch(void* const* d_in, const int* in_sizes, int n_in,
                              void* d_out, int out_size)
{
    (void)in_sizes; (void)n_in; (void)out_size;
    const float* x      = (const float*)d_in[0];
    const float* W_qkv  = (const float*)d_in[1];
    const float* b_qkv  = (const float*)d_in[2];
    const float* W_proj = (const float*)d_in[3];
    const float* b_proj = (const float*)d_in[4];
    const float* qn_w   = (const float*)d_in[5];
    const float* kn_w   = (const float*)d_in[6];
    float* out = (float*)d_out;

    float *qkv = nullptr;
    __half *A1 = nullptr, *B1 = nullptr, *B2 = nullptr, *A2 = nullptr;
    __half *ksp = nullptr, *vsp = nullptr;
    cudaGetSymbolAddress((void**)&qkv, g_qkv);
    cudaGetSymbolAddress((void**)&A1,  g_A1);
    cudaGetSymbolAddress((void**)&B1,  g_B1);
    cudaGetSymbolAddress((void**)&B2,  g_B2);
    cudaGetSymbolAddress((void**)&A2,  g_A2);
    cudaGetSymbolAddress((void**)&ksp, g_ks);
    cudaGetSymbolAddress((void**)&vsp, g_vs);

    cudaFuncSetAttribute(gemm_mma_kernel, cudaFuncAttributeMaxDynamicSharedMemorySize, G_SMEM);
    cudaFuncSetAttribute(attn_mma_kernel, cudaFuncAttributeMaxDynamicSharedMemorySize, ATT_SMEM);

    // 0) Conversions to fp16
    convX_kernel<<<(TOKENS * CDIM) / 256, 256>>>(x, A1);
    convW_kernel<<<dim3(QKVDIM / 32, CDIM / 32), 256>>>(W_qkv, B1, QKVDIM);
    convW_kernel<<<dim3(CDIM / 32, CDIM / 32), 256>>>(W_proj, B2, CDIM);

    // 1) QKV projection (pure fp16 hi). V columns (>=2048) go straight to g_vs fp16.
    gemm_mma_kernel<<<dim3(QKVDIM / BN, TOKENS / BM), 256, G_SMEM>>>(
        A1, B1, b_qkv, qkv, QKVDIM, vsp, 2 * CDIM);

    // 2) K rmsnorm + fp16 store (Q rmsnorm fused into attention; V fused above)
    rmsk_kernel<<<(TOKENS * 16) / 8, 256>>>(qkv, kn_w, ksp);

    // 3) Attention (tensor cores, fused Q rmsnorm) -> g_A2 (fp16 hi)
    attn_mma_kernel<<<dim3(SEQ / 128, BATCH * HEADS), 256, ATT_SMEM>>>(
        qkv, qn_w, ksp, vsp, A2);

    // 4) Output projection (pure fp16 hi); vCol beyond range -> all fp32 path
    gemm_mma_kernel<<<dim3(CDIM / BN, TOKENS / BM), 256, G_SMEM>>>(
        A2, B2, b_proj, out, CDIM, nullptr, CDIM + 1);
}

// round 16
// speedup vs baseline: 9.5487x; 1.0531x over previous
#include <cuda_runtime.h>
#include <cuda_fp16.h>
#include <math_constants.h>
#include <cstdint>

// Problem constants
#define BATCH 4
#define SEQ   2048
#define CDIM  1024
#define HEADS 16
#define HDIM  64
#define TOKENS (BATCH * SEQ)         // 8192
#define QKVDIM (3 * CDIM)            // 3072
#define KB    1024                   // hi-only K

// ---------------------------------------------------------------------------
// Scratch (device globals — no allocation allowed)
// ---------------------------------------------------------------------------
__device__ float g_qkv[(size_t)TOKENS * QKVDIM];                    // QKV output fp32 (Q,K used)
__device__ __align__(256) __half g_A1[(size_t)TOKENS * KB];        // x hi        [m, k]
__device__ __align__(256) __half g_B1[(size_t)QKVDIM * KB];        // W_qkv^T hi  [n, k]
__device__ __align__(256) __half g_B2[(size_t)CDIM * KB];          // W_proj^T hi
__device__ __align__(256) __half g_A2[(size_t)TOKENS * KB];        // attn out hi [m, k]
__device__ __align__(256) __half g_ks[(size_t)BATCH * HEADS * SEQ * 64]; // K hi [bh, n, d]
__device__ __align__(256) __half g_vs[(size_t)BATCH * HEADS * SEQ * 64]; // V hi

// ---------------------------------------------------------------------------
// PTX helpers (portable sm_80+ features only)
// ---------------------------------------------------------------------------
__device__ __forceinline__ uint32_t smem_u32(const void* p) {
    uint32_t a;
    asm("{ .reg .u64 t; cvta.to.shared.u64 t, %1; cvt.u32.u64 %0, t; }" : "=r"(a) : "l"(p));
    return a;
}
__device__ __forceinline__ void cp_async16(uint32_t dst, const void* src) {
    asm volatile("cp.async.cg.shared.global [%0], [%1], 16;" :: "r"(dst), "l"(src));
}
__device__ __forceinline__ void cp_commit() {
    asm volatile("cp.async.commit_group;" ::: "memory");
}
__device__ __forceinline__ void cp_wait0() {
    asm volatile("cp.async.wait_group 0;" ::: "memory");
}
__device__ __forceinline__ void cp_wait1() {
    asm volatile("cp.async.wait_group 1;" ::: "memory");
}
__device__ __forceinline__ void cp_wait2() {
    asm volatile("cp.async.wait_group 2;" ::: "memory");
}
__device__ __forceinline__ void ldsm_x4(uint32_t* r, uint32_t addr) {
    asm volatile("ldmatrix.sync.aligned.m8n8.x4.shared.b16 {%0,%1,%2,%3}, [%4];"
                 : "=r"(r[0]), "=r"(r[1]), "=r"(r[2]), "=r"(r[3]) : "r"(addr));
}
__device__ __forceinline__ void ldsm_x4_t(uint32_t* r, uint32_t addr) {
    asm volatile("ldmatrix.sync.aligned.m8n8.x4.trans.shared.b16 {%0,%1,%2,%3}, [%4];"
                 : "=r"(r[0]), "=r"(r[1]), "=r"(r[2]), "=r"(r[3]) : "r"(addr));
}
__device__ __forceinline__ void mma_fp16(float* c, const uint32_t* a, const uint32_t* b) {
    asm volatile(
        "mma.sync.aligned.m16n8k16.row.col.f32.f16.f16.f32 "
        "{%0,%1,%2,%3}, {%4,%5,%6,%7}, {%8,%9}, {%0,%1,%2,%3};"
        : "+f"(c[0]), "+f"(c[1]), "+f"(c[2]), "+f"(c[3])
        : "r"(a[0]), "r"(a[1]), "r"(a[2]), "r"(a[3]), "r"(b[0]), "r"(b[1]));
}
__device__ __forceinline__ float ex2f(float x) {
    float y; asm("ex2.approx.ftz.f32 %0, %1;" : "=f"(y) : "f"(x)); return y;
}
__device__ __forceinline__ uint32_t h2pack(float a, float b) {
    __half2 h;
    h.x = __float2half_rn(a);
    h.y = __float2half_rn(b);
    return *(uint32_t*)&h;
}

// ---------------------------------------------------------------------------
// Conversion kernels (fp32 -> fp16 hi)
// ---------------------------------------------------------------------------
__global__ __launch_bounds__(256) void convX_kernel(const float* __restrict__ x,
                                                    __half* __restrict__ A)
{
    const int idx = blockIdx.x * 256 + threadIdx.x;      // over TOKENS*CDIM
    A[idx] = __float2half_rn(x[idx]);
}

// Transpose: W [K=1024, N] fp32 -> B [N, 1024] fp16 (hi only)
__global__ __launch_bounds__(256) void convW_kernel(const float* __restrict__ W,
                                                    __half* __restrict__ B, int N)
{
    __shared__ float t[32][33];
    const int n0 = blockIdx.x * 32;
    const int k0 = blockIdx.y * 32;
    const int tx = threadIdx.x & 31;
    const int ty = threadIdx.x >> 5;          // 0..7
    #pragma unroll
    for (int i = 0; i < 4; ++i)
        t[ty + 8 * i][tx] = W[(size_t)(k0 + ty + 8 * i) * N + n0 + tx];
    __syncthreads();
    #pragma unroll
    for (int i = 0; i < 4; ++i) {
        const int n = n0 + ty + 8 * i;
        const int k = k0 + tx;
        B[(size_t)n * KB + k] = __float2half_rn(t[tx][ty + 8 * i]);
    }
}

// ---------------------------------------------------------------------------
// mma.sync fp16 GEMM (pure hi):  C[M,N] = A_hi @ B_hi^T + bias
// 3-stage cp.async pipeline, ONE barrier per chunk. CTA 128x128, 8 warps.
// V-column CTAs (colBase >= vCol) write fp16 directly to vs[bh,n,d].
// ---------------------------------------------------------------------------
#define BM 128
#define BN 128
#define BK 64
#define G_REGION (BM * BK * 2)           // 16384 bytes per matrix region
#define G_STAGE_BYTES (2 * G_REGION)     // 32768 (A + B)
#define G_STAGES 3
#define G_SMEM (G_STAGES * G_STAGE_BYTES)// 98304
#define NCHUNKG (KB / BK)                // 16

__global__ __launch_bounds__(256, 2) void gemm_mma_kernel(
    const __half* __restrict__ A, const __half* __restrict__ Bm,
    const float* __restrict__ bias, float* __restrict__ C, int N,
    __half* __restrict__ vs, int vCol)
{
    extern __shared__ __align__(256) char gsm[];
    const uint32_t base = smem_u32(gsm);

    const int tid  = threadIdx.x;
    const int wid  = tid >> 5;
    const int lane = tid & 31;
    const int wm   = wid >> 2;           // 0..1
    const int wn   = wid & 3;            // 0..3
    const int rowBase = blockIdx.y * BM;
    const int colBase = blockIdx.x * BN;

    float acc[4][4][4] = {};

    const int lrow = tid >> 3;           // 0..31 (x4 via +32)
    const int lch  = tid & 7;

    auto loadStage = [&](int c, int s) {
        const __half* Ag = A + (size_t)rowBase * KB + c * BK;
        const __half* Bg = Bm + (size_t)colBase * KB + c * BK;
        const uint32_t st = base + s * G_STAGE_BYTES;
        #pragma unroll
        for (int m = 0; m < 4; ++m) {
            const int row = lrow + m * 32;
            const uint32_t soff = row * 128 + ((lch ^ (row & 7)) << 4);
            cp_async16(st + soff,            Ag + (size_t)row * KB + lch * 8);
            cp_async16(st + G_REGION + soff, Bg + (size_t)row * KB + lch * 8);
        }
        cp_commit();
    };

    loadStage(0, 0);
    loadStage(1, 1);

    for (int c = 0; c < NCHUNKG; ++c) {
        if (c < NCHUNKG - 1) cp_wait1(); else cp_wait0();
        __syncthreads();                 // chunk c ready; compute of c-1 done everywhere
        if (c + 2 < NCHUNKG) loadStage(c + 2, (c + 2) % G_STAGES);

        const uint32_t st  = base + (c % G_STAGES) * G_STAGE_BYTES;
        const uint32_t ahs = st;
        const uint32_t bsb = st + G_REGION;

        #pragma unroll
        for (int ks = 0; ks < 4; ++ks) {
            const int arow = wm * 64 + (lane & 15);
            const int ach  = ks * 2 + (lane >> 4);
            uint32_t afr[4][4];
            #pragma unroll
            for (int mt = 0; mt < 4; ++mt) {
                const int row = arow + mt * 16;
                ldsm_x4(afr[mt], ahs + row * 128 + ((ach ^ (row & 7)) << 4));
            }
            uint32_t bfr[4][2];
            #pragma unroll
            for (int ntp = 0; ntp < 2; ++ntp) {
                const int row = wn * 32 + ntp * 16 + (lane & 7) + ((lane >> 4) << 3);
                const int ch  = ks * 2 + ((lane >> 3) & 1);
                uint32_t r[4];
                ldsm_x4(r, bsb + row * 128 + ((ch ^ (row & 7)) << 4));
                bfr[2 * ntp][0]     = r[0]; bfr[2 * ntp][1]     = r[1];
                bfr[2 * ntp + 1][0] = r[2]; bfr[2 * ntp + 1][1] = r[3];
            }
            #pragma unroll
            for (int mt = 0; mt < 4; ++mt)
                #pragma unroll
                for (int nt = 0; nt < 4; ++nt)
                    mma_fp16(acc[mt][nt], afr[mt], bfr[nt]);
        }
    }

    // Epilogue
    const int erow = lane >> 2;
    const int ecol = (lane & 3) * 2;
    if (colBase >= vCol) {
        // V columns: write fp16 directly to vs[( (b*16+h)*SEQ + n )*64 + d]
        #pragma unroll
        for (int mt = 0; mt < 4; ++mt) {
            const int rA = rowBase + wm * 64 + mt * 16 + erow;   // token index
            const int b0i = rA >> 11, n0i = rA & 2047;
            const int b1i = (rA + 8) >> 11, n1i = (rA + 8) & 2047;
            #pragma unroll
            for (int nt = 0; nt < 4; ++nt) {
                const int col = colBase + wn * 32 + nt * 8 + ecol;
                const float bb0 = bias[col], bb1 = bias[col + 1];
                const int hd = col - vCol;            // 0..1023
                const int h = hd >> 6, d = hd & 63;
                __half* p0 = vs + ((size_t)(b0i * HEADS + h) * SEQ + n0i) * 64 + d;
                __half* p1 = vs + ((size_t)(b1i * HEADS + h) * SEQ + n1i) * 64 + d;
                *(uint32_t*)p0 = h2pack(acc[mt][nt][0] + bb0, acc[mt][nt][1] + bb1);
                *(uint32_t*)p1 = h2pack(acc[mt][nt][2] + bb0, acc[mt][nt][3] + bb1);
            }
        }
    } else {
        #pragma unroll
        for (int mt = 0; mt < 4; ++mt) {
            const int rA = rowBase + wm * 64 + mt * 16 + erow;
            #pragma unroll
            for (int nt = 0; nt < 4; ++nt) {
                const int col = colBase + wn * 32 + nt * 8 + ecol;
                const float b0 = bias[col], b1 = bias[col + 1];
                *(float2*)&C[(size_t)rA * N + col] =
                    make_float2(acc[mt][nt][0] + b0, acc[mt][nt][1] + b1);
                *(float2*)&C[(size_t)(rA + 8) * N + col] =
                    make_float2(acc[mt][nt][2] + b0, acc[mt][nt][3] + b1);
            }
        }
    }
}

// ---------------------------------------------------------------------------
// K prep: K rmsnorm + fp16 store. One warp per (token, head).
// ---------------------------------------------------------------------------
__global__ __launch_bounds__(256) void rmsk_kernel(
    const float* __restrict__ qkv,
    const float* __restrict__ kn_w,
    __half* __restrict__ ks)
{
    const int gwarp = (blockIdx.x * blockDim.x + threadIdx.x) >> 5;
    const int lane  = threadIdx.x & 31;
    const int token = gwarp >> 4;
    const int h     = gwarp & 15;
    if (token >= TOKENS) return;

    const int b = token >> 11;
    const int n = token & 2047;
    const size_t dstRow = ((size_t)(b * HEADS + h) * SEQ + n) * 64;

    const float* row = qkv + (size_t)token * QKVDIM + CDIM + h * HDIM;
    float x0 = row[lane];
    float x1 = row[lane + 32];
    float ss = x0 * x0 + x1 * x1;
    #pragma unroll
    for (int off = 16; off; off >>= 1) ss += __shfl_xor_sync(0xffffffffu, ss, off);
    const float inv = rsqrtf(ss * (1.0f / 64.0f) + 1e-6f);
    ks[dstRow + lane]      = __float2half_rn(x0 * inv * kn_w[lane]);
    ks[dstRow + lane + 32] = __float2half_rn(x1 * inv * kn_w[lane + 32]);
}

// ---------------------------------------------------------------------------
// FlashAttention mma.sync fp16 attention, MAX-FREE softmax.
// After RMSNorm, |logit_base2| <= 0.125*64*log2(e) = 11.54, so exp2(S) is
// bounded in [3.4e-4, 2980]: no overflow/underflow, and the 2^max factor
// cancels in P/l. Bc=64, 4-stage pipeline, 2 CTAs/SM.
// ---------------------------------------------------------------------------
#define ATT_NT (SEQ / 64)             // 32 key tiles
#define ATT_TILE_B 8192               // one matrix tile: 64 rows * 128B
#define ATT_BUF_B  16384              // K + V per stage
#define ATT_STAGES 4
#define ATT_SMEM   (ATT_STAGES * ATT_BUF_B)   // 65536

__global__ __launch_bounds__(256, 2) void attn_mma_kernel(
    const float* __restrict__ qkv, const float* __restrict__ qn_w,
    const __half* __restrict__ ks, const __half* __restrict__ vs,
    __half* __restrict__ outA)
{
    extern __shared__ __align__(256) char sm[];
    const uint32_t smBase = smem_u32(sm);

    const int tid  = threadIdx.x;
    const int wq   = tid >> 5;
    const int lane = tid & 31;

    const int bh = blockIdx.y;
    const int b  = bh >> 4;
    const int h  = bh & 15;
    const int qBase = blockIdx.x * 128;

    // ---- Q load + fused RMSNorm + fp16 pack, scale folded: 0.125*log2(e) ----
    const float SC = 0.125f * 1.44269504088896340736f;
    uint32_t qh[4][4];
    {
        const float* qg = qkv + ((size_t)(b * SEQ + qBase + wq * 16)) * QKVDIM + h * HDIM;
        const int rr = lane >> 2;
        const int cb = (lane & 3) * 2;
        float2 v0[4], v1[4], v2[4], v3[4];
        float ssa = 0.0f, ssb = 0.0f;
        #pragma unroll
        for (int kd = 0; kd < 4; ++kd) {
            const int d0 = kd * 16;
            v0[kd] = *(const float2*)&qg[(size_t)rr * QKVDIM + d0 + cb];
            v1[kd] = *(const float2*)&qg[(size_t)(rr + 8) * QKVDIM + d0 + cb];
            v2[kd] = *(const float2*)&qg[(size_t)rr * QKVDIM + d0 + cb + 8];
            v3[kd] = *(const float2*)&qg[(size_t)(rr + 8) * QKVDIM + d0 + cb + 8];
            ssa += v0[kd].x * v0[kd].x + v0[kd].y * v0[kd].y
                 + v2[kd].x * v2[kd].x + v2[kd].y * v2[kd].y;
            ssb += v1[kd].x * v1[kd].x + v1[kd].y * v1[kd].y
                 + v3[kd].x * v3[kd].x + v3[kd].y * v3[kd].y;
        }
        ssa += __shfl_xor_sync(0xffffffffu, ssa, 1);
        ssa += __shfl_xor_sync(0xffffffffu, ssa, 2);
        ssb += __shfl_xor_sync(0xffffffffu, ssb, 1);
        ssb += __shfl_xor_sync(0xffffffffu, ssb, 2);
        const float ia = rsqrtf(ssa * (1.0f / 64.0f) + 1e-6f) * SC;
        const float ib = rsqrtf(ssb * (1.0f / 64.0f) + 1e-6f) * SC;
        #pragma unroll
        for (int kd = 0; kd < 4; ++kd) {
            const int d0 = kd * 16;
            const float2 w0 = *(const float2*)&qn_w[d0 + cb];
            const float2 w1 = *(const float2*)&qn_w[d0 + cb + 8];
            qh[kd][0] = h2pack(v0[kd].x * ia * w0.x, v0[kd].y * ia * w0.y);
            qh[kd][1] = h2pack(v1[kd].x * ib * w0.x, v1[kd].y * ib * w0.y);
            qh[kd][2] = h2pack(v2[kd].x * ia * w1.x, v2[kd].y * ia * w1.y);
            qh[kd][3] = h2pack(v3[kd].x * ib * w1.x, v3[kd].y * ib * w1.y);
        }
    }

    // ---- cp.async tile loader: 64 keys, K + V hi (128B rows, XOR swizzle) ----
    auto loadTile = [&](int kt, int st) {
        const __half* gk = ks + ((size_t)bh * SEQ + kt * 64) * 64;
        const __half* gv = vs + ((size_t)bh * SEQ + kt * 64) * 64;
        const uint32_t kb = smBase + st * ATT_BUF_B;
        const uint32_t vb = kb + ATT_TILE_B;
        #pragma unroll
        for (int m = 0; m < 2; ++m) {
            const int id = tid + m * 256;           // 0..511
            const int c = id >> 3, j = id & 7;
            const uint32_t soff = c * 128 + ((j ^ (c & 7)) << 4);
            cp_async16(kb + soff, gk + (size_t)c * 64 + j * 8);
            cp_async16(vb + soff, gv + (size_t)c * 64 + j * 8);
        }
        cp_commit();
    };

    float l0 = 0.0f, l1 = 0.0f;
    float O[8][4] = {};

    loadTile(0, 0);
    loadTile(1, 1);
    loadTile(2, 2);

    for (int kt = 0; kt < ATT_NT; ++kt) {
        const int st = kt & 3;
        if (kt + 2 < ATT_NT)      cp_wait2();
        else if (kt + 1 < ATT_NT) cp_wait1();
        else                      cp_wait0();
        __syncthreads();
        if (kt + 3 < ATT_NT) loadTile(kt + 3, (kt + 3) & 3);

        const uint32_t Kb = smBase + st * ATT_BUF_B;
        const uint32_t Vb = Kb + ATT_TILE_B;

        // ---- S = Qh K^T, 64 keys ----
        float S[8][4] = {};
        #pragma unroll
        for (int kd = 0; kd < 4; ++kd) {
            #pragma unroll
            for (int t = 0; t < 4; ++t) {
                const int row = 16 * t + (lane & 7) + 8 * ((lane >> 4) & 1);
                const int j = kd * 2 + ((lane >> 3) & 1);
                uint32_t r[4];
                ldsm_x4(r, Kb + row * 128 + ((j ^ (row & 7)) << 4));
                mma_fp16(S[2 * t],     qh[kd], r);
                mma_fp16(S[2 * t + 1], qh[kd], r + 2);
            }
        }

        // ---- Max-free softmax: P = exp2(S), accumulate row sums ----
        float rs0 = 0.0f, rs1 = 0.0f;
        #pragma unroll
        for (int nc = 0; nc < 8; ++nc) {
            S[nc][0] = ex2f(S[nc][0]); rs0 += S[nc][0];
            S[nc][1] = ex2f(S[nc][1]); rs0 += S[nc][1];
            S[nc][2] = ex2f(S[nc][2]); rs1 += S[nc][2];
            S[nc][3] = ex2f(S[nc][3]); rs1 += S[nc][3];
        }
        rs0 += __shfl_xor_sync(0xffffffffu, rs0, 1);
        rs0 += __shfl_xor_sync(0xffffffffu, rs0, 2);
        rs1 += __shfl_xor_sync(0xffffffffu, rs1, 1);
        rs1 += __shfl_xor_sync(0xffffffffu, rs1, 2);
        l0 += rs0;
        l1 += rs1;

        // ---- O += P V (P fp16), 4 k16 chunks ----
        #pragma unroll
        for (int kc = 0; kc < 4; ++kc) {
            uint32_t ph[4];
            {
                const float* s0 = S[2 * kc];
                const float* s1 = S[2 * kc + 1];
                ph[0] = h2pack(s0[0], s0[1]);
                ph[1] = h2pack(s0[2], s0[3]);
                ph[2] = h2pack(s1[0], s1[1]);
                ph[3] = h2pack(s1[2], s1[3]);
            }
            #pragma unroll
            for (int t = 0; t < 4; ++t) {
                const int row = kc * 16 + (lane & 7) + 8 * ((lane >> 3) & 1);
                const int j = 2 * t + ((lane >> 4) & 1);
                uint32_t r[4];
                ldsm_x4_t(r, Vb + row * 128 + ((j ^ (row & 7)) << 4));
                mma_fp16(O[2 * t],     ph, r);
                mma_fp16(O[2 * t + 1], ph, r + 2);
            }
        }
    }

    // ---- Epilogue: normalize, write fp16 hi rows to outA (stride KB) ----
    const float inv0 = 1.0f / l0;
    const float inv1 = 1.0f / l1;
    const size_t row1 = (size_t)b * SEQ + qBase + wq * 16 + (lane >> 2);
    const int colBase = h * HDIM + (lane & 3) * 2;
    #pragma unroll
    for (int nd = 0; nd < 8; ++nd) {
        const int col = colBase + nd * 8;
        *(uint32_t*)(outA + row1 * KB + col) =
            h2pack(O[nd][0] * inv0, O[nd][1] * inv0);
        *(uint32_t*)(outA + (row1 + 8) * KB + col) =
            h2pack(O[nd][2] * inv1, O[nd][3] * inv1);
    }
}

// ---------------------------------------------------------------------------
// Launch
// ---------------------------------------------------------------------------
extern "C" void kernel_launch(void* const* d_in, const int* in_sizes, int n_in,
                              void* d_out, int out_size)
{
    (void)in_sizes; (void)n_in; (void)out_size;
    const float* x      = (const float*)d_in[0];
    const float* W_qkv  = (const float*)d_in[1];
    const float* b_qkv  = (const float*)d_in[2];
    const float* W_proj = (const float*)d_in[3];
    const float* b_proj = (const float*)d_in[4];
    const float* qn_w   = (const float*)d_in[5];
    const float* kn_w   = (const float*)d_in[6];
    float* out = (float*)d_out;

    float *qkv = nullptr;
    __half *A1 = nullptr, *B1 = nullptr, *B2 = nullptr, *A2 = nullptr;
    __half *ksp = nullptr, *vsp = nullptr;
    cudaGetSymbolAddress((void**)&qkv, g_qkv);
    cudaGetSymbolAddress((void**)&A1,  g_A1);
    cudaGetSymbolAddress((void**)&B1,  g_B1);
    cudaGetSymbolAddress((void**)&B2,  g_B2);
    cudaGetSymbolAddress((void**)&A2,  g_A2);
    cudaGetSymbolAddress((void**)&ksp, g_ks);
    cudaGetSymbolAddress((void**)&vsp, g_vs);

    cudaFuncSetAttribute(gemm_mma_kernel, cudaFuncAttributeMaxDynamicSharedMemorySize, G_SMEM);
    cudaFuncSetAttribute(attn_mma_kernel, cudaFuncAttributeMaxDynamicSharedMemorySize, ATT_SMEM);

    // 0) Conversions to fp16
    convX_kernel<<<(TOKENS * CDIM) / 256, 256>>>(x, A1);
    convW_kernel<<<dim3(QKVDIM / 32, CDIM / 32), 256>>>(W_qkv, B1, QKVDIM);
    convW_kernel<<<dim3(CDIM / 32, CDIM / 32), 256>>>(W_proj, B2, CDIM);

    // 1) QKV projection (pure fp16 hi). V columns (>=2048) go straight to g_vs fp16.
    gemm_mma_kernel<<<dim3(QKVDIM / BN, TOKENS / BM), 256, G_SMEM>>>(
        A1, B1, b_qkv, qkv, QKVDIM, vsp, 2 * CDIM);

    // 2) K rmsnorm + fp16 store (Q rmsnorm fused into attention; V fused above)
    rmsk_kernel<<<(TOKENS * 16) / 8, 256>>>(qkv, kn_w, ksp);

    // 3) Attention (tensor cores, fused Q rmsnorm, max-free softmax) -> g_A2
    attn_mma_kernel<<<dim3(SEQ / 128, BATCH * HEADS), 256, ATT_SMEM>>>(
        qkv, qn_w, ksp, vsp, A2);

    // 4) Output projection (pure fp16 hi); vCol beyond range -> all fp32 path
    gemm_mma_kernel<<<dim3(CDIM / BN, TOKENS / BM), 256, G_SMEM>>>(
        A2, B2, b_proj, out, CDIM, nullptr, CDIM + 1);
}

// round 17
// speedup vs baseline: 10.0970x; 1.0574x over previous
#include <cuda_runtime.h>
#include <cuda_fp16.h>
#include <math_constants.h>
#include <cstdint>

// Problem constants
#define BATCH 4
#define SEQ   2048
#define CDIM  1024
#define HEADS 16
#define HDIM  64
#define TOKENS (BATCH * SEQ)         // 8192
#define QKVDIM (3 * CDIM)            // 3072
#define KB    1024                   // hi-only K

// ---------------------------------------------------------------------------
// Scratch (device globals — no allocation allowed)
// ---------------------------------------------------------------------------
__device__ __align__(256) __half g_A1[(size_t)TOKENS * KB];        // x hi        [m, k]
__device__ __align__(256) __half g_B1[(size_t)QKVDIM * KB];        // W_qkv^T hi  [n, k]
__device__ __align__(256) __half g_B2[(size_t)CDIM * KB];          // W_proj^T hi
__device__ __align__(256) __half g_A2[(size_t)TOKENS * KB];        // attn out hi [m, k]
__device__ __align__(256) __half g_qs[(size_t)BATCH * HEADS * SEQ * 64]; // Q norm*qn_w*SC fp16
__device__ __align__(256) __half g_ks[(size_t)BATCH * HEADS * SEQ * 64]; // K norm*kn_w fp16
__device__ __align__(256) __half g_vs[(size_t)BATCH * HEADS * SEQ * 64]; // V fp16

// ---------------------------------------------------------------------------
// PTX helpers (portable sm_80+ features only)
// ---------------------------------------------------------------------------
__device__ __forceinline__ uint32_t smem_u32(const void* p) {
    uint32_t a;
    asm("{ .reg .u64 t; cvta.to.shared.u64 t, %1; cvt.u32.u64 %0, t; }" : "=r"(a) : "l"(p));
    return a;
}
__device__ __forceinline__ void cp_async16(uint32_t dst, const void* src) {
    asm volatile("cp.async.cg.shared.global [%0], [%1], 16;" :: "r"(dst), "l"(src));
}
__device__ __forceinline__ void cp_commit() {
    asm volatile("cp.async.commit_group;" ::: "memory");
}
__device__ __forceinline__ void cp_wait0() {
    asm volatile("cp.async.wait_group 0;" ::: "memory");
}
__device__ __forceinline__ void cp_wait1() {
    asm volatile("cp.async.wait_group 1;" ::: "memory");
}
__device__ __forceinline__ void cp_wait2() {
    asm volatile("cp.async.wait_group 2;" ::: "memory");
}
__device__ __forceinline__ void ldsm_x4(uint32_t* r, uint32_t addr) {
    asm volatile("ldmatrix.sync.aligned.m8n8.x4.shared.b16 {%0,%1,%2,%3}, [%4];"
                 : "=r"(r[0]), "=r"(r[1]), "=r"(r[2]), "=r"(r[3]) : "r"(addr));
}
__device__ __forceinline__ void ldsm_x4_t(uint32_t* r, uint32_t addr) {
    asm volatile("ldmatrix.sync.aligned.m8n8.x4.trans.shared.b16 {%0,%1,%2,%3}, [%4];"
                 : "=r"(r[0]), "=r"(r[1]), "=r"(r[2]), "=r"(r[3]) : "r"(addr));
}
__device__ __forceinline__ void mma_fp16(float* c, const uint32_t* a, const uint32_t* b) {
    asm volatile(
        "mma.sync.aligned.m16n8k16.row.col.f32.f16.f16.f32 "
        "{%0,%1,%2,%3}, {%4,%5,%6,%7}, {%8,%9}, {%0,%1,%2,%3};"
        : "+f"(c[0]), "+f"(c[1]), "+f"(c[2]), "+f"(c[3])
        : "r"(a[0]), "r"(a[1]), "r"(a[2]), "r"(a[3]), "r"(b[0]), "r"(b[1]));
}
__device__ __forceinline__ float ex2f(float x) {
    float y; asm("ex2.approx.ftz.f32 %0, %1;" : "=f"(y) : "f"(x)); return y;
}
__device__ __forceinline__ uint32_t h2pack(float a, float b) {
    __half2 h;
    h.x = __float2half_rn(a);
    h.y = __float2half_rn(b);
    return *(uint32_t*)&h;
}

// ---------------------------------------------------------------------------
// Conversion kernels (fp32 -> fp16 hi)
// ---------------------------------------------------------------------------
__global__ __launch_bounds__(256) void convX_kernel(const float* __restrict__ x,
                                                    __half* __restrict__ A)
{
    const int idx = blockIdx.x * 256 + threadIdx.x;      // over TOKENS*CDIM
    A[idx] = __float2half_rn(x[idx]);
}

// Transpose: W [K=1024, N] fp32 -> B [N, 1024] fp16 (hi only)
__global__ __launch_bounds__(256) void convW_kernel(const float* __restrict__ W,
                                                    __half* __restrict__ B, int N)
{
    __shared__ float t[32][33];
    const int n0 = blockIdx.x * 32;
    const int k0 = blockIdx.y * 32;
    const int tx = threadIdx.x & 31;
    const int ty = threadIdx.x >> 5;          // 0..7
    #pragma unroll
    for (int i = 0; i < 4; ++i)
        t[ty + 8 * i][tx] = W[(size_t)(k0 + ty + 8 * i) * N + n0 + tx];
    __syncthreads();
    #pragma unroll
    for (int i = 0; i < 4; ++i) {
        const int n = n0 + ty + 8 * i;
        const int k = k0 + tx;
        B[(size_t)n * KB + k] = __float2half_rn(t[tx][ty + 8 * i]);
    }
}

// ---------------------------------------------------------------------------
// mma.sync fp16 GEMM (pure hi):  C = A_hi @ B_hi^T + bias
// 3-stage cp.async pipeline, ONE barrier per chunk. CTA 128x128, 8 warps.
// QKV mode (qs != nullptr): epilogue fuses per-head RMSNorm for Q (x qn_w x SC)
// and K (x kn_w) and writes fp16 [bh,n,d]; V written fp16 unnormalized.
// Row sumsq: per-thread 8 cols -> shfl(1,2) over the 4-lane row group (32 cols)
// -> smem exchange with partner warp (wn^1) for the head's other 32 cols.
// ---------------------------------------------------------------------------
#define BM 128
#define BN 128
#define BK 64
#define G_REGION (BM * BK * 2)           // 16384 bytes per matrix region
#define G_STAGE_BYTES (2 * G_REGION)     // 32768 (A + B)
#define G_STAGES 3
#define G_SMEM (G_STAGES * G_STAGE_BYTES)// 98304
#define NCHUNKG (KB / BK)                // 16

__global__ __launch_bounds__(256, 2) void gemm_mma_kernel(
    const __half* __restrict__ A, const __half* __restrict__ Bm,
    const float* __restrict__ bias, float* __restrict__ C, int N,
    __half* __restrict__ qs, __half* __restrict__ ks, __half* __restrict__ vs,
    const float* __restrict__ qn_w, const float* __restrict__ kn_w)
{
    extern __shared__ __align__(256) char gsm[];
    const uint32_t base = smem_u32(gsm);

    const int tid  = threadIdx.x;
    const int wid  = tid >> 5;
    const int lane = tid & 31;
    const int wm   = wid >> 2;           // 0..1
    const int wn   = wid & 3;            // 0..3
    const int rowBase = blockIdx.y * BM;
    const int colBase = blockIdx.x * BN;

    float acc[4][4][4] = {};

    const int lrow = tid >> 3;           // 0..31 (x4 via +32)
    const int lch  = tid & 7;

    auto loadStage = [&](int c, int s) {
        const __half* Ag = A + (size_t)rowBase * KB + c * BK;
        const __half* Bg = Bm + (size_t)colBase * KB + c * BK;
        const uint32_t st = base + s * G_STAGE_BYTES;
        #pragma unroll
        for (int m = 0; m < 4; ++m) {
            const int row = lrow + m * 32;
            const uint32_t soff = row * 128 + ((lch ^ (row & 7)) << 4);
            cp_async16(st + soff,            Ag + (size_t)row * KB + lch * 8);
            cp_async16(st + G_REGION + soff, Bg + (size_t)row * KB + lch * 8);
        }
        cp_commit();
    };

    loadStage(0, 0);
    loadStage(1, 1);

    for (int c = 0; c < NCHUNKG; ++c) {
        if (c < NCHUNKG - 1) cp_wait1(); else cp_wait0();
        __syncthreads();                 // chunk c ready; compute of c-1 done everywhere
        if (c + 2 < NCHUNKG) loadStage(c + 2, (c + 2) % G_STAGES);

        const uint32_t st  = base + (c % G_STAGES) * G_STAGE_BYTES;
        const uint32_t ahs = st;
        const uint32_t bsb = st + G_REGION;

        #pragma unroll
        for (int ks2 = 0; ks2 < 4; ++ks2) {
            const int arow = wm * 64 + (lane & 15);
            const int ach  = ks2 * 2 + (lane >> 4);
            uint32_t afr[4][4];
            #pragma unroll
            for (int mt = 0; mt < 4; ++mt) {
                const int row = arow + mt * 16;
                ldsm_x4(afr[mt], ahs + row * 128 + ((ach ^ (row & 7)) << 4));
            }
            uint32_t bfr[4][2];
            #pragma unroll
            for (int ntp = 0; ntp < 2; ++ntp) {
                const int row = wn * 32 + ntp * 16 + (lane & 7) + ((lane >> 4) << 3);
                const int ch  = ks2 * 2 + ((lane >> 3) & 1);
                uint32_t r[4];
                ldsm_x4(r, bsb + row * 128 + ((ch ^ (row & 7)) << 4));
                bfr[2 * ntp][0]     = r[0]; bfr[2 * ntp][1]     = r[1];
                bfr[2 * ntp + 1][0] = r[2]; bfr[2 * ntp + 1][1] = r[3];
            }
            #pragma unroll
            for (int mt = 0; mt < 4; ++mt)
                #pragma unroll
                for (int nt = 0; nt < 4; ++nt)
                    mma_fp16(acc[mt][nt], afr[mt], bfr[nt]);
        }
    }

    // ---- Epilogue ----
    const int erow = lane >> 2;
    const int ecol = (lane & 3) * 2;

    // bias
    #pragma unroll
    for (int mt = 0; mt < 4; ++mt)
        #pragma unroll
        for (int nt = 0; nt < 4; ++nt) {
            const int col = colBase + wn * 32 + nt * 8 + ecol;
            acc[mt][nt][0] += bias[col];
            acc[mt][nt][1] += bias[col + 1];
            acc[mt][nt][2] += bias[col];
            acc[mt][nt][3] += bias[col + 1];
        }

    if (qs == nullptr) {
        // plain fp32 store (proj GEMM)
        #pragma unroll
        for (int mt = 0; mt < 4; ++mt) {
            const int rA = rowBase + wm * 64 + mt * 16 + erow;
            #pragma unroll
            for (int nt = 0; nt < 4; ++nt) {
                const int col = colBase + wn * 32 + nt * 8 + ecol;
                *(float2*)&C[(size_t)rA * N + col] =
                    make_float2(acc[mt][nt][0], acc[mt][nt][1]);
                *(float2*)&C[(size_t)(rA + 8) * N + col] =
                    make_float2(acc[mt][nt][2], acc[mt][nt][3]);
            }
        }
        return;
    }

    // QKV mode: region 0=Q, 1=K, 2=V (CTA-uniform; head blocks align to BN)
    const int region = colBase >> 10;
    __syncthreads();                      // mainloop reads done; reuse smem
    float* sums = (float*)gsm;            // [4][128]

    if (region < 2) {
        #pragma unroll
        for (int mt = 0; mt < 4; ++mt) {
            float s0 = 0.0f, s1 = 0.0f;
            #pragma unroll
            for (int nt = 0; nt < 4; ++nt) {
                s0 += acc[mt][nt][0] * acc[mt][nt][0] + acc[mt][nt][1] * acc[mt][nt][1];
                s1 += acc[mt][nt][2] * acc[mt][nt][2] + acc[mt][nt][3] * acc[mt][nt][3];
            }
            s0 += __shfl_xor_sync(0xffffffffu, s0, 1);
            s0 += __shfl_xor_sync(0xffffffffu, s0, 2);
            s1 += __shfl_xor_sync(0xffffffffu, s1, 1);
            s1 += __shfl_xor_sync(0xffffffffu, s1, 2);
            if ((lane & 3) == 0) {
                sums[wn * 128 + wm * 64 + mt * 16 + erow]     = s0;
                sums[wn * 128 + wm * 64 + mt * 16 + erow + 8] = s1;
            }
        }
        __syncthreads();
    }

    const float SCQ = (region == 0) ? (0.125f * 1.44269504088896340736f) : 1.0f;
    const float* wv = (region == 0) ? qn_w : kn_w;
    __half* dst = (region == 0) ? qs : (region == 1) ? ks : vs;

    #pragma unroll
    for (int mt = 0; mt < 4; ++mt) {
        const int rA = rowBase + wm * 64 + mt * 16 + erow;     // token
        const int r1 = rA + 8;
        float inv0 = 1.0f, inv1 = 1.0f;
        if (region < 2) {
            const float t0 = sums[wn * 128 + wm * 64 + mt * 16 + erow] +
                             sums[(wn ^ 1) * 128 + wm * 64 + mt * 16 + erow];
            const float t1 = sums[wn * 128 + wm * 64 + mt * 16 + erow + 8] +
                             sums[(wn ^ 1) * 128 + wm * 64 + mt * 16 + erow + 8];
            inv0 = rsqrtf(t0 * (1.0f / 64.0f) + 1e-6f) * SCQ;
            inv1 = rsqrtf(t1 * (1.0f / 64.0f) + 1e-6f) * SCQ;
        }
        const int b0i = rA >> 11, n0i = rA & 2047;
        const int b1i = r1 >> 11, n1i = r1 & 2047;
        #pragma unroll
        for (int nt = 0; nt < 4; ++nt) {
            const int col = colBase + wn * 32 + nt * 8 + ecol;
            const int hd = col & 1023;
            const int h = hd >> 6, d = hd & 63;
            float w0 = 1.0f, w1 = 1.0f;
            if (region < 2) { w0 = wv[d]; w1 = wv[d + 1]; }
            __half* p0 = dst + ((size_t)(b0i * HEADS + h) * SEQ + n0i) * 64 + d;
            __half* p1 = dst + ((size_t)(b1i * HEADS + h) * SEQ + n1i) * 64 + d;
            *(uint32_t*)p0 = h2pack(acc[mt][nt][0] * inv0 * w0, acc[mt][nt][1] * inv0 * w1);
            *(uint32_t*)p1 = h2pack(acc[mt][nt][2] * inv1 * w0, acc[mt][nt][3] * inv1 * w1);
        }
    }
}

// ---------------------------------------------------------------------------
// FlashAttention mma.sync fp16 attention, MAX-FREE softmax.
// Q pre-normalized (x qn_w x 0.125*log2e) fp16 in [bh,n,d]; K,V fp16 likewise.
// Bc=64, 4-stage pipeline, 2 CTAs/SM.
// ---------------------------------------------------------------------------
#define ATT_NT (SEQ / 64)             // 32 key tiles
#define ATT_TILE_B 8192               // one matrix tile: 64 rows * 128B
#define ATT_BUF_B  16384              // K + V per stage
#define ATT_STAGES 4
#define ATT_SMEM   (ATT_STAGES * ATT_BUF_B)   // 65536

__global__ __launch_bounds__(256, 2) void attn_mma_kernel(
    const __half* __restrict__ qsg,
    const __half* __restrict__ ks, const __half* __restrict__ vs,
    __half* __restrict__ outA)
{
    extern __shared__ __align__(256) char sm[];
    const uint32_t smBase = smem_u32(sm);

    const int tid  = threadIdx.x;
    const int wq   = tid >> 5;
    const int lane = tid & 31;

    const int bh = blockIdx.y;
    const int b  = bh >> 4;
    const int qBase = blockIdx.x * 128;

    // ---- Q fragments: plain fp16 loads (pre-normalized, pre-scaled) ----
    uint32_t qh[4][4];
    {
        const __half* qg = qsg + ((size_t)bh * SEQ + qBase + wq * 16) * 64;
        const int rr = lane >> 2;
        const int cb = (lane & 3) * 2;
        #pragma unroll
        for (int kd = 0; kd < 4; ++kd) {
            const int d0 = kd * 16;
            qh[kd][0] = *(const uint32_t*)&qg[(size_t)rr * 64 + d0 + cb];
            qh[kd][1] = *(const uint32_t*)&qg[(size_t)(rr + 8) * 64 + d0 + cb];
            qh[kd][2] = *(const uint32_t*)&qg[(size_t)rr * 64 + d0 + cb + 8];
            qh[kd][3] = *(const uint32_t*)&qg[(size_t)(rr + 8) * 64 + d0 + cb + 8];
        }
    }

    // ---- cp.async tile loader: 64 keys, K + V (128B rows, XOR swizzle) ----
    auto loadTile = [&](int kt, int st) {
        const __half* gk = ks + ((size_t)bh * SEQ + kt * 64) * 64;
        const __half* gv = vs + ((size_t)bh * SEQ + kt * 64) * 64;
        const uint32_t kb = smBase + st * ATT_BUF_B;
        const uint32_t vb = kb + ATT_TILE_B;
        #pragma unroll
        for (int m = 0; m < 2; ++m) {
            const int id = tid + m * 256;           // 0..511
            const int c = id >> 3, j = id & 7;
            const uint32_t soff = c * 128 + ((j ^ (c & 7)) << 4);
            cp_async16(kb + soff, gk + (size_t)c * 64 + j * 8);
            cp_async16(vb + soff, gv + (size_t)c * 64 + j * 8);
        }
        cp_commit();
    };

    float l0 = 0.0f, l1 = 0.0f;
    float O[8][4] = {};

    loadTile(0, 0);
    loadTile(1, 1);
    loadTile(2, 2);

    for (int kt = 0; kt < ATT_NT; ++kt) {
        const int st = kt & 3;
        if (kt + 2 < ATT_NT)      cp_wait2();
        else if (kt + 1 < ATT_NT) cp_wait1();
        else                      cp_wait0();
        __syncthreads();
        if (kt + 3 < ATT_NT) loadTile(kt + 3, (kt + 3) & 3);

        const uint32_t Kb = smBase + st * ATT_BUF_B;
        const uint32_t Vb = Kb + ATT_TILE_B;

        // ---- S = Q K^T, 64 keys ----
        float S[8][4] = {};
        #pragma unroll
        for (int kd = 0; kd < 4; ++kd) {
            #pragma unroll
            for (int t = 0; t < 4; ++t) {
                const int row = 16 * t + (lane & 7) + 8 * ((lane >> 4) & 1);
                const int j = kd * 2 + ((lane >> 3) & 1);
                uint32_t r[4];
                ldsm_x4(r, Kb + row * 128 + ((j ^ (row & 7)) << 4));
                mma_fp16(S[2 * t],     qh[kd], r);
                mma_fp16(S[2 * t + 1], qh[kd], r + 2);
            }
        }

        // ---- Max-free softmax: P = exp2(S), accumulate row sums ----
        float rs0 = 0.0f, rs1 = 0.0f;
        #pragma unroll
        for (int nc = 0; nc < 8; ++nc) {
            S[nc][0] = ex2f(S[nc][0]); rs0 += S[nc][0];
            S[nc][1] = ex2f(S[nc][1]); rs0 += S[nc][1];
            S[nc][2] = ex2f(S[nc][2]); rs1 += S[nc][2];
            S[nc][3] = ex2f(S[nc][3]); rs1 += S[nc][3];
        }
        rs0 += __shfl_xor_sync(0xffffffffu, rs0, 1);
        rs0 += __shfl_xor_sync(0xffffffffu, rs0, 2);
        rs1 += __shfl_xor_sync(0xffffffffu, rs1, 1);
        rs1 += __shfl_xor_sync(0xffffffffu, rs1, 2);
        l0 += rs0;
        l1 += rs1;

        // ---- O += P V (P fp16), 4 k16 chunks ----
        #pragma unroll
        for (int kc = 0; kc < 4; ++kc) {
            uint32_t ph[4];
            {
                const float* s0 = S[2 * kc];
                const float* s1 = S[2 * kc + 1];
                ph[0] = h2pack(s0[0], s0[1]);
                ph[1] = h2pack(s0[2], s0[3]);
                ph[2] = h2pack(s1[0], s1[1]);
                ph[3] = h2pack(s1[2], s1[3]);
            }
            #pragma unroll
            for (int t = 0; t < 4; ++t) {
                const int row = kc * 16 + (lane & 7) + 8 * ((lane >> 3) & 1);
                const int j = 2 * t + ((lane >> 4) & 1);
                uint32_t r[4];
                ldsm_x4_t(r, Vb + row * 128 + ((j ^ (row & 7)) << 4));
                mma_fp16(O[2 * t],     ph, r);
                mma_fp16(O[2 * t + 1], ph, r + 2);
            }
        }
    }

    // ---- Epilogue: normalize, write fp16 rows to outA (stride KB) ----
    const int h = bh & 15;
    const float inv0 = 1.0f / l0;
    const float inv1 = 1.0f / l1;
    const size_t row1 = (size_t)b * SEQ + qBase + wq * 16 + (lane >> 2);
    const int colBase = h * HDIM + (lane & 3) * 2;
    #pragma unroll
    for (int nd = 0; nd < 8; ++nd) {
        const int col = colBase + nd * 8;
        *(uint32_t*)(outA + row1 * KB + col) =
            h2pack(O[nd][0] * inv0, O[nd][1] * inv0);
        *(uint32_t*)(outA + (row1 + 8) * KB + col) =
            h2pack(O[nd][2] * inv1, O[nd][3] * inv1);
    }
}

// ---------------------------------------------------------------------------
// Launch
// ---------------------------------------------------------------------------
extern "C" void kernel_launch(void* const* d_in, const int* in_sizes, int n_in,
                              void* d_out, int out_size)
{
    (void)in_sizes; (void)n_in; (void)out_size;
    const float* x      = (const float*)d_in[0];
    const float* W_qkv  = (const float*)d_in[1];
    const float* b_qkv  = (const float*)d_in[2];
    const float* W_proj = (const float*)d_in[3];
    const float* b_proj = (const float*)d_in[4];
    const float* qn_w   = (const float*)d_in[5];
    const float* kn_w   = (const float*)d_in[6];
    float* out = (float*)d_out;

    __half *A1 = nullptr, *B1 = nullptr, *B2 = nullptr, *A2 = nullptr;
    __half *qsp = nullptr, *ksp = nullptr, *vsp = nullptr;
    cudaGetSymbolAddress((void**)&A1,  g_A1);
    cudaGetSymbolAddress((void**)&B1,  g_B1);
    cudaGetSymbolAddress((void**)&B2,  g_B2);
    cudaGetSymbolAddress((void**)&A2,  g_A2);
    cudaGetSymbolAddress((void**)&qsp, g_qs);
    cudaGetSymbolAddress((void**)&ksp, g_ks);
    cudaGetSymbolAddress((void**)&vsp, g_vs);

    cudaFuncSetAttribute(gemm_mma_kernel, cudaFuncAttributeMaxDynamicSharedMemorySize, G_SMEM);
    cudaFuncSetAttribute(attn_mma_kernel, cudaFuncAttributeMaxDynamicSharedMemorySize, ATT_SMEM);

    // 0) Conversions to fp16
    convX_kernel<<<(TOKENS * CDIM) / 256, 256>>>(x, A1);
    convW_kernel<<<dim3(QKVDIM / 32, CDIM / 32), 256>>>(W_qkv, B1, QKVDIM);
    convW_kernel<<<dim3(CDIM / 32, CDIM / 32), 256>>>(W_proj, B2, CDIM);

    // 1) QKV projection with fused RMSNorm(Q,K) + fp16 [bh,n,d] outputs
    gemm_mma_kernel<<<dim3(QKVDIM / BN, TOKENS / BM), 256, G_SMEM>>>(
        A1, B1, b_qkv, nullptr, QKVDIM, qsp, ksp, vsp, qn_w, kn_w);

    // 2) Attention (tensor cores, max-free softmax) -> g_A2 (fp16)
    attn_mma_kernel<<<dim3(SEQ / 128, BATCH * HEADS), 256, ATT_SMEM>>>(
        qsp, ksp, vsp, A2);

    // 3) Output projection (plain fp32 store)
    gemm_mma_kernel<<<dim3(CDIM / BN, TOKENS / BM), 256, G_SMEM>>>(
        A2, B2, b_proj, out, CDIM, nullptr, nullptr, nullptr, nullptr, nullptr);
}